// round 10
// baseline (speedup 1.0000x reference)
#include <cuda_runtime.h>
#include <cuda_fp16.h>
#include <cstdint>

#define N_NODES_C 150000
#define N_EDGES_C 300000
#define N_LG_C    600000
#define HID       256
#define NGRAPH    2048
#define AFD       35
#define BFD       5
#define KIN       40

#define E_SPLIT   150016   // edge chunk boundary (multiple of 128 and 4)
#define V_SPLIT   75008    // node chunk boundary (multiple of 128 and 4)

// ---------------- scratch (static device globals; no allocation) ----------------
__device__ float g_msg_input[(size_t)N_EDGES_C * HID];
__device__ float g_msg      [(size_t)N_EDGES_C * HID];
__device__ float g_msgB     [(size_t)N_EDGES_C * HID];
__device__ float g_accum    [(size_t)N_EDGES_C * HID];
__device__ float g_alpha    [(size_t)N_NODES_C * HID];
__device__ float g_mplus    [(size_t)N_NODES_C * HID];
__device__ float g_hbias    [(size_t)N_NODES_C * HID];
__device__ __half g_WhT_hi  [HID * HID];
__device__ __half g_WhT_lo  [HID * HID];
__device__ __half g_WoT_hi  [HID * HID];
__device__ __half g_WoT_lo  [HID * HID];
__device__ float g_counts   [NGRAPH];

// CSR structures
__device__ int g_lg_rowptr[N_EDGES_C + 1];
__device__ int g_lg_cursor[N_EDGES_C];
__device__ int g_lg_csr[N_LG_C];
__device__ int g_nd_rowptr[N_NODES_C + 1];
__device__ int g_nd_cursor[N_NODES_C];
__device__ int g_nd_csr[N_EDGES_C];
__device__ int g_part [1024];
__device__ int g_part2[1024];

// ---------------- PTX helpers (portable: sm_80/sm_90 level only) ----------------
__device__ __forceinline__ uint32_t smem_u32(const void* p) {
    uint32_t a;
    asm("{ .reg .u64 t; cvta.to.shared.u64 t, %1; cvt.u32.u64 %0, t; }" : "=r"(a) : "l"(p));
    return a;
}
__device__ __forceinline__ void red4(float* p, float a, float b, float c, float d) {
    asm volatile("red.global.add.v4.f32 [%0], {%1, %2, %3, %4};"
                 :: "l"(p), "f"(a), "f"(b), "f"(c), "f"(d) : "memory");
}
__device__ __forceinline__ void red2(float* p, float a, float b) {
    asm volatile("red.global.add.v2.f32 [%0], {%1, %2};"
                 :: "l"(p), "f"(a), "f"(b) : "memory");
}
__device__ __forceinline__ void ldsm4(uint32_t* r, uint32_t addr) {
    asm volatile("ldmatrix.sync.aligned.m8n8.x4.shared.b16 {%0,%1,%2,%3}, [%4];"
                 : "=r"(r[0]), "=r"(r[1]), "=r"(r[2]), "=r"(r[3]) : "r"(addr));
}
__device__ __forceinline__ void mma_f16(float* d, const uint32_t* a, const uint32_t* b) {
    asm volatile(
        "mma.sync.aligned.m16n8k16.row.col.f32.f16.f16.f32 "
        "{%0,%1,%2,%3}, {%4,%5,%6,%7}, {%8,%9}, {%0,%1,%2,%3};"
        : "+f"(d[0]), "+f"(d[1]), "+f"(d[2]), "+f"(d[3])
        : "r"(a[0]), "r"(a[1]), "r"(a[2]), "r"(a[3]), "r"(b[0]), "r"(b[1]));
}
__device__ __forceinline__ uint32_t h2u(__half2 h) { return *reinterpret_cast<uint32_t*>(&h); }
__device__ __forceinline__ void cp16(uint32_t dst, const void* src) {
    asm volatile("cp.async.cg.shared.global [%0], [%1], 16;" :: "r"(dst), "l"(src));
}
#define CP_COMMIT() asm volatile("cp.async.commit_group;" ::: "memory")
#define CP_WAIT0()  asm volatile("cp.async.wait_group 0;" ::: "memory")

// ---------------- CSR build kernels ----------------
__global__ void k_zeroi(int* __restrict__ p, int n) {
    int i = blockIdx.x * 256 + threadIdx.x;
    if (i < n) p[i] = 0;
}
__global__ void k_hist(const int* __restrict__ dst, int* __restrict__ cnt, int n) {
    int i = blockIdx.x * 256 + threadIdx.x;
    if (i < n) atomicAdd(&cnt[dst[i]], 1);
}
__global__ void k_scan1(const int* __restrict__ cnt, int* __restrict__ ex, int n,
                        int* __restrict__ part) {
    __shared__ int sh[256];
    int base = blockIdx.x * 1024;
    int t = threadIdx.x;
    int v[4], s = 0;
#pragma unroll
    for (int j = 0; j < 4; j++) {
        int i = base + t * 4 + j;
        v[j] = (i < n) ? cnt[i] : 0;
        s += v[j];
    }
    sh[t] = s;
    __syncthreads();
    for (int off = 1; off < 256; off <<= 1) {
        int x = (t >= off) ? sh[t - off] : 0;
        __syncthreads();
        sh[t] += x;
        __syncthreads();
    }
    int run = (t > 0) ? sh[t - 1] : 0;
    if (part && t == 255) part[blockIdx.x] = sh[255];
#pragma unroll
    for (int j = 0; j < 4; j++) {
        int i = base + t * 4 + j;
        if (i < n) ex[i] = run;
        run += v[j];
    }
}
__global__ void k_scan3(int* __restrict__ ex, int* __restrict__ cursor,
                        const int* __restrict__ part2, int n, int ntot) {
    int i = blockIdx.x * 256 + threadIdx.x;
    if (i < n) {
        int v = ex[i] + part2[i >> 10];
        ex[i] = v;
        cursor[i] = v;
    }
    if (i == 0) ex[n] = ntot;
}
__global__ void k_fill(const int* __restrict__ src, const int* __restrict__ dst,
                       int* __restrict__ cursor, int* __restrict__ csr, int n) {
    int i = blockIdx.x * 256 + threadIdx.x;
    if (i < n) {
        int pos = atomicAdd(&cursor[dst[i]], 1);
        csr[pos] = src[i];
    }
}
__global__ void k_fill_id(const int* __restrict__ dst, int* __restrict__ cursor,
                          int* __restrict__ csr, int n) {
    int i = blockIdx.x * 256 + threadIdx.x;
    if (i < n) {
        int pos = atomicAdd(&cursor[dst[i]], 1);
        csr[pos] = i;
    }
}

// ---------------- utility kernels ----------------
__global__ void k_zero_alpha() {
    int i = blockIdx.x * 256 + threadIdx.x;
    ((float4*)g_alpha)[i] = make_float4(0.f, 0.f, 0.f, 0.f);
}
__global__ void k_zero_out(float* __restrict__ out) {
    int i = blockIdx.x * 256 + threadIdx.x;
    ((float4*)out)[i] = make_float4(0.f, 0.f, 0.f, 0.f);
    if (i < NGRAPH) g_counts[i] = 0.f;
}
__global__ void k_counts(const int* __restrict__ gids) {
    int v = blockIdx.x * 256 + threadIdx.x;
    if (v < N_NODES_C) atomicAdd(&g_counts[gids[v]], 1.0f);
}
__global__ void k_div(float* __restrict__ out) {
    int i = blockIdx.x * 256 + threadIdx.x;
    int g = i >> 6;
    float c = fmaxf(g_counts[g], 1.0f);
    float4 v = ((float4*)out)[i];
    v.x /= c; v.y /= c; v.z /= c; v.w /= c;
    ((float4*)out)[i] = v;
}
// pre-split W to fp16 hi/lo, transposed to [n][k]
__global__ void k_prep_w(const float* __restrict__ Wh, const float* __restrict__ Wo) {
    int n = blockIdx.x & 255;
    int k = threadIdx.x;
    float v;
    __half* hi;
    __half* lo;
    if (blockIdx.x < 256) { v = Wh[k * 256 + n];         hi = g_WhT_hi; lo = g_WhT_lo; }
    else                  { v = Wo[(AFD + k) * 256 + n]; hi = g_WoT_hi; lo = g_WoT_lo; }
    __half h = __float2half_rn(v);
    hi[n * 256 + k] = h;
    lo[n * 256 + k] = __float2half_rn(v - __half2float(h));
}
__global__ void k_tree_scatter(const float* __restrict__ tree, const int* __restrict__ tgt) {
    int i = blockIdx.x * 256 + threadIdx.x;
    int t = i >> 6, q = i & 63;
    float4 v = ((const float4*)tree)[(size_t)t * 64 + q];
    red4(g_alpha + (size_t)tgt[t] * HID + q * 4, v.x, v.y, v.z, v.w);
}

// ---------------- CSR gather: accum[e] = alpha[esrc[e]] + sum src[lg_csr[...]] --------
template<bool FIRST>
__global__ __launch_bounds__(256)
void k_lg_gather(const int* __restrict__ esrc, const float* __restrict__ src,
                 int e_off, int e_cnt) {
    int i = blockIdx.x * 256 + threadIdx.x;
    int e = e_off + (i >> 6), q = i & 63;
    if (e >= e_off + e_cnt) return;
    int a = __ldg(&esrc[e]);
    float4 acc = ((const float4*)g_alpha)[(size_t)a * 64 + q];
    int beg = __ldg(&g_lg_rowptr[e]);
    int end = __ldg(&g_lg_rowptr[e + 1]);
    const float4* s4 = (const float4*)src;
    for (int j = beg; j < end; j++) {
        int s = __ldg(&g_lg_csr[j]);
        float4 v = s4[(size_t)s * 64 + q];
        if (FIRST) {
            v.x = fmaxf(v.x, 0.f); v.y = fmaxf(v.y, 0.f);
            v.z = fmaxf(v.z, 0.f); v.w = fmaxf(v.w, 0.f);
        }
        acc.x += v.x; acc.y += v.y; acc.z += v.z; acc.w += v.w;
    }
    ((float4*)g_accum)[(size_t)e * 64 + q] = acc;
}

// mplus[v] = alpha[v] + sum msg[nd_csr[...]]
__global__ __launch_bounds__(256)
void k_node_gather(const float* __restrict__ msg, int v_off, int v_cnt) {
    int i = blockIdx.x * 256 + threadIdx.x;
    int v = v_off + (i >> 6), q = i & 63;
    if (v >= v_off + v_cnt) return;
    float4 acc = ((const float4*)g_alpha)[(size_t)v * 64 + q];
    int beg = __ldg(&g_nd_rowptr[v]);
    int end = __ldg(&g_nd_rowptr[v + 1]);
    const float4* m4 = (const float4*)msg;
    for (int j = beg; j < end; j++) {
        int s = __ldg(&g_nd_csr[j]);
        float4 m = m4[(size_t)s * 64 + q];
        acc.x += m.x; acc.y += m.y; acc.z += m.z; acc.w += m.w;
    }
    ((float4*)g_mplus)[(size_t)v * 64 + q] = acc;
}

// ---------------- msg_input = [node_x[src]; bond_x] @ W_i ----------------
__global__ __launch_bounds__(256)
void k_msg_in(const float* __restrict__ node_x, const float* __restrict__ bond_x,
              const float* __restrict__ W_i, const int* __restrict__ esrc) {
    __shared__ float feat[64][KIN];
    int e0 = blockIdx.x * 64;
    int tid = threadIdx.x;
    float w[KIN];
#pragma unroll
    for (int k = 0; k < KIN; k++) w[k] = W_i[k * HID + tid];
    for (int idx = tid; idx < 64 * KIN; idx += 256) {
        int e = idx / KIN, k = idx % KIN;
        int ge = e0 + e;
        float vv = 0.f;
        if (ge < N_EDGES_C)
            vv = (k < AFD) ? node_x[(size_t)esrc[ge] * AFD + k]
                           : bond_x[(size_t)ge * BFD + (k - AFD)];
        feat[e][k] = vv;
    }
    __syncthreads();
    for (int e = 0; e < 64; e++) {
        int ge = e0 + e;
        if (ge >= N_EDGES_C) break;
        const float4* f4 = (const float4*)feat[e];
        float a0 = 0.f, a1 = 0.f;
#pragma unroll
        for (int k4 = 0; k4 < KIN / 4; k4++) {
            float4 ff = f4[k4];
            a0 = fmaf(ff.x, w[k4 * 4 + 0], a0);
            a1 = fmaf(ff.y, w[k4 * 4 + 1], a1);
            a0 = fmaf(ff.z, w[k4 * 4 + 2], a0);
            a1 = fmaf(ff.w, w[k4 * 4 + 3], a1);
        }
        g_msg_input[(size_t)ge * HID + tid] = a0 + a1;
    }
}

// ---------------- g_hbias = node_x @ W_o[:35] + b_o ----------------
__global__ __launch_bounds__(256)
void k_hbias(const float* __restrict__ node_x, const float* __restrict__ W_o,
             const float* __restrict__ b_o) {
    __shared__ float feat[64][36];
    int v0 = blockIdx.x * 64;
    int tid = threadIdx.x;
    float w[36];
#pragma unroll
    for (int k = 0; k < AFD; k++) w[k] = W_o[k * HID + tid];
    w[35] = 0.f;
    float bb = b_o[tid];
    for (int idx = tid; idx < 64 * 36; idx += 256) {
        int v = idx / 36, k = idx % 36;
        int gv = v0 + v;
        feat[v][k] = (gv < N_NODES_C && k < AFD) ? node_x[(size_t)gv * AFD + k] : 0.f;
    }
    __syncthreads();
    for (int v = 0; v < 64; v++) {
        int gv = v0 + v;
        if (gv >= N_NODES_C) break;
        const float4* f4 = (const float4*)feat[v];
        float a0 = bb, a1 = 0.f;
#pragma unroll
        for (int k4 = 0; k4 < 9; k4++) {
            float4 ff = f4[k4];
            a0 = fmaf(ff.x, w[k4 * 4 + 0], a0);
            a1 = fmaf(ff.y, w[k4 * 4 + 1], a1);
            a0 = fmaf(ff.z, w[k4 * 4 + 2], a0);
            a1 = fmaf(ff.w, w[k4 * 4 + 3], a1);
        }
        g_hbias[(size_t)gv * HID + tid] = a0 + a1;
    }
}

// ---------------- wide-N fp16-split GEMM (A linear from accum buffer) ----------------
// D[128,256] = A[M,256] @ B^T; 2-term fp16 split (3 mma terms); B pre-split hi/lo.
// B fragments loaded 2 n-tiles at a time via ldmatrix.x4.
// MODE 0: dst = relu(bias + D)           (A = g_accum, dst = msg buffer)
// MODE 1: out[gids[row]] += relu(bias+D) (A = g_mplus)
#define MMW_BUF  98304
#define MMW_SMEM (2 * MMW_BUF)

template<int MODE>
__global__ __launch_bounds__(512, 1)
void k_mmw(const float* __restrict__ A, const float* __restrict__ bias,
           const __half* __restrict__ Bhi, const __half* __restrict__ Blo,
           float* __restrict__ dst, const int* __restrict__ gids,
           float* __restrict__ out, int m_off, int M) {
    extern __shared__ char sm[];
    const int tid  = threadIdx.x;
    const int lane = tid & 31;
    const int wid  = tid >> 5;
    const int wm   = wid >> 2;
    const int wn   = wid & 3;
    const int m0   = m_off + blockIdx.x * 128;
    const uint32_t sbase = smem_u32(sm);

    float d[2][8][4];
#pragma unroll
    for (int i = 0; i < 2; i++)
#pragma unroll
        for (int j = 0; j < 8; j++)
#pragma unroll
            for (int q = 0; q < 4; q++) d[i][j][q] = 0.f;

    float4 pfA[4];

    auto ldgA = [&](int cc) {
#pragma unroll
        for (int j = 0; j < 4; j++) {
            int idx = tid + j * 512;
            int row = idx >> 4, seg = idx & 15;
            int gm = m0 + row;
            pfA[j] = make_float4(0.f, 0.f, 0.f, 0.f);
            if (gm < M)
                pfA[j] = __ldg((const float4*)A + (size_t)gm * 64 + cc * 16 + seg);
        }
    };
    auto stsA = [&](int b) {
        char* buf = sm + b * MMW_BUF;
#pragma unroll
        for (int j = 0; j < 4; j++) {
            int idx = tid + j * 512;
            int row = idx >> 4, seg = idx & 15;
            uint32_t off = (uint32_t)(row * 128 + seg * 8);
            uint32_t sw = off ^ ((off >> 3) & 0x70);
            float4 v = pfA[j];
            __half2 h01 = __floats2half2_rn(v.x, v.y);
            __half2 h23 = __floats2half2_rn(v.z, v.w);
            __half2 l01 = __floats2half2_rn(v.x - __low2float(h01), v.y - __high2float(h01));
            __half2 l23 = __floats2half2_rn(v.z - __low2float(h23), v.w - __high2float(h23));
            *(uint2*)(buf + sw)         = make_uint2(h2u(h01), h2u(h23));
            *(uint2*)(buf + 16384 + sw) = make_uint2(h2u(l01), h2u(l23));
        }
    };
    auto cpB = [&](int cc, int b) {
        uint32_t base = sbase + b * MMW_BUF;
#pragma unroll
        for (int j = 0; j < 8; j++) {
            int idx = tid + j * 512;
            int u = idx & 2047;
            int row = u >> 3, seg = u & 7;
            uint32_t off = (uint32_t)(row * 128 + seg * 16);
            uint32_t sw = off ^ ((off >> 3) & 0x70);
            const __half* src = (idx < 2048) ? Bhi : Blo;
            uint32_t dsm = base + ((idx < 2048) ? 32768u : 65536u) + sw;
            cp16(dsm, src + (size_t)row * 256 + cc * 64 + seg * 8);
        }
        CP_COMMIT();
    };
    auto compute = [&](int b) {
        uint32_t baseA  = sbase + b * MMW_BUF;
        uint32_t baseAl = baseA + 16384;
        uint32_t baseBh = baseA + 32768;
        uint32_t baseBl = baseA + 65536;
        const int r = lane & 7, q = lane >> 3;
        const int bro = ((q >> 1) << 3) + r;
        const int bkp = (q & 1) << 4;
#pragma unroll
        for (int s = 0; s < 4; s++) {
            uint32_t ah[2][4], al[2][4];
#pragma unroll
            for (int mt = 0; mt < 2; mt++) {
                uint32_t mrow = (uint32_t)(wm * 32 + mt * 16 + (q & 1) * 8 + r);
                uint32_t off = mrow * 128 + (q >> 1) * 16 + s * 32;
                uint32_t sw = off ^ ((off >> 3) & 0x70);
                ldsm4(ah[mt], baseA + sw);
                ldsm4(al[mt], baseAl + sw);
            }
#pragma unroll
            for (int h = 0; h < 2; h++) {
                uint32_t bh4[2][4], bl4[2][4];
#pragma unroll
                for (int ntp = 0; ntp < 2; ntp++) {
                    uint32_t nrow = (uint32_t)(wn * 64 + h * 32 + ntp * 16 + bro);
                    uint32_t off = nrow * 128 + bkp + s * 32;
                    uint32_t sw = off ^ ((off >> 3) & 0x70);
                    ldsm4(bh4[ntp], baseBh + sw);
                    ldsm4(bl4[ntp], baseBl + sw);
                }
#pragma unroll
                for (int mt = 0; mt < 2; mt++)
#pragma unroll
                    for (int nt = 0; nt < 4; nt++) {
                        float* acc = d[mt][h * 4 + nt];
                        const uint32_t* bhp = &bh4[nt >> 1][(nt & 1) * 2];
                        const uint32_t* blp = &bl4[nt >> 1][(nt & 1) * 2];
                        mma_f16(acc, ah[mt], bhp);
                        mma_f16(acc, ah[mt], blp);
                        mma_f16(acc, al[mt], bhp);
                    }
            }
        }
    };

    cpB(0, 0);
    ldgA(0);
    stsA(0);
    CP_WAIT0();
    __syncthreads();

#pragma unroll
    for (int c = 0; c < 4; c++) {
        if (c < 3) {
            cpB(c + 1, (c + 1) & 1);
            ldgA(c + 1);
        }
        compute(c & 1);
        if (c < 3) stsA((c + 1) & 1);
        CP_WAIT0();
        __syncthreads();
    }

#pragma unroll
    for (int mt = 0; mt < 2; mt++) {
#pragma unroll
        for (int n = 0; n < 8; n++) {
            int row = m0 + wm * 32 + mt * 16 + (lane >> 2);
            int col = wn * 64 + n * 8 + (lane & 3) * 2;
#pragma unroll
            for (int h2 = 0; h2 < 2; h2++) {
                int gr = row + h2 * 8;
                if (gr >= M) continue;
                size_t gb = (size_t)gr * 256 + col;
                float2 bv = *(const float2*)(bias + gb);
                float ox = fmaxf(bv.x + d[mt][n][h2 * 2 + 0], 0.f);
                float oy = fmaxf(bv.y + d[mt][n][h2 * 2 + 1], 0.f);
                if (MODE == 0) {
                    *(float2*)(dst + gb) = make_float2(ox, oy);
                } else {
                    int g = gids[gr];
                    red2(out + (size_t)g * 256 + col, ox, oy);
                }
            }
        }
    }
}

// ---------------- launch ----------------
extern "C" void kernel_launch(void* const* d_in, const int* in_sizes, int n_in,
                              void* d_out, int out_size) {
    (void)in_sizes; (void)n_in; (void)out_size;
    const float* node_x = (const float*)d_in[0];
    const float* bond_x = (const float*)d_in[1];
    const float* tree   = (const float*)d_in[2];
    const float* W_i    = (const float*)d_in[3];
    const float* W_h    = (const float*)d_in[4];
    const float* W_o    = (const float*)d_in[5];
    const float* b_o    = (const float*)d_in[6];
    const int* esrc = (const int*)d_in[7];
    const int* edst = (const int*)d_in[8];
    const int* lsrc = (const int*)d_in[9];
    const int* ldst = (const int*)d_in[10];
    const int* tgt  = (const int*)d_in[11];
    const int* gids = (const int*)d_in[12];
    float* out = (float*)d_out;

    // one-time host-side resources (streams/events are not device memory)
    static cudaStream_t s1 = nullptr;
    static cudaEvent_t ev[12];
    if (!s1) {
        cudaStreamCreateWithFlags(&s1, cudaStreamNonBlocking);
        for (int i = 0; i < 12; i++)
            cudaEventCreateWithFlags(&ev[i], cudaEventDisableTiming);
        cudaFuncSetAttribute(k_mmw<0>, cudaFuncAttributeMaxDynamicSharedMemorySize, MMW_SMEM);
        cudaFuncSetAttribute(k_mmw<1>, cudaFuncAttributeMaxDynamicSharedMemorySize, MMW_SMEM);
    }

    float *hb_p, *mi_p, *msg_p, *msgB_p, *acc_p, *mp_p;
    cudaGetSymbolAddress((void**)&hb_p,   g_hbias);
    cudaGetSymbolAddress((void**)&mi_p,   g_msg_input);
    cudaGetSymbolAddress((void**)&msg_p,  g_msg);
    cudaGetSymbolAddress((void**)&msgB_p, g_msgB);
    cudaGetSymbolAddress((void**)&acc_p,  g_accum);
    cudaGetSymbolAddress((void**)&mp_p,   g_mplus);
    __half *WhH, *WhL, *WoH, *WoL;
    cudaGetSymbolAddress((void**)&WhH, g_WhT_hi);
    cudaGetSymbolAddress((void**)&WhL, g_WhT_lo);
    cudaGetSymbolAddress((void**)&WoH, g_WoT_hi);
    cudaGetSymbolAddress((void**)&WoL, g_WoT_lo);
    int *lg_rp, *lg_cur, *lg_csr_p, *nd_rp, *nd_cur, *nd_csr_p, *part_p, *part2_p;
    cudaGetSymbolAddress((void**)&lg_rp,    g_lg_rowptr);
    cudaGetSymbolAddress((void**)&lg_cur,   g_lg_cursor);
    cudaGetSymbolAddress((void**)&lg_csr_p, g_lg_csr);
    cudaGetSymbolAddress((void**)&nd_rp,    g_nd_rowptr);
    cudaGetSymbolAddress((void**)&nd_cur,   g_nd_cursor);
    cudaGetSymbolAddress((void**)&nd_csr_p, g_nd_csr);
    cudaGetSymbolAddress((void**)&part_p,   g_part);
    cudaGetSymbolAddress((void**)&part2_p,  g_part2);

    int evi = 0;

    // ==== fork side stream ====
    cudaEventRecord(ev[evi], 0);
    cudaStreamWaitEvent(s1, ev[evi], 0);
    evi++;

    // ---- side stream: CSR builds + weight prep + hbias + out/counts init ----
    k_zeroi<<<1172, 256, 0, s1>>>(lg_cur, N_EDGES_C);
    k_hist<<<2344, 256, 0, s1>>>(ldst, lg_cur, N_LG_C);
    k_scan1<<<293, 256, 0, s1>>>(lg_cur, lg_rp, N_EDGES_C, part_p);
    k_scan1<<<1, 256, 0, s1>>>(part_p, part2_p, 293, nullptr);
    k_scan3<<<1172, 256, 0, s1>>>(lg_rp, lg_cur, part2_p, N_EDGES_C, N_LG_C);
    k_fill<<<2344, 256, 0, s1>>>(lsrc, ldst, lg_cur, lg_csr_p, N_LG_C);
    k_zeroi<<<586, 256, 0, s1>>>(nd_cur, N_NODES_C);
    k_hist<<<1172, 256, 0, s1>>>(edst, nd_cur, N_EDGES_C);
    k_scan1<<<147, 256, 0, s1>>>(nd_cur, nd_rp, N_NODES_C, part_p);
    k_scan1<<<1, 256, 0, s1>>>(part_p, part2_p, 147, nullptr);
    k_scan3<<<586, 256, 0, s1>>>(nd_rp, nd_cur, part2_p, N_NODES_C, N_EDGES_C);
    k_fill_id<<<1172, 256, 0, s1>>>(edst, nd_cur, nd_csr_p, N_EDGES_C);
    k_prep_w<<<512, 256, 0, s1>>>(W_h, W_o);
    k_hbias<<<(N_NODES_C + 63) / 64, 256, 0, s1>>>(node_x, W_o, b_o);
    k_zero_out<<<512, 256, 0, s1>>>(out);
    k_counts<<<586, 256, 0, s1>>>(gids);

    // ---- main stream: alpha + msg_input ----
    k_zero_alpha<<<37500, 256>>>();
    k_tree_scatter<<<15000, 256>>>(tree, tgt);
    k_msg_in<<<(N_EDGES_C + 63) / 64, 256>>>(node_x, bond_x, W_i, esrc);

    // ==== join ====
    cudaEventRecord(ev[evi], s1);
    cudaStreamWaitEvent(0, ev[evi], 0);
    evi++;

    // ==== BP iterations: pipelined chunks G0 -> [M0 || G1] -> M1 ====
    const float* srcb[3] = { mi_p, msg_p, msgB_p };
    float*       dstb[3] = { msg_p, msgB_p, msg_p };
    const int E1 = N_EDGES_C - E_SPLIT;               // 149984
    for (int it = 0; it < 3; it++) {
        // G0 on main
        if (it == 0) k_lg_gather<true><<<E_SPLIT / 4, 256>>>(esrc, srcb[it], 0, E_SPLIT);
        else         k_lg_gather<false><<<E_SPLIT / 4, 256>>>(esrc, srcb[it], 0, E_SPLIT);
        cudaEventRecord(ev[evi], 0);
        cudaStreamWaitEvent(s1, ev[evi], 0);
        evi++;
        // G1 on side
        if (it == 0) k_lg_gather<true><<<E1 / 4, 256, 0, s1>>>(esrc, srcb[it], E_SPLIT, E1);
        else         k_lg_gather<false><<<E1 / 4, 256, 0, s1>>>(esrc, srcb[it], E_SPLIT, E1);
        // M0 on main (rows [0, E_SPLIT))
        k_mmw<0><<<E_SPLIT / 128, 512, MMW_SMEM>>>(acc_p, mi_p, WhH, WhL, dstb[it],
                                                   nullptr, nullptr, 0, N_EDGES_C);
        // M1 on side (rows [E_SPLIT, N_EDGES))
        k_mmw<0><<<E_SPLIT / 128, 512, MMW_SMEM, s1>>>(acc_p, mi_p, WhH, WhL, dstb[it],
                                                       nullptr, nullptr, E_SPLIT, N_EDGES_C);
        // join side back to main
        cudaEventRecord(ev[evi], s1);
        cudaStreamWaitEvent(0, ev[evi], 0);
        evi++;
    }

    // ==== readout: NG0 -> [MM0 || NG1] -> MM1 ====
    const int V1 = N_NODES_C - V_SPLIT;               // 74992
    k_node_gather<<<V_SPLIT / 4, 256>>>(msg_p, 0, V_SPLIT);
    cudaEventRecord(ev[evi], 0);
    cudaStreamWaitEvent(s1, ev[evi], 0);
    evi++;
    k_node_gather<<<V1 / 4, 256, 0, s1>>>(msg_p, V_SPLIT, V1);
    k_mmw<1><<<V_SPLIT / 128, 512, MMW_SMEM>>>(mp_p, hb_p, WoH, WoL, nullptr,
                                               gids, out, 0, N_NODES_C);
    k_mmw<1><<<V_SPLIT / 128, 512, MMW_SMEM, s1>>>(mp_p, hb_p, WoH, WoL, nullptr,
                                                   gids, out, V_SPLIT, N_NODES_C);
    cudaEventRecord(ev[evi], s1);
    cudaStreamWaitEvent(0, ev[evi], 0);
    evi++;

    k_div<<<512, 256>>>(out);
}

// round 11
// speedup vs baseline: 1.0750x; 1.0750x over previous
#include <cuda_runtime.h>
#include <cuda_fp16.h>
#include <cstdint>

#define N_NODES_C 150000
#define N_EDGES_C 300000
#define N_LG_C    600000
#define HID       256
#define NGRAPH    2048
#define AFD       35
#define BFD       5
#define KIN       40

// ---------------- scratch (static device globals; no allocation) ----------------
__device__ float  g_msg_input[(size_t)N_EDGES_C * HID];
__device__ __half g_msgH [(size_t)N_EDGES_C * HID];
__device__ __half g_msgHB[(size_t)N_EDGES_C * HID];
// accum / mplus pre-split hi/lo planes, padded +128 rows for unconditional cp.async
__device__ __half g_accH[((size_t)N_EDGES_C + 128) * HID];
__device__ __half g_accL[((size_t)N_EDGES_C + 128) * HID];
__device__ __half g_mpH [((size_t)N_NODES_C + 128) * HID];
__device__ __half g_mpL [((size_t)N_NODES_C + 128) * HID];
__device__ float  g_alpha[(size_t)N_NODES_C * HID];
__device__ float  g_hbias[(size_t)N_NODES_C * HID];
__device__ __half g_WhT_hi[HID * HID];
__device__ __half g_WhT_lo[HID * HID];
__device__ __half g_WoT_hi[HID * HID];
__device__ __half g_WoT_lo[HID * HID];
__device__ float  g_counts[NGRAPH];

// CSR structures
__device__ int g_lg_rowptr[N_EDGES_C + 1];
__device__ int g_lg_cursor[N_EDGES_C];
__device__ int g_lg_csr[N_LG_C];
__device__ int g_nd_rowptr[N_NODES_C + 1];
__device__ int g_nd_cursor[N_NODES_C];
__device__ int g_nd_csr[N_EDGES_C];
__device__ int g_part [1024];
__device__ int g_part2[1024];

// ---------------- PTX helpers (portable: sm_80/sm_90 level only) ----------------
__device__ __forceinline__ uint32_t smem_u32(const void* p) {
    uint32_t a;
    asm("{ .reg .u64 t; cvta.to.shared.u64 t, %1; cvt.u32.u64 %0, t; }" : "=r"(a) : "l"(p));
    return a;
}
__device__ __forceinline__ void red4(float* p, float a, float b, float c, float d) {
    asm volatile("red.global.add.v4.f32 [%0], {%1, %2, %3, %4};"
                 :: "l"(p), "f"(a), "f"(b), "f"(c), "f"(d) : "memory");
}
__device__ __forceinline__ void red2(float* p, float a, float b) {
    asm volatile("red.global.add.v2.f32 [%0], {%1, %2};"
                 :: "l"(p), "f"(a), "f"(b) : "memory");
}
__device__ __forceinline__ void ldsm4(uint32_t* r, uint32_t addr) {
    asm volatile("ldmatrix.sync.aligned.m8n8.x4.shared.b16 {%0,%1,%2,%3}, [%4];"
                 : "=r"(r[0]), "=r"(r[1]), "=r"(r[2]), "=r"(r[3]) : "r"(addr));
}
__device__ __forceinline__ void mma_f16(float* d, const uint32_t* a, const uint32_t* b) {
    asm volatile(
        "mma.sync.aligned.m16n8k16.row.col.f32.f16.f16.f32 "
        "{%0,%1,%2,%3}, {%4,%5,%6,%7}, {%8,%9}, {%0,%1,%2,%3};"
        : "+f"(d[0]), "+f"(d[1]), "+f"(d[2]), "+f"(d[3])
        : "r"(a[0]), "r"(a[1]), "r"(a[2]), "r"(a[3]), "r"(b[0]), "r"(b[1]));
}
__device__ __forceinline__ uint32_t h2u(__half2 h) { return *reinterpret_cast<uint32_t*>(&h); }
__device__ __forceinline__ void cp16(uint32_t dst, const void* src) {
    asm volatile("cp.async.cg.shared.global [%0], [%1], 16;" :: "r"(dst), "l"(src));
}
#define CP_COMMIT() asm volatile("cp.async.commit_group;" ::: "memory")
#define CP_WAIT0()  asm volatile("cp.async.wait_group 0;" ::: "memory")

// ---------------- CSR build kernels ----------------
__global__ void k_zeroi(int* __restrict__ p, int n) {
    int i = blockIdx.x * 256 + threadIdx.x;
    if (i < n) p[i] = 0;
}
__global__ void k_hist(const int* __restrict__ dst, int* __restrict__ cnt, int n) {
    int i = blockIdx.x * 256 + threadIdx.x;
    if (i < n) atomicAdd(&cnt[dst[i]], 1);
}
__global__ void k_scan1(const int* __restrict__ cnt, int* __restrict__ ex, int n,
                        int* __restrict__ part) {
    __shared__ int sh[256];
    int base = blockIdx.x * 1024;
    int t = threadIdx.x;
    int v[4], s = 0;
#pragma unroll
    for (int j = 0; j < 4; j++) {
        int i = base + t * 4 + j;
        v[j] = (i < n) ? cnt[i] : 0;
        s += v[j];
    }
    sh[t] = s;
    __syncthreads();
    for (int off = 1; off < 256; off <<= 1) {
        int x = (t >= off) ? sh[t - off] : 0;
        __syncthreads();
        sh[t] += x;
        __syncthreads();
    }
    int run = (t > 0) ? sh[t - 1] : 0;
    if (part && t == 255) part[blockIdx.x] = sh[255];
#pragma unroll
    for (int j = 0; j < 4; j++) {
        int i = base + t * 4 + j;
        if (i < n) ex[i] = run;
        run += v[j];
    }
}
__global__ void k_scan3(int* __restrict__ ex, int* __restrict__ cursor,
                        const int* __restrict__ part2, int n, int ntot) {
    int i = blockIdx.x * 256 + threadIdx.x;
    if (i < n) {
        int v = ex[i] + part2[i >> 10];
        ex[i] = v;
        cursor[i] = v;
    }
    if (i == 0) ex[n] = ntot;
}
__global__ void k_fill(const int* __restrict__ src, const int* __restrict__ dst,
                       int* __restrict__ cursor, int* __restrict__ csr, int n) {
    int i = blockIdx.x * 256 + threadIdx.x;
    if (i < n) {
        int pos = atomicAdd(&cursor[dst[i]], 1);
        csr[pos] = src[i];
    }
}
__global__ void k_fill_id(const int* __restrict__ dst, int* __restrict__ cursor,
                          int* __restrict__ csr, int n) {
    int i = blockIdx.x * 256 + threadIdx.x;
    if (i < n) {
        int pos = atomicAdd(&cursor[dst[i]], 1);
        csr[pos] = i;
    }
}

// ---------------- utility kernels ----------------
__global__ void k_zero_alpha() {
    int i = blockIdx.x * 256 + threadIdx.x;
    ((float4*)g_alpha)[i] = make_float4(0.f, 0.f, 0.f, 0.f);
}
__global__ void k_zero_out(float* __restrict__ out) {
    int i = blockIdx.x * 256 + threadIdx.x;
    ((float4*)out)[i] = make_float4(0.f, 0.f, 0.f, 0.f);
    if (i < NGRAPH) g_counts[i] = 0.f;
}
__global__ void k_counts(const int* __restrict__ gids) {
    int v = blockIdx.x * 256 + threadIdx.x;
    if (v < N_NODES_C) atomicAdd(&g_counts[gids[v]], 1.0f);
}
__global__ void k_div(float* __restrict__ out) {
    int i = blockIdx.x * 256 + threadIdx.x;
    int g = i >> 6;
    float c = fmaxf(g_counts[g], 1.0f);
    float4 v = ((float4*)out)[i];
    v.x /= c; v.y /= c; v.z /= c; v.w /= c;
    ((float4*)out)[i] = v;
}
// pre-split W to fp16 hi/lo, transposed to [n][k]
__global__ void k_prep_w(const float* __restrict__ Wh, const float* __restrict__ Wo) {
    int n = blockIdx.x & 255;
    int k = threadIdx.x;
    float v;
    __half* hi;
    __half* lo;
    if (blockIdx.x < 256) { v = Wh[k * 256 + n];         hi = g_WhT_hi; lo = g_WhT_lo; }
    else                  { v = Wo[(AFD + k) * 256 + n]; hi = g_WoT_hi; lo = g_WoT_lo; }
    __half h = __float2half_rn(v);
    hi[n * 256 + k] = h;
    lo[n * 256 + k] = __float2half_rn(v - __half2float(h));
}
__global__ void k_tree_scatter(const float* __restrict__ tree, const int* __restrict__ tgt) {
    int i = blockIdx.x * 256 + threadIdx.x;
    int t = i >> 6, q = i & 63;
    float4 v = ((const float4*)tree)[(size_t)t * 64 + q];
    red4(g_alpha + (size_t)tgt[t] * HID + q * 4, v.x, v.y, v.z, v.w);
}

// split 4 floats -> hi/lo half4 (as uint2 each)
__device__ __forceinline__ void split4h(float4 v, uint2& hv, uint2& lv) {
    __half2 h01 = __floats2half2_rn(v.x, v.y);
    __half2 h23 = __floats2half2_rn(v.z, v.w);
    __half2 l01 = __floats2half2_rn(v.x - __low2float(h01), v.y - __high2float(h01));
    __half2 l23 = __floats2half2_rn(v.z - __low2float(h23), v.w - __high2float(h23));
    hv = make_uint2(h2u(h01), h2u(h23));
    lv = make_uint2(h2u(l01), h2u(l23));
}
__device__ __forceinline__ float4 h4tof4(uint2 u) {
    __half2 a = *reinterpret_cast<__half2*>(&u.x);
    __half2 b = *reinterpret_cast<__half2*>(&u.y);
    float2 fa = __half22float2(a);
    float2 fb = __half22float2(b);
    return make_float4(fa.x, fa.y, fb.x, fb.y);
}

// ---------------- CSR gather: acc[e] = alpha[esrc[e]] + sum src[lg_csr[...]] ----------
// writes pre-split hi/lo fp16 planes (exact w.r.t. the GEMM's own split)
template<bool FIRST>
__global__ __launch_bounds__(256)
void k_lg_gather(const int* __restrict__ esrc, const float* __restrict__ srcf,
                 const __half* __restrict__ srch) {
    int i = blockIdx.x * 256 + threadIdx.x;
    int e = i >> 6, q = i & 63;
    int a = __ldg(&esrc[e]);
    float4 acc = ((const float4*)g_alpha)[(size_t)a * 64 + q];
    int beg = __ldg(&g_lg_rowptr[e]);
    int end = __ldg(&g_lg_rowptr[e + 1]);
    for (int j = beg; j < end; j++) {
        int s = __ldg(&g_lg_csr[j]);
        float4 v;
        if (FIRST) {
            v = __ldg((const float4*)srcf + (size_t)s * 64 + q);
            v.x = fmaxf(v.x, 0.f); v.y = fmaxf(v.y, 0.f);
            v.z = fmaxf(v.z, 0.f); v.w = fmaxf(v.w, 0.f);
        } else {
            v = h4tof4(__ldg((const uint2*)srch + (size_t)s * 64 + q));
        }
        acc.x += v.x; acc.y += v.y; acc.z += v.z; acc.w += v.w;
    }
    uint2 hv, lv;
    split4h(acc, hv, lv);
    ((uint2*)g_accH)[(size_t)e * 64 + q] = hv;
    ((uint2*)g_accL)[(size_t)e * 64 + q] = lv;
}

// mplus[v] = alpha[v] + sum msg[nd_csr[...]]  (split planes)
__global__ __launch_bounds__(256)
void k_node_gather(const __half* __restrict__ msg) {
    int i = blockIdx.x * 256 + threadIdx.x;
    int v = i >> 6, q = i & 63;
    float4 acc = ((const float4*)g_alpha)[(size_t)v * 64 + q];
    int beg = __ldg(&g_nd_rowptr[v]);
    int end = __ldg(&g_nd_rowptr[v + 1]);
    for (int j = beg; j < end; j++) {
        int s = __ldg(&g_nd_csr[j]);
        float4 m = h4tof4(__ldg((const uint2*)msg + (size_t)s * 64 + q));
        acc.x += m.x; acc.y += m.y; acc.z += m.z; acc.w += m.w;
    }
    uint2 hv, lv;
    split4h(acc, hv, lv);
    ((uint2*)g_mpH)[(size_t)v * 64 + q] = hv;
    ((uint2*)g_mpL)[(size_t)v * 64 + q] = lv;
}

// ---------------- msg_input = [node_x[src]; bond_x] @ W_i ----------------
__global__ __launch_bounds__(256)
void k_msg_in(const float* __restrict__ node_x, const float* __restrict__ bond_x,
              const float* __restrict__ W_i, const int* __restrict__ esrc) {
    __shared__ float feat[64][KIN];
    int e0 = blockIdx.x * 64;
    int tid = threadIdx.x;
    float w[KIN];
#pragma unroll
    for (int k = 0; k < KIN; k++) w[k] = W_i[k * HID + tid];
    for (int idx = tid; idx < 64 * KIN; idx += 256) {
        int e = idx / KIN, k = idx % KIN;
        int ge = e0 + e;
        float vv = 0.f;
        if (ge < N_EDGES_C)
            vv = (k < AFD) ? node_x[(size_t)esrc[ge] * AFD + k]
                           : bond_x[(size_t)ge * BFD + (k - AFD)];
        feat[e][k] = vv;
    }
    __syncthreads();
    for (int e = 0; e < 64; e++) {
        int ge = e0 + e;
        if (ge >= N_EDGES_C) break;
        const float4* f4 = (const float4*)feat[e];
        float a0 = 0.f, a1 = 0.f;
#pragma unroll
        for (int k4 = 0; k4 < KIN / 4; k4++) {
            float4 ff = f4[k4];
            a0 = fmaf(ff.x, w[k4 * 4 + 0], a0);
            a1 = fmaf(ff.y, w[k4 * 4 + 1], a1);
            a0 = fmaf(ff.z, w[k4 * 4 + 2], a0);
            a1 = fmaf(ff.w, w[k4 * 4 + 3], a1);
        }
        g_msg_input[(size_t)ge * HID + tid] = a0 + a1;
    }
}

// ---------------- g_hbias = node_x @ W_o[:35] + b_o ----------------
__global__ __launch_bounds__(256)
void k_hbias(const float* __restrict__ node_x, const float* __restrict__ W_o,
             const float* __restrict__ b_o) {
    __shared__ float feat[64][36];
    int v0 = blockIdx.x * 64;
    int tid = threadIdx.x;
    float w[36];
#pragma unroll
    for (int k = 0; k < AFD; k++) w[k] = W_o[k * HID + tid];
    w[35] = 0.f;
    float bb = b_o[tid];
    for (int idx = tid; idx < 64 * 36; idx += 256) {
        int v = idx / 36, k = idx % 36;
        int gv = v0 + v;
        feat[v][k] = (gv < N_NODES_C && k < AFD) ? node_x[(size_t)gv * AFD + k] : 0.f;
    }
    __syncthreads();
    for (int v = 0; v < 64; v++) {
        int gv = v0 + v;
        if (gv >= N_NODES_C) break;
        const float4* f4 = (const float4*)feat[v];
        float a0 = bb, a1 = 0.f;
#pragma unroll
        for (int k4 = 0; k4 < 9; k4++) {
            float4 ff = f4[k4];
            a0 = fmaf(ff.x, w[k4 * 4 + 0], a0);
            a1 = fmaf(ff.y, w[k4 * 4 + 1], a1);
            a0 = fmaf(ff.z, w[k4 * 4 + 2], a0);
            a1 = fmaf(ff.w, w[k4 * 4 + 3], a1);
        }
        g_hbias[(size_t)gv * HID + tid] = a0 + a1;
    }
}

// ---------------- wide-N fp16-split GEMM (A pre-split planes via cp.async) -----------
// D[128,256] = A[M,256] @ B^T; 3 mma terms (AhBh + AhBl + AlBh); A and B pre-split.
// B fragments loaded 2 n-tiles at a time via ldmatrix.x4.
// MODE 0: dsth = relu(bias + D) as fp16    MODE 1: out[gids[row]] += relu(bias+D)
// SMEM per buffer: Ahi 16K | Alo 16K | Bhi 32K | Blo 32K = 96K, double-buffered.
#define MMW_BUF  98304
#define MMW_SMEM (2 * MMW_BUF)

template<int MODE>
__global__ __launch_bounds__(512, 1)
void k_mmw(const __half* __restrict__ Ahi, const __half* __restrict__ Alo,
           const float* __restrict__ bias,
           const __half* __restrict__ Bhi, const __half* __restrict__ Blo,
           __half* __restrict__ dsth, const int* __restrict__ gids,
           float* __restrict__ out, int M) {
    extern __shared__ char sm[];
    const int tid  = threadIdx.x;
    const int lane = tid & 31;
    const int wid  = tid >> 5;
    const int wm   = wid >> 2;
    const int wn   = wid & 3;
    const int m0   = blockIdx.x * 128;
    const uint32_t sbase = smem_u32(sm);

    float d[2][8][4];
#pragma unroll
    for (int i = 0; i < 2; i++)
#pragma unroll
        for (int j = 0; j < 8; j++)
#pragma unroll
            for (int q = 0; q < 4; q++) d[i][j][q] = 0.f;

    // A chunk: 128 rows x 64 halves per plane = 1024 x 16B; 2 planes = 2048 cp16
    auto cpA = [&](int cc, int b) {
        uint32_t base = sbase + b * MMW_BUF;
#pragma unroll
        for (int j = 0; j < 4; j++) {
            int idx = tid + j * 512;            // 0..2047
            int u = idx & 1023;
            int row = u >> 3, seg = u & 7;
            uint32_t off = (uint32_t)(row * 128 + seg * 16);
            uint32_t sw = off ^ ((off >> 3) & 0x70);
            const __half* src = (idx < 1024) ? Ahi : Alo;
            uint32_t dsm = base + ((idx < 1024) ? 0u : 16384u) + sw;
            cp16(dsm, src + (size_t)(m0 + row) * 256 + cc * 64 + seg * 8);
        }
    };
    // B chunk: 256 rows x 64 halves per plane = 2048 x 16B; 2 planes = 4096 cp16
    auto cpB = [&](int cc, int b) {
        uint32_t base = sbase + b * MMW_BUF;
#pragma unroll
        for (int j = 0; j < 8; j++) {
            int idx = tid + j * 512;            // 0..4095
            int u = idx & 2047;
            int row = u >> 3, seg = u & 7;
            uint32_t off = (uint32_t)(row * 128 + seg * 16);
            uint32_t sw = off ^ ((off >> 3) & 0x70);
            const __half* src = (idx < 2048) ? Bhi : Blo;
            uint32_t dsm = base + ((idx < 2048) ? 32768u : 65536u) + sw;
            cp16(dsm, src + (size_t)row * 256 + cc * 64 + seg * 8);
        }
    };
    auto compute = [&](int b) {
        uint32_t baseA  = sbase + b * MMW_BUF;
        uint32_t baseAl = baseA + 16384;
        uint32_t baseBh = baseA + 32768;
        uint32_t baseBl = baseA + 65536;
        const int r = lane & 7, q = lane >> 3;
        const int bro = ((q >> 1) << 3) + r;
        const int bkp = (q & 1) << 4;
#pragma unroll
        for (int s = 0; s < 4; s++) {
            uint32_t ah[2][4], al[2][4];
#pragma unroll
            for (int mt = 0; mt < 2; mt++) {
                uint32_t mrow = (uint32_t)(wm * 32 + mt * 16 + (q & 1) * 8 + r);
                uint32_t off = mrow * 128 + (q >> 1) * 16 + s * 32;
                uint32_t sw = off ^ ((off >> 3) & 0x70);
                ldsm4(ah[mt], baseA + sw);
                ldsm4(al[mt], baseAl + sw);
            }
#pragma unroll
            for (int h = 0; h < 2; h++) {
                uint32_t bh4[2][4], bl4[2][4];
#pragma unroll
                for (int ntp = 0; ntp < 2; ntp++) {
                    uint32_t nrow = (uint32_t)(wn * 64 + h * 32 + ntp * 16 + bro);
                    uint32_t off = nrow * 128 + bkp + s * 32;
                    uint32_t sw = off ^ ((off >> 3) & 0x70);
                    ldsm4(bh4[ntp], baseBh + sw);
                    ldsm4(bl4[ntp], baseBl + sw);
                }
#pragma unroll
                for (int mt = 0; mt < 2; mt++)
#pragma unroll
                    for (int nt = 0; nt < 4; nt++) {
                        float* acc = d[mt][h * 4 + nt];
                        const uint32_t* bhp = &bh4[nt >> 1][(nt & 1) * 2];
                        const uint32_t* blp = &bl4[nt >> 1][(nt & 1) * 2];
                        mma_f16(acc, ah[mt], bhp);
                        mma_f16(acc, ah[mt], blp);
                        mma_f16(acc, al[mt], bhp);
                    }
            }
        }
    };

    cpA(0, 0); cpB(0, 0); CP_COMMIT();
    CP_WAIT0();
    __syncthreads();

#pragma unroll
    for (int c = 0; c < 4; c++) {
        if (c < 3) { cpA(c + 1, (c + 1) & 1); cpB(c + 1, (c + 1) & 1); CP_COMMIT(); }
        compute(c & 1);
        if (c < 3) CP_WAIT0();
        __syncthreads();
    }

#pragma unroll
    for (int mt = 0; mt < 2; mt++) {
#pragma unroll
        for (int n = 0; n < 8; n++) {
            int row = m0 + wm * 32 + mt * 16 + (lane >> 2);
            int col = wn * 64 + n * 8 + (lane & 3) * 2;
#pragma unroll
            for (int h2 = 0; h2 < 2; h2++) {
                int gr = row + h2 * 8;
                if (gr >= M) continue;
                size_t gb = (size_t)gr * 256 + col;
                float2 bv = *(const float2*)(bias + gb);
                float ox = fmaxf(bv.x + d[mt][n][h2 * 2 + 0], 0.f);
                float oy = fmaxf(bv.y + d[mt][n][h2 * 2 + 1], 0.f);
                if (MODE == 0) {
                    __half2 hv = __floats2half2_rn(ox, oy);
                    *(uint32_t*)(dsth + gb) = h2u(hv);
                } else {
                    int g = gids[gr];
                    red2(out + (size_t)g * 256 + col, ox, oy);
                }
            }
        }
    }
}

// ---------------- launch ----------------
extern "C" void kernel_launch(void* const* d_in, const int* in_sizes, int n_in,
                              void* d_out, int out_size) {
    (void)in_sizes; (void)n_in; (void)out_size;
    const float* node_x = (const float*)d_in[0];
    const float* bond_x = (const float*)d_in[1];
    const float* tree   = (const float*)d_in[2];
    const float* W_i    = (const float*)d_in[3];
    const float* W_h    = (const float*)d_in[4];
    const float* W_o    = (const float*)d_in[5];
    const float* b_o    = (const float*)d_in[6];
    const int* esrc = (const int*)d_in[7];
    const int* edst = (const int*)d_in[8];
    const int* lsrc = (const int*)d_in[9];
    const int* ldst = (const int*)d_in[10];
    const int* tgt  = (const int*)d_in[11];
    const int* gids = (const int*)d_in[12];
    float* out = (float*)d_out;

    cudaFuncSetAttribute(k_mmw<0>, cudaFuncAttributeMaxDynamicSharedMemorySize, MMW_SMEM);
    cudaFuncSetAttribute(k_mmw<1>, cudaFuncAttributeMaxDynamicSharedMemorySize, MMW_SMEM);

    float *hb_p, *mi_p;
    cudaGetSymbolAddress((void**)&hb_p, g_hbias);
    cudaGetSymbolAddress((void**)&mi_p, g_msg_input);
    __half *msgH_p, *msgHB_p, *accH_p, *accL_p, *mpH_p, *mpL_p;
    cudaGetSymbolAddress((void**)&msgH_p,  g_msgH);
    cudaGetSymbolAddress((void**)&msgHB_p, g_msgHB);
    cudaGetSymbolAddress((void**)&accH_p,  g_accH);
    cudaGetSymbolAddress((void**)&accL_p,  g_accL);
    cudaGetSymbolAddress((void**)&mpH_p,   g_mpH);
    cudaGetSymbolAddress((void**)&mpL_p,   g_mpL);
    __half *WhH, *WhL, *WoH, *WoL;
    cudaGetSymbolAddress((void**)&WhH, g_WhT_hi);
    cudaGetSymbolAddress((void**)&WhL, g_WhT_lo);
    cudaGetSymbolAddress((void**)&WoH, g_WoT_hi);
    cudaGetSymbolAddress((void**)&WoL, g_WoT_lo);
    int *lg_rp, *lg_cur, *lg_csr_p, *nd_rp, *nd_cur, *nd_csr_p, *part_p, *part2_p;
    cudaGetSymbolAddress((void**)&lg_rp,    g_lg_rowptr);
    cudaGetSymbolAddress((void**)&lg_cur,   g_lg_cursor);
    cudaGetSymbolAddress((void**)&lg_csr_p, g_lg_csr);
    cudaGetSymbolAddress((void**)&nd_rp,    g_nd_rowptr);
    cudaGetSymbolAddress((void**)&nd_cur,   g_nd_cursor);
    cudaGetSymbolAddress((void**)&nd_csr_p, g_nd_csr);
    cudaGetSymbolAddress((void**)&part_p,   g_part);
    cudaGetSymbolAddress((void**)&part2_p,  g_part2);

    // ---- CSR build: line graph ----
    k_zeroi<<<1172, 256>>>(lg_cur, N_EDGES_C);
    k_hist<<<2344, 256>>>(ldst, lg_cur, N_LG_C);
    k_scan1<<<293, 256>>>(lg_cur, lg_rp, N_EDGES_C, part_p);
    k_scan1<<<1, 256>>>(part_p, part2_p, 293, nullptr);
    k_scan3<<<1172, 256>>>(lg_rp, lg_cur, part2_p, N_EDGES_C, N_LG_C);
    k_fill<<<2344, 256>>>(lsrc, ldst, lg_cur, lg_csr_p, N_LG_C);
    // ---- CSR build: node graph ----
    k_zeroi<<<586, 256>>>(nd_cur, N_NODES_C);
    k_hist<<<1172, 256>>>(edst, nd_cur, N_EDGES_C);
    k_scan1<<<147, 256>>>(nd_cur, nd_rp, N_NODES_C, part_p);
    k_scan1<<<1, 256>>>(part_p, part2_p, 147, nullptr);
    k_scan3<<<586, 256>>>(nd_rp, nd_cur, part2_p, N_NODES_C, N_EDGES_C);
    k_fill_id<<<1172, 256>>>(edst, nd_cur, nd_csr_p, N_EDGES_C);

    k_prep_w<<<512, 256>>>(W_h, W_o);
    k_zero_alpha<<<37500, 256>>>();
    k_zero_out<<<512, 256>>>(out);
    k_tree_scatter<<<15000, 256>>>(tree, tgt);
    k_msg_in<<<(N_EDGES_C + 63) / 64, 256>>>(node_x, bond_x, W_i, esrc);
    k_hbias<<<(N_NODES_C + 63) / 64, 256>>>(node_x, W_o, b_o);

    // BP iterations: msg ping-pong (mi fp32 -> msgH -> msgHB -> msgH)
    k_lg_gather<true><<<75000, 256>>>(esrc, mi_p, nullptr);
    k_mmw<0><<<2344, 512, MMW_SMEM>>>(accH_p, accL_p, mi_p, WhH, WhL,
                                      msgH_p, nullptr, nullptr, N_EDGES_C);
    k_lg_gather<false><<<75000, 256>>>(esrc, nullptr, msgH_p);
    k_mmw<0><<<2344, 512, MMW_SMEM>>>(accH_p, accL_p, mi_p, WhH, WhL,
                                      msgHB_p, nullptr, nullptr, N_EDGES_C);
    k_lg_gather<false><<<75000, 256>>>(esrc, nullptr, msgHB_p);
    k_mmw<0><<<2344, 512, MMW_SMEM>>>(accH_p, accL_p, mi_p, WhH, WhL,
                                      msgH_p, nullptr, nullptr, N_EDGES_C);

    k_node_gather<<<37500, 256>>>(msgH_p);
    k_counts<<<586, 256>>>(gids);
    k_mmw<1><<<1172, 512, MMW_SMEM>>>(mpH_p, mpL_p, hb_p, WoH, WoL,
                                      nullptr, gids, out, N_NODES_C);
    k_div<<<512, 256>>>(out);
}

// round 12
// speedup vs baseline: 1.3057x; 1.2146x over previous
#include <cuda_runtime.h>
#include <cuda_fp16.h>
#include <cstdint>

#define N_NODES_C 150000
#define N_EDGES_C 300000
#define N_LG_C    600000
#define HID       256
#define NGRAPH    2048
#define AFD       35
#define BFD       5
#define KIN       40

// ---------------- scratch (static device globals; no allocation) ----------------
__device__ float  g_msg_input[(size_t)N_EDGES_C * HID];
__device__ __half g_msgH [(size_t)N_EDGES_C * HID];
__device__ __half g_msgHB[(size_t)N_EDGES_C * HID];
// accum / mplus single fp16 plane, padded +128 rows for unconditional cp.async
__device__ __half g_accH[((size_t)N_EDGES_C + 128) * HID];
__device__ __half g_mpH [((size_t)N_NODES_C + 128) * HID];
__device__ float  g_alpha[(size_t)N_NODES_C * HID];
__device__ float  g_hbias[(size_t)N_NODES_C * HID];
__device__ __half g_WhT_hi[HID * HID];
__device__ __half g_WhT_lo[HID * HID];
__device__ __half g_WoT_hi[HID * HID];
__device__ __half g_WoT_lo[HID * HID];
__device__ float  g_counts[NGRAPH];

// CSR structures
__device__ int g_lg_rowptr[N_EDGES_C + 1];
__device__ int g_lg_cursor[N_EDGES_C];
__device__ int g_lg_csr[N_LG_C];
__device__ int g_nd_rowptr[N_NODES_C + 1];
__device__ int g_nd_cursor[N_NODES_C];
__device__ int g_nd_csr[N_EDGES_C];
__device__ int g_part [1024];
__device__ int g_part2[1024];

// ---------------- PTX helpers (portable: sm_80/sm_90 level only) ----------------
__device__ __forceinline__ uint32_t smem_u32(const void* p) {
    uint32_t a;
    asm("{ .reg .u64 t; cvta.to.shared.u64 t, %1; cvt.u32.u64 %0, t; }" : "=r"(a) : "l"(p));
    return a;
}
__device__ __forceinline__ void red4(float* p, float a, float b, float c, float d) {
    asm volatile("red.global.add.v4.f32 [%0], {%1, %2, %3, %4};"
                 :: "l"(p), "f"(a), "f"(b), "f"(c), "f"(d) : "memory");
}
__device__ __forceinline__ void red2(float* p, float a, float b) {
    asm volatile("red.global.add.v2.f32 [%0], {%1, %2};"
                 :: "l"(p), "f"(a), "f"(b) : "memory");
}
__device__ __forceinline__ void ldsm4(uint32_t* r, uint32_t addr) {
    asm volatile("ldmatrix.sync.aligned.m8n8.x4.shared.b16 {%0,%1,%2,%3}, [%4];"
                 : "=r"(r[0]), "=r"(r[1]), "=r"(r[2]), "=r"(r[3]) : "r"(addr));
}
__device__ __forceinline__ void mma_f16(float* d, const uint32_t* a, const uint32_t* b) {
    asm volatile(
        "mma.sync.aligned.m16n8k16.row.col.f32.f16.f16.f32 "
        "{%0,%1,%2,%3}, {%4,%5,%6,%7}, {%8,%9}, {%0,%1,%2,%3};"
        : "+f"(d[0]), "+f"(d[1]), "+f"(d[2]), "+f"(d[3])
        : "r"(a[0]), "r"(a[1]), "r"(a[2]), "r"(a[3]), "r"(b[0]), "r"(b[1]));
}
__device__ __forceinline__ uint32_t h2u(__half2 h) { return *reinterpret_cast<uint32_t*>(&h); }
__device__ __forceinline__ void cp16(uint32_t dst, const void* src) {
    asm volatile("cp.async.cg.shared.global [%0], [%1], 16;" :: "r"(dst), "l"(src));
}
#define CP_COMMIT() asm volatile("cp.async.commit_group;" ::: "memory")
#define CP_WAIT0()  asm volatile("cp.async.wait_group 0;" ::: "memory")

// ---------------- CSR build kernels ----------------
__global__ void k_zeroi(int* __restrict__ p, int n) {
    int i = blockIdx.x * 256 + threadIdx.x;
    if (i < n) p[i] = 0;
}
__global__ void k_hist(const int* __restrict__ dst, int* __restrict__ cnt, int n) {
    int i = blockIdx.x * 256 + threadIdx.x;
    if (i < n) atomicAdd(&cnt[dst[i]], 1);
}
__global__ void k_scan1(const int* __restrict__ cnt, int* __restrict__ ex, int n,
                        int* __restrict__ part) {
    __shared__ int sh[256];
    int base = blockIdx.x * 1024;
    int t = threadIdx.x;
    int v[4], s = 0;
#pragma unroll
    for (int j = 0; j < 4; j++) {
        int i = base + t * 4 + j;
        v[j] = (i < n) ? cnt[i] : 0;
        s += v[j];
    }
    sh[t] = s;
    __syncthreads();
    for (int off = 1; off < 256; off <<= 1) {
        int x = (t >= off) ? sh[t - off] : 0;
        __syncthreads();
        sh[t] += x;
        __syncthreads();
    }
    int run = (t > 0) ? sh[t - 1] : 0;
    if (part && t == 255) part[blockIdx.x] = sh[255];
#pragma unroll
    for (int j = 0; j < 4; j++) {
        int i = base + t * 4 + j;
        if (i < n) ex[i] = run;
        run += v[j];
    }
}
__global__ void k_scan3(int* __restrict__ ex, int* __restrict__ cursor,
                        const int* __restrict__ part2, int n, int ntot) {
    int i = blockIdx.x * 256 + threadIdx.x;
    if (i < n) {
        int v = ex[i] + part2[i >> 10];
        ex[i] = v;
        cursor[i] = v;
    }
    if (i == 0) ex[n] = ntot;
}
__global__ void k_fill(const int* __restrict__ src, const int* __restrict__ dst,
                       int* __restrict__ cursor, int* __restrict__ csr, int n) {
    int i = blockIdx.x * 256 + threadIdx.x;
    if (i < n) {
        int pos = atomicAdd(&cursor[dst[i]], 1);
        csr[pos] = src[i];
    }
}
__global__ void k_fill_id(const int* __restrict__ dst, int* __restrict__ cursor,
                          int* __restrict__ csr, int n) {
    int i = blockIdx.x * 256 + threadIdx.x;
    if (i < n) {
        int pos = atomicAdd(&cursor[dst[i]], 1);
        csr[pos] = i;
    }
}

// ---------------- utility kernels ----------------
__global__ void k_zero_alpha() {
    int i = blockIdx.x * 256 + threadIdx.x;
    ((float4*)g_alpha)[i] = make_float4(0.f, 0.f, 0.f, 0.f);
}
__global__ void k_zero_out(float* __restrict__ out) {
    int i = blockIdx.x * 256 + threadIdx.x;
    ((float4*)out)[i] = make_float4(0.f, 0.f, 0.f, 0.f);
    if (i < NGRAPH) g_counts[i] = 0.f;
}
__global__ void k_counts(const int* __restrict__ gids) {
    int v = blockIdx.x * 256 + threadIdx.x;
    if (v < N_NODES_C) atomicAdd(&g_counts[gids[v]], 1.0f);
}
__global__ void k_div(float* __restrict__ out) {
    int i = blockIdx.x * 256 + threadIdx.x;
    int g = i >> 6;
    float c = fmaxf(g_counts[g], 1.0f);
    float4 v = ((float4*)out)[i];
    v.x /= c; v.y /= c; v.z /= c; v.w /= c;
    ((float4*)out)[i] = v;
}
// pre-split W to fp16 hi/lo, transposed to [n][k]
__global__ void k_prep_w(const float* __restrict__ Wh, const float* __restrict__ Wo) {
    int n = blockIdx.x & 255;
    int k = threadIdx.x;
    float v;
    __half* hi;
    __half* lo;
    if (blockIdx.x < 256) { v = Wh[k * 256 + n];         hi = g_WhT_hi; lo = g_WhT_lo; }
    else                  { v = Wo[(AFD + k) * 256 + n]; hi = g_WoT_hi; lo = g_WoT_lo; }
    __half h = __float2half_rn(v);
    hi[n * 256 + k] = h;
    lo[n * 256 + k] = __float2half_rn(v - __half2float(h));
}
__global__ void k_tree_scatter(const float* __restrict__ tree, const int* __restrict__ tgt) {
    int i = blockIdx.x * 256 + threadIdx.x;
    int t = i >> 6, q = i & 63;
    float4 v = ((const float4*)tree)[(size_t)t * 64 + q];
    red4(g_alpha + (size_t)tgt[t] * HID + q * 4, v.x, v.y, v.z, v.w);
}

__device__ __forceinline__ uint2 f4toh4(float4 v) {
    __half2 h01 = __floats2half2_rn(v.x, v.y);
    __half2 h23 = __floats2half2_rn(v.z, v.w);
    return make_uint2(h2u(h01), h2u(h23));
}
__device__ __forceinline__ float4 h4tof4(uint2 u) {
    __half2 a = *reinterpret_cast<__half2*>(&u.x);
    __half2 b = *reinterpret_cast<__half2*>(&u.y);
    float2 fa = __half22float2(a);
    float2 fb = __half22float2(b);
    return make_float4(fa.x, fa.y, fb.x, fb.y);
}

// ---------------- CSR gather: acc[e] = alpha[esrc[e]] + sum src[lg_csr[...]] ----------
// writes single fp16 plane
template<bool FIRST>
__global__ __launch_bounds__(256)
void k_lg_gather(const int* __restrict__ esrc, const float* __restrict__ srcf,
                 const __half* __restrict__ srch) {
    int i = blockIdx.x * 256 + threadIdx.x;
    int e = i >> 6, q = i & 63;
    int a = __ldg(&esrc[e]);
    float4 acc = ((const float4*)g_alpha)[(size_t)a * 64 + q];
    int beg = __ldg(&g_lg_rowptr[e]);
    int end = __ldg(&g_lg_rowptr[e + 1]);
    for (int j = beg; j < end; j++) {
        int s = __ldg(&g_lg_csr[j]);
        float4 v;
        if (FIRST) {
            v = __ldg((const float4*)srcf + (size_t)s * 64 + q);
            v.x = fmaxf(v.x, 0.f); v.y = fmaxf(v.y, 0.f);
            v.z = fmaxf(v.z, 0.f); v.w = fmaxf(v.w, 0.f);
        } else {
            v = h4tof4(__ldg((const uint2*)srch + (size_t)s * 64 + q));
        }
        acc.x += v.x; acc.y += v.y; acc.z += v.z; acc.w += v.w;
    }
    ((uint2*)g_accH)[(size_t)e * 64 + q] = f4toh4(acc);
}

// mplus[v] = alpha[v] + sum msg[nd_csr[...]]  (single fp16 plane)
__global__ __launch_bounds__(256)
void k_node_gather(const __half* __restrict__ msg) {
    int i = blockIdx.x * 256 + threadIdx.x;
    int v = i >> 6, q = i & 63;
    float4 acc = ((const float4*)g_alpha)[(size_t)v * 64 + q];
    int beg = __ldg(&g_nd_rowptr[v]);
    int end = __ldg(&g_nd_rowptr[v + 1]);
    for (int j = beg; j < end; j++) {
        int s = __ldg(&g_nd_csr[j]);
        float4 m = h4tof4(__ldg((const uint2*)msg + (size_t)s * 64 + q));
        acc.x += m.x; acc.y += m.y; acc.z += m.z; acc.w += m.w;
    }
    ((uint2*)g_mpH)[(size_t)v * 64 + q] = f4toh4(acc);
}

// ---------------- msg_input = [node_x[src]; bond_x] @ W_i ----------------
__global__ __launch_bounds__(256)
void k_msg_in(const float* __restrict__ node_x, const float* __restrict__ bond_x,
              const float* __restrict__ W_i, const int* __restrict__ esrc) {
    __shared__ float feat[64][KIN];
    int e0 = blockIdx.x * 64;
    int tid = threadIdx.x;
    float w[KIN];
#pragma unroll
    for (int k = 0; k < KIN; k++) w[k] = W_i[k * HID + tid];
    for (int idx = tid; idx < 64 * KIN; idx += 256) {
        int e = idx / KIN, k = idx % KIN;
        int ge = e0 + e;
        float vv = 0.f;
        if (ge < N_EDGES_C)
            vv = (k < AFD) ? node_x[(size_t)esrc[ge] * AFD + k]
                           : bond_x[(size_t)ge * BFD + (k - AFD)];
        feat[e][k] = vv;
    }
    __syncthreads();
    for (int e = 0; e < 64; e++) {
        int ge = e0 + e;
        if (ge >= N_EDGES_C) break;
        const float4* f4 = (const float4*)feat[e];
        float a0 = 0.f, a1 = 0.f;
#pragma unroll
        for (int k4 = 0; k4 < KIN / 4; k4++) {
            float4 ff = f4[k4];
            a0 = fmaf(ff.x, w[k4 * 4 + 0], a0);
            a1 = fmaf(ff.y, w[k4 * 4 + 1], a1);
            a0 = fmaf(ff.z, w[k4 * 4 + 2], a0);
            a1 = fmaf(ff.w, w[k4 * 4 + 3], a1);
        }
        g_msg_input[(size_t)ge * HID + tid] = a0 + a1;
    }
}

// ---------------- g_hbias = node_x @ W_o[:35] + b_o ----------------
__global__ __launch_bounds__(256)
void k_hbias(const float* __restrict__ node_x, const float* __restrict__ W_o,
             const float* __restrict__ b_o) {
    __shared__ float feat[64][36];
    int v0 = blockIdx.x * 64;
    int tid = threadIdx.x;
    float w[36];
#pragma unroll
    for (int k = 0; k < AFD; k++) w[k] = W_o[k * HID + tid];
    w[35] = 0.f;
    float bb = b_o[tid];
    for (int idx = tid; idx < 64 * 36; idx += 256) {
        int v = idx / 36, k = idx % 36;
        int gv = v0 + v;
        feat[v][k] = (gv < N_NODES_C && k < AFD) ? node_x[(size_t)gv * AFD + k] : 0.f;
    }
    __syncthreads();
    for (int v = 0; v < 64; v++) {
        int gv = v0 + v;
        if (gv >= N_NODES_C) break;
        const float4* f4 = (const float4*)feat[v];
        float a0 = bb, a1 = 0.f;
#pragma unroll
        for (int k4 = 0; k4 < 9; k4++) {
            float4 ff = f4[k4];
            a0 = fmaf(ff.x, w[k4 * 4 + 0], a0);
            a1 = fmaf(ff.y, w[k4 * 4 + 1], a1);
            a0 = fmaf(ff.z, w[k4 * 4 + 2], a0);
            a1 = fmaf(ff.w, w[k4 * 4 + 3], a1);
        }
        g_hbias[(size_t)gv * HID + tid] = a0 + a1;
    }
}

// ---------------- wide-N fp16 GEMM: D = Ah @ (Bh + Bl)^T  (2 mma terms) --------------
// A single fp16 plane via cp.async; B exact hi/lo split (weights).
// B fragments loaded 2 n-tiles at a time via ldmatrix.x4.
// MODE 0: dsth = relu(bias + D) as fp16    MODE 1: out[gids[row]] += relu(bias+D)
// SMEM per buffer: Ah 16K | Bhi 32K | Blo 32K = 80K, double-buffered = 160K.
#define MMW_BUF  81920
#define MMW_SMEM (2 * MMW_BUF)

template<int MODE>
__global__ __launch_bounds__(512, 1)
void k_mmw(const __half* __restrict__ Ahi,
           const float* __restrict__ bias,
           const __half* __restrict__ Bhi, const __half* __restrict__ Blo,
           __half* __restrict__ dsth, const int* __restrict__ gids,
           float* __restrict__ out, int M) {
    extern __shared__ char sm[];
    const int tid  = threadIdx.x;
    const int lane = tid & 31;
    const int wid  = tid >> 5;
    const int wm   = wid >> 2;
    const int wn   = wid & 3;
    const int m0   = blockIdx.x * 128;
    const uint32_t sbase = smem_u32(sm);

    float d[2][8][4];
#pragma unroll
    for (int i = 0; i < 2; i++)
#pragma unroll
        for (int j = 0; j < 8; j++)
#pragma unroll
            for (int q = 0; q < 4; q++) d[i][j][q] = 0.f;

    // A chunk: 128 rows x 64 halves = 1024 x 16B
    auto cpA = [&](int cc, int b) {
        uint32_t base = sbase + b * MMW_BUF;
#pragma unroll
        for (int j = 0; j < 2; j++) {
            int idx = tid + j * 512;            // 0..1023
            int row = idx >> 3, seg = idx & 7;
            uint32_t off = (uint32_t)(row * 128 + seg * 16);
            uint32_t sw = off ^ ((off >> 3) & 0x70);
            cp16(base + sw, Ahi + (size_t)(m0 + row) * 256 + cc * 64 + seg * 8);
        }
    };
    // B chunk: 256 rows x 64 halves per plane = 2048 x 16B; 2 planes = 4096 cp16
    auto cpB = [&](int cc, int b) {
        uint32_t base = sbase + b * MMW_BUF;
#pragma unroll
        for (int j = 0; j < 8; j++) {
            int idx = tid + j * 512;            // 0..4095
            int u = idx & 2047;
            int row = u >> 3, seg = u & 7;
            uint32_t off = (uint32_t)(row * 128 + seg * 16);
            uint32_t sw = off ^ ((off >> 3) & 0x70);
            const __half* src = (idx < 2048) ? Bhi : Blo;
            uint32_t dsm = base + ((idx < 2048) ? 16384u : 49152u) + sw;
            cp16(dsm, src + (size_t)row * 256 + cc * 64 + seg * 8);
        }
    };
    auto compute = [&](int b) {
        uint32_t baseA  = sbase + b * MMW_BUF;
        uint32_t baseBh = baseA + 16384;
        uint32_t baseBl = baseA + 49152;
        const int r = lane & 7, q = lane >> 3;
        const int bro = ((q >> 1) << 3) + r;
        const int bkp = (q & 1) << 4;
#pragma unroll
        for (int s = 0; s < 4; s++) {
            uint32_t ah[2][4];
#pragma unroll
            for (int mt = 0; mt < 2; mt++) {
                uint32_t mrow = (uint32_t)(wm * 32 + mt * 16 + (q & 1) * 8 + r);
                uint32_t off = mrow * 128 + (q >> 1) * 16 + s * 32;
                uint32_t sw = off ^ ((off >> 3) & 0x70);
                ldsm4(ah[mt], baseA + sw);
            }
#pragma unroll
            for (int h = 0; h < 2; h++) {
                uint32_t bh4[2][4], bl4[2][4];
#pragma unroll
                for (int ntp = 0; ntp < 2; ntp++) {
                    uint32_t nrow = (uint32_t)(wn * 64 + h * 32 + ntp * 16 + bro);
                    uint32_t off = nrow * 128 + bkp + s * 32;
                    uint32_t sw = off ^ ((off >> 3) & 0x70);
                    ldsm4(bh4[ntp], baseBh + sw);
                    ldsm4(bl4[ntp], baseBl + sw);
                }
#pragma unroll
                for (int mt = 0; mt < 2; mt++)
#pragma unroll
                    for (int nt = 0; nt < 4; nt++) {
                        float* acc = d[mt][h * 4 + nt];
                        const uint32_t* bhp = &bh4[nt >> 1][(nt & 1) * 2];
                        const uint32_t* blp = &bl4[nt >> 1][(nt & 1) * 2];
                        mma_f16(acc, ah[mt], bhp);
                        mma_f16(acc, ah[mt], blp);
                    }
            }
        }
    };

    cpA(0, 0); cpB(0, 0); CP_COMMIT();
    CP_WAIT0();
    __syncthreads();

#pragma unroll
    for (int c = 0; c < 4; c++) {
        if (c < 3) { cpA(c + 1, (c + 1) & 1); cpB(c + 1, (c + 1) & 1); CP_COMMIT(); }
        compute(c & 1);
        if (c < 3) CP_WAIT0();
        __syncthreads();
    }

#pragma unroll
    for (int mt = 0; mt < 2; mt++) {
#pragma unroll
        for (int n = 0; n < 8; n++) {
            int row = m0 + wm * 32 + mt * 16 + (lane >> 2);
            int col = wn * 64 + n * 8 + (lane & 3) * 2;
#pragma unroll
            for (int h2 = 0; h2 < 2; h2++) {
                int gr = row + h2 * 8;
                if (gr >= M) continue;
                size_t gb = (size_t)gr * 256 + col;
                float2 bv = *(const float2*)(bias + gb);
                float ox = fmaxf(bv.x + d[mt][n][h2 * 2 + 0], 0.f);
                float oy = fmaxf(bv.y + d[mt][n][h2 * 2 + 1], 0.f);
                if (MODE == 0) {
                    __half2 hv = __floats2half2_rn(ox, oy);
                    *(uint32_t*)(dsth + gb) = h2u(hv);
                } else {
                    int g = gids[gr];
                    red2(out + (size_t)g * 256 + col, ox, oy);
                }
            }
        }
    }
}

// ---------------- launch ----------------
extern "C" void kernel_launch(void* const* d_in, const int* in_sizes, int n_in,
                              void* d_out, int out_size) {
    (void)in_sizes; (void)n_in; (void)out_size;
    const float* node_x = (const float*)d_in[0];
    const float* bond_x = (const float*)d_in[1];
    const float* tree   = (const float*)d_in[2];
    const float* W_i    = (const float*)d_in[3];
    const float* W_h    = (const float*)d_in[4];
    const float* W_o    = (const float*)d_in[5];
    const float* b_o    = (const float*)d_in[6];
    const int* esrc = (const int*)d_in[7];
    const int* edst = (const int*)d_in[8];
    const int* lsrc = (const int*)d_in[9];
    const int* ldst = (const int*)d_in[10];
    const int* tgt  = (const int*)d_in[11];
    const int* gids = (const int*)d_in[12];
    float* out = (float*)d_out;

    cudaFuncSetAttribute(k_mmw<0>, cudaFuncAttributeMaxDynamicSharedMemorySize, MMW_SMEM);
    cudaFuncSetAttribute(k_mmw<1>, cudaFuncAttributeMaxDynamicSharedMemorySize, MMW_SMEM);

    float *hb_p, *mi_p;
    cudaGetSymbolAddress((void**)&hb_p, g_hbias);
    cudaGetSymbolAddress((void**)&mi_p, g_msg_input);
    __half *msgH_p, *msgHB_p, *accH_p, *mpH_p;
    cudaGetSymbolAddress((void**)&msgH_p,  g_msgH);
    cudaGetSymbolAddress((void**)&msgHB_p, g_msgHB);
    cudaGetSymbolAddress((void**)&accH_p,  g_accH);
    cudaGetSymbolAddress((void**)&mpH_p,   g_mpH);
    __half *WhH, *WhL, *WoH, *WoL;
    cudaGetSymbolAddress((void**)&WhH, g_WhT_hi);
    cudaGetSymbolAddress((void**)&WhL, g_WhT_lo);
    cudaGetSymbolAddress((void**)&WoH, g_WoT_hi);
    cudaGetSymbolAddress((void**)&WoL, g_WoT_lo);
    int *lg_rp, *lg_cur, *lg_csr_p, *nd_rp, *nd_cur, *nd_csr_p, *part_p, *part2_p;
    cudaGetSymbolAddress((void**)&lg_rp,    g_lg_rowptr);
    cudaGetSymbolAddress((void**)&lg_cur,   g_lg_cursor);
    cudaGetSymbolAddress((void**)&lg_csr_p, g_lg_csr);
    cudaGetSymbolAddress((void**)&nd_rp,    g_nd_rowptr);
    cudaGetSymbolAddress((void**)&nd_cur,   g_nd_cursor);
    cudaGetSymbolAddress((void**)&nd_csr_p, g_nd_csr);
    cudaGetSymbolAddress((void**)&part_p,   g_part);
    cudaGetSymbolAddress((void**)&part2_p,  g_part2);

    // ---- CSR build: line graph ----
    k_zeroi<<<1172, 256>>>(lg_cur, N_EDGES_C);
    k_hist<<<2344, 256>>>(ldst, lg_cur, N_LG_C);
    k_scan1<<<293, 256>>>(lg_cur, lg_rp, N_EDGES_C, part_p);
    k_scan1<<<1, 256>>>(part_p, part2_p, 293, nullptr);
    k_scan3<<<1172, 256>>>(lg_rp, lg_cur, part2_p, N_EDGES_C, N_LG_C);
    k_fill<<<2344, 256>>>(lsrc, ldst, lg_cur, lg_csr_p, N_LG_C);
    // ---- CSR build: node graph ----
    k_zeroi<<<586, 256>>>(nd_cur, N_NODES_C);
    k_hist<<<1172, 256>>>(edst, nd_cur, N_EDGES_C);
    k_scan1<<<147, 256>>>(nd_cur, nd_rp, N_NODES_C, part_p);
    k_scan1<<<1, 256>>>(part_p, part2_p, 147, nullptr);
    k_scan3<<<586, 256>>>(nd_rp, nd_cur, part2_p, N_NODES_C, N_EDGES_C);
    k_fill_id<<<1172, 256>>>(edst, nd_cur, nd_csr_p, N_EDGES_C);

    k_prep_w<<<512, 256>>>(W_h, W_o);
    k_zero_alpha<<<37500, 256>>>();
    k_zero_out<<<512, 256>>>(out);
    k_tree_scatter<<<15000, 256>>>(tree, tgt);
    k_msg_in<<<(N_EDGES_C + 63) / 64, 256>>>(node_x, bond_x, W_i, esrc);
    k_hbias<<<(N_NODES_C + 63) / 64, 256>>>(node_x, W_o, b_o);

    // BP iterations: msg ping-pong (mi fp32 -> msgH -> msgHB -> msgH)
    k_lg_gather<true><<<75000, 256>>>(esrc, mi_p, nullptr);
    k_mmw<0><<<2344, 512, MMW_SMEM>>>(accH_p, mi_p, WhH, WhL,
                                      msgH_p, nullptr, nullptr, N_EDGES_C);
    k_lg_gather<false><<<75000, 256>>>(esrc, nullptr, msgH_p);
    k_mmw<0><<<2344, 512, MMW_SMEM>>>(accH_p, mi_p, WhH, WhL,
                                      msgHB_p, nullptr, nullptr, N_EDGES_C);
    k_lg_gather<false><<<75000, 256>>>(esrc, nullptr, msgHB_p);
    k_mmw<0><<<2344, 512, MMW_SMEM>>>(accH_p, mi_p, WhH, WhL,
                                      msgH_p, nullptr, nullptr, N_EDGES_C);

    k_node_gather<<<37500, 256>>>(msgH_p);
    k_counts<<<586, 256>>>(gids);
    k_mmw<1><<<1172, 512, MMW_SMEM>>>(mpH_p, hb_p, WoH, WoL,
                                      nullptr, gids, out, N_NODES_C);
    k_div<<<512, 256>>>(out);
}

// round 13
// speedup vs baseline: 1.5987x; 1.2244x over previous
#include <cuda_runtime.h>
#include <cuda_fp16.h>
#include <cstdint>

#define N_NODES_C 150000
#define N_EDGES_C 300000
#define N_LG_C    600000
#define HID       256
#define NGRAPH    2048
#define AFD       35
#define BFD       5
#define KIN       40

// ---------------- scratch (static device globals; no allocation) ----------------
__device__ __half g_msgIn[(size_t)N_EDGES_C * HID];       // fp16 msg_input (GEMM bias)
__device__ __half g_msgH [(size_t)N_EDGES_C * HID];
__device__ __half g_msgHB[(size_t)N_EDGES_C * HID];
// accum / mplus single fp16 plane, padded +128 rows for unconditional cp.async
__device__ __half g_accH[((size_t)N_EDGES_C + 128) * HID];
__device__ __half g_mpH [((size_t)N_NODES_C + 128) * HID];
__device__ float  g_alpha[(size_t)N_NODES_C * HID];
__device__ __half g_hbias[(size_t)N_NODES_C * HID];
__device__ __half g_WhT[HID * HID];
__device__ __half g_WoT[HID * HID];
__device__ float  g_counts[NGRAPH];

// CSR structures
__device__ int g_lg_rowptr[N_EDGES_C + 1];
__device__ int g_lg_cursor[N_EDGES_C];
__device__ int g_lg_csr[N_LG_C];
__device__ int g_nd_rowptr[N_NODES_C + 1];
__device__ int g_nd_cursor[N_NODES_C];
__device__ int g_nd_csr[N_EDGES_C];
__device__ int g_part [1024];
__device__ int g_part2[1024];

// ---------------- PTX helpers (portable: sm_80/sm_90 level only) ----------------
__device__ __forceinline__ uint32_t smem_u32(const void* p) {
    uint32_t a;
    asm("{ .reg .u64 t; cvta.to.shared.u64 t, %1; cvt.u32.u64 %0, t; }" : "=r"(a) : "l"(p));
    return a;
}
__device__ __forceinline__ void red4(float* p, float a, float b, float c, float d) {
    asm volatile("red.global.add.v4.f32 [%0], {%1, %2, %3, %4};"
                 :: "l"(p), "f"(a), "f"(b), "f"(c), "f"(d) : "memory");
}
__device__ __forceinline__ void red2(float* p, float a, float b) {
    asm volatile("red.global.add.v2.f32 [%0], {%1, %2};"
                 :: "l"(p), "f"(a), "f"(b) : "memory");
}
__device__ __forceinline__ void ldsm4(uint32_t* r, uint32_t addr) {
    asm volatile("ldmatrix.sync.aligned.m8n8.x4.shared.b16 {%0,%1,%2,%3}, [%4];"
                 : "=r"(r[0]), "=r"(r[1]), "=r"(r[2]), "=r"(r[3]) : "r"(addr));
}
__device__ __forceinline__ void mma_f16(float* d, const uint32_t* a, const uint32_t* b) {
    asm volatile(
        "mma.sync.aligned.m16n8k16.row.col.f32.f16.f16.f32 "
        "{%0,%1,%2,%3}, {%4,%5,%6,%7}, {%8,%9}, {%0,%1,%2,%3};"
        : "+f"(d[0]), "+f"(d[1]), "+f"(d[2]), "+f"(d[3])
        : "r"(a[0]), "r"(a[1]), "r"(a[2]), "r"(a[3]), "r"(b[0]), "r"(b[1]));
}
__device__ __forceinline__ uint32_t h2u(__half2 h) { return *reinterpret_cast<uint32_t*>(&h); }
__device__ __forceinline__ void cp16(uint32_t dst, const void* src) {
    asm volatile("cp.async.cg.shared.global [%0], [%1], 16;" :: "r"(dst), "l"(src));
}
#define CP_COMMIT() asm volatile("cp.async.commit_group;" ::: "memory")
#define CP_WAIT0()  asm volatile("cp.async.wait_group 0;" ::: "memory")

// ---------------- CSR build kernels ----------------
__global__ void k_zeroi(int* __restrict__ p, int n) {
    int i = blockIdx.x * 256 + threadIdx.x;
    if (i < n) p[i] = 0;
}
__global__ void k_hist(const int* __restrict__ dst, int* __restrict__ cnt, int n) {
    int i = blockIdx.x * 256 + threadIdx.x;
    if (i < n) atomicAdd(&cnt[dst[i]], 1);
}
__global__ void k_scan1(const int* __restrict__ cnt, int* __restrict__ ex, int n,
                        int* __restrict__ part) {
    __shared__ int sh[256];
    int base = blockIdx.x * 1024;
    int t = threadIdx.x;
    int v[4], s = 0;
#pragma unroll
    for (int j = 0; j < 4; j++) {
        int i = base + t * 4 + j;
        v[j] = (i < n) ? cnt[i] : 0;
        s += v[j];
    }
    sh[t] = s;
    __syncthreads();
    for (int off = 1; off < 256; off <<= 1) {
        int x = (t >= off) ? sh[t - off] : 0;
        __syncthreads();
        sh[t] += x;
        __syncthreads();
    }
    int run = (t > 0) ? sh[t - 1] : 0;
    if (part && t == 255) part[blockIdx.x] = sh[255];
#pragma unroll
    for (int j = 0; j < 4; j++) {
        int i = base + t * 4 + j;
        if (i < n) ex[i] = run;
        run += v[j];
    }
}
__global__ void k_scan3(int* __restrict__ ex, int* __restrict__ cursor,
                        const int* __restrict__ part2, int n, int ntot) {
    int i = blockIdx.x * 256 + threadIdx.x;
    if (i < n) {
        int v = ex[i] + part2[i >> 10];
        ex[i] = v;
        cursor[i] = v;
    }
    if (i == 0) ex[n] = ntot;
}
__global__ void k_fill(const int* __restrict__ src, const int* __restrict__ dst,
                       int* __restrict__ cursor, int* __restrict__ csr, int n) {
    int i = blockIdx.x * 256 + threadIdx.x;
    if (i < n) {
        int pos = atomicAdd(&cursor[dst[i]], 1);
        csr[pos] = src[i];
    }
}
__global__ void k_fill_id(const int* __restrict__ dst, int* __restrict__ cursor,
                          int* __restrict__ csr, int n) {
    int i = blockIdx.x * 256 + threadIdx.x;
    if (i < n) {
        int pos = atomicAdd(&cursor[dst[i]], 1);
        csr[pos] = i;
    }
}

// ---------------- utility kernels ----------------
__global__ void k_zero_alpha() {
    int i = blockIdx.x * 256 + threadIdx.x;
    ((float4*)g_alpha)[i] = make_float4(0.f, 0.f, 0.f, 0.f);
}
__global__ void k_zero_out(float* __restrict__ out) {
    int i = blockIdx.x * 256 + threadIdx.x;
    ((float4*)out)[i] = make_float4(0.f, 0.f, 0.f, 0.f);
    if (i < NGRAPH) g_counts[i] = 0.f;
}
__global__ void k_counts(const int* __restrict__ gids) {
    int v = blockIdx.x * 256 + threadIdx.x;
    if (v < N_NODES_C) atomicAdd(&g_counts[gids[v]], 1.0f);
}
__global__ void k_div(float* __restrict__ out) {
    int i = blockIdx.x * 256 + threadIdx.x;
    int g = i >> 6;
    float c = fmaxf(g_counts[g], 1.0f);
    float4 v = ((float4*)out)[i];
    v.x /= c; v.y /= c; v.z /= c; v.w /= c;
    ((float4*)out)[i] = v;
}
// W -> fp16, transposed to [n][k]
__global__ void k_prep_w(const float* __restrict__ Wh, const float* __restrict__ Wo) {
    int n = blockIdx.x & 255;
    int k = threadIdx.x;
    if (blockIdx.x < 256) g_WhT[n * 256 + k] = __float2half_rn(Wh[k * 256 + n]);
    else                  g_WoT[n * 256 + k] = __float2half_rn(Wo[(AFD + k) * 256 + n]);
}
__global__ void k_tree_scatter(const float* __restrict__ tree, const int* __restrict__ tgt) {
    int i = blockIdx.x * 256 + threadIdx.x;
    int t = i >> 6, q = i & 63;
    float4 v = ((const float4*)tree)[(size_t)t * 64 + q];
    red4(g_alpha + (size_t)tgt[t] * HID + q * 4, v.x, v.y, v.z, v.w);
}

__device__ __forceinline__ uint2 f4toh4(float4 v) {
    __half2 h01 = __floats2half2_rn(v.x, v.y);
    __half2 h23 = __floats2half2_rn(v.z, v.w);
    return make_uint2(h2u(h01), h2u(h23));
}
__device__ __forceinline__ float4 h4tof4(uint2 u) {
    __half2 a = *reinterpret_cast<__half2*>(&u.x);
    __half2 b = *reinterpret_cast<__half2*>(&u.y);
    float2 fa = __half22float2(a);
    float2 fb = __half22float2(b);
    return make_float4(fa.x, fa.y, fb.x, fb.y);
}

// ---------------- CSR gather: acc[e] = alpha[esrc[e]] + sum src[lg_csr[...]] ----------
// src is fp16; FIRST applies relu to src values. Writes single fp16 plane.
template<bool FIRST>
__global__ __launch_bounds__(256)
void k_lg_gather(const int* __restrict__ esrc, const __half* __restrict__ srch) {
    int i = blockIdx.x * 256 + threadIdx.x;
    int e = i >> 6, q = i & 63;
    int a = __ldg(&esrc[e]);
    float4 acc = ((const float4*)g_alpha)[(size_t)a * 64 + q];
    int beg = __ldg(&g_lg_rowptr[e]);
    int end = __ldg(&g_lg_rowptr[e + 1]);
    for (int j = beg; j < end; j++) {
        int s = __ldg(&g_lg_csr[j]);
        float4 v = h4tof4(__ldg((const uint2*)srch + (size_t)s * 64 + q));
        if (FIRST) {
            v.x = fmaxf(v.x, 0.f); v.y = fmaxf(v.y, 0.f);
            v.z = fmaxf(v.z, 0.f); v.w = fmaxf(v.w, 0.f);
        }
        acc.x += v.x; acc.y += v.y; acc.z += v.z; acc.w += v.w;
    }
    ((uint2*)g_accH)[(size_t)e * 64 + q] = f4toh4(acc);
}

// mplus[v] = alpha[v] + sum msg[nd_csr[...]]  (single fp16 plane)
__global__ __launch_bounds__(256)
void k_node_gather(const __half* __restrict__ msg) {
    int i = blockIdx.x * 256 + threadIdx.x;
    int v = i >> 6, q = i & 63;
    float4 acc = ((const float4*)g_alpha)[(size_t)v * 64 + q];
    int beg = __ldg(&g_nd_rowptr[v]);
    int end = __ldg(&g_nd_rowptr[v + 1]);
    for (int j = beg; j < end; j++) {
        int s = __ldg(&g_nd_csr[j]);
        float4 m = h4tof4(__ldg((const uint2*)msg + (size_t)s * 64 + q));
        acc.x += m.x; acc.y += m.y; acc.z += m.z; acc.w += m.w;
    }
    ((uint2*)g_mpH)[(size_t)v * 64 + q] = f4toh4(acc);
}

// ---------------- msg_input = [node_x[src]; bond_x] @ W_i  (fp16 out) ----------------
__global__ __launch_bounds__(256)
void k_msg_in(const float* __restrict__ node_x, const float* __restrict__ bond_x,
              const float* __restrict__ W_i, const int* __restrict__ esrc) {
    __shared__ float feat[64][KIN];
    int e0 = blockIdx.x * 64;
    int tid = threadIdx.x;
    float w[KIN];
#pragma unroll
    for (int k = 0; k < KIN; k++) w[k] = W_i[k * HID + tid];
    for (int idx = tid; idx < 64 * KIN; idx += 256) {
        int e = idx / KIN, k = idx % KIN;
        int ge = e0 + e;
        float vv = 0.f;
        if (ge < N_EDGES_C)
            vv = (k < AFD) ? node_x[(size_t)esrc[ge] * AFD + k]
                           : bond_x[(size_t)ge * BFD + (k - AFD)];
        feat[e][k] = vv;
    }
    __syncthreads();
    for (int e = 0; e < 64; e++) {
        int ge = e0 + e;
        if (ge >= N_EDGES_C) break;
        const float4* f4 = (const float4*)feat[e];
        float a0 = 0.f, a1 = 0.f;
#pragma unroll
        for (int k4 = 0; k4 < KIN / 4; k4++) {
            float4 ff = f4[k4];
            a0 = fmaf(ff.x, w[k4 * 4 + 0], a0);
            a1 = fmaf(ff.y, w[k4 * 4 + 1], a1);
            a0 = fmaf(ff.z, w[k4 * 4 + 2], a0);
            a1 = fmaf(ff.w, w[k4 * 4 + 3], a1);
        }
        g_msgIn[(size_t)ge * HID + tid] = __float2half_rn(a0 + a1);
    }
}

// ---------------- g_hbias = node_x @ W_o[:35] + b_o  (fp16 out) ----------------
__global__ __launch_bounds__(256)
void k_hbias(const float* __restrict__ node_x, const float* __restrict__ W_o,
             const float* __restrict__ b_o) {
    __shared__ float feat[64][36];
    int v0 = blockIdx.x * 64;
    int tid = threadIdx.x;
    float w[36];
#pragma unroll
    for (int k = 0; k < AFD; k++) w[k] = W_o[k * HID + tid];
    w[35] = 0.f;
    float bb = b_o[tid];
    for (int idx = tid; idx < 64 * 36; idx += 256) {
        int v = idx / 36, k = idx % 36;
        int gv = v0 + v;
        feat[v][k] = (gv < N_NODES_C && k < AFD) ? node_x[(size_t)gv * AFD + k] : 0.f;
    }
    __syncthreads();
    for (int v = 0; v < 64; v++) {
        int gv = v0 + v;
        if (gv >= N_NODES_C) break;
        const float4* f4 = (const float4*)feat[v];
        float a0 = bb, a1 = 0.f;
#pragma unroll
        for (int k4 = 0; k4 < 9; k4++) {
            float4 ff = f4[k4];
            a0 = fmaf(ff.x, w[k4 * 4 + 0], a0);
            a1 = fmaf(ff.y, w[k4 * 4 + 1], a1);
            a0 = fmaf(ff.z, w[k4 * 4 + 2], a0);
            a1 = fmaf(ff.w, w[k4 * 4 + 3], a1);
        }
        g_hbias[(size_t)gv * HID + tid] = __float2half_rn(a0 + a1);
    }
}

// ---------------- wide-N fp16 GEMM: D = Ah @ Bh^T  (1 mma term) ----------------------
// A and B single fp16 planes via cp.async; bias fp16.
// B fragments loaded 2 n-tiles at a time via ldmatrix.x4.
// MODE 0: dsth = relu(bias + D) as fp16    MODE 1: out[gids[row]] += relu(bias+D)
// SMEM per buffer: Ah 16K | Bh 32K = 48K, double-buffered = 96K.
#define MMW_BUF  49152
#define MMW_SMEM (2 * MMW_BUF)

template<int MODE>
__global__ __launch_bounds__(512, 1)
void k_mmw(const __half* __restrict__ Ahi,
           const __half* __restrict__ bias,
           const __half* __restrict__ Bhi,
           __half* __restrict__ dsth, const int* __restrict__ gids,
           float* __restrict__ out, int M) {
    extern __shared__ char sm[];
    const int tid  = threadIdx.x;
    const int lane = tid & 31;
    const int wid  = tid >> 5;
    const int wm   = wid >> 2;
    const int wn   = wid & 3;
    const int m0   = blockIdx.x * 128;
    const uint32_t sbase = smem_u32(sm);

    float d[2][8][4];
#pragma unroll
    for (int i = 0; i < 2; i++)
#pragma unroll
        for (int j = 0; j < 8; j++)
#pragma unroll
            for (int q = 0; q < 4; q++) d[i][j][q] = 0.f;

    // A chunk: 128 rows x 64 halves = 1024 x 16B
    auto cpA = [&](int cc, int b) {
        uint32_t base = sbase + b * MMW_BUF;
#pragma unroll
        for (int j = 0; j < 2; j++) {
            int idx = tid + j * 512;            // 0..1023
            int row = idx >> 3, seg = idx & 7;
            uint32_t off = (uint32_t)(row * 128 + seg * 16);
            uint32_t sw = off ^ ((off >> 3) & 0x70);
            cp16(base + sw, Ahi + (size_t)(m0 + row) * 256 + cc * 64 + seg * 8);
        }
    };
    // B chunk: 256 rows x 64 halves = 2048 x 16B
    auto cpB = [&](int cc, int b) {
        uint32_t base = sbase + b * MMW_BUF;
#pragma unroll
        for (int j = 0; j < 4; j++) {
            int idx = tid + j * 512;            // 0..2047
            int row = idx >> 3, seg = idx & 7;
            uint32_t off = (uint32_t)(row * 128 + seg * 16);
            uint32_t sw = off ^ ((off >> 3) & 0x70);
            cp16(base + 16384u + sw, Bhi + (size_t)row * 256 + cc * 64 + seg * 8);
        }
    };
    auto compute = [&](int b) {
        uint32_t baseA  = sbase + b * MMW_BUF;
        uint32_t baseBh = baseA + 16384;
        const int r = lane & 7, q = lane >> 3;
        const int bro = ((q >> 1) << 3) + r;
        const int bkp = (q & 1) << 4;
#pragma unroll
        for (int s = 0; s < 4; s++) {
            uint32_t ah[2][4];
#pragma unroll
            for (int mt = 0; mt < 2; mt++) {
                uint32_t mrow = (uint32_t)(wm * 32 + mt * 16 + (q & 1) * 8 + r);
                uint32_t off = mrow * 128 + (q >> 1) * 16 + s * 32;
                uint32_t sw = off ^ ((off >> 3) & 0x70);
                ldsm4(ah[mt], baseA + sw);
            }
#pragma unroll
            for (int h = 0; h < 2; h++) {
                uint32_t bh4[2][4];
#pragma unroll
                for (int ntp = 0; ntp < 2; ntp++) {
                    uint32_t nrow = (uint32_t)(wn * 64 + h * 32 + ntp * 16 + bro);
                    uint32_t off = nrow * 128 + bkp + s * 32;
                    uint32_t sw = off ^ ((off >> 3) & 0x70);
                    ldsm4(bh4[ntp], baseBh + sw);
                }
#pragma unroll
                for (int mt = 0; mt < 2; mt++)
#pragma unroll
                    for (int nt = 0; nt < 4; nt++)
                        mma_f16(d[mt][h * 4 + nt], ah[mt], &bh4[nt >> 1][(nt & 1) * 2]);
            }
        }
    };

    cpA(0, 0); cpB(0, 0); CP_COMMIT();
    CP_WAIT0();
    __syncthreads();

#pragma unroll
    for (int c = 0; c < 4; c++) {
        if (c < 3) { cpA(c + 1, (c + 1) & 1); cpB(c + 1, (c + 1) & 1); CP_COMMIT(); }
        compute(c & 1);
        if (c < 3) CP_WAIT0();
        __syncthreads();
    }

#pragma unroll
    for (int mt = 0; mt < 2; mt++) {
#pragma unroll
        for (int n = 0; n < 8; n++) {
            int row = m0 + wm * 32 + mt * 16 + (lane >> 2);
            int col = wn * 64 + n * 8 + (lane & 3) * 2;
#pragma unroll
            for (int h2 = 0; h2 < 2; h2++) {
                int gr = row + h2 * 8;
                if (gr >= M) continue;
                size_t gb = (size_t)gr * 256 + col;
                uint32_t bu = *(const uint32_t*)(bias + gb);
                __half2 bh = *reinterpret_cast<__half2*>(&bu);
                float2 bv = __half22float2(bh);
                float ox = fmaxf(bv.x + d[mt][n][h2 * 2 + 0], 0.f);
                float oy = fmaxf(bv.y + d[mt][n][h2 * 2 + 1], 0.f);
                if (MODE == 0) {
                    __half2 hv = __floats2half2_rn(ox, oy);
                    *(uint32_t*)(dsth + gb) = h2u(hv);
                } else {
                    int g = gids[gr];
                    red2(out + (size_t)g * 256 + col, ox, oy);
                }
            }
        }
    }
}

// ---------------- launch ----------------
extern "C" void kernel_launch(void* const* d_in, const int* in_sizes, int n_in,
                              void* d_out, int out_size) {
    (void)in_sizes; (void)n_in; (void)out_size;
    const float* node_x = (const float*)d_in[0];
    const float* bond_x = (const float*)d_in[1];
    const float* tree   = (const float*)d_in[2];
    const float* W_i    = (const float*)d_in[3];
    const float* W_h    = (const float*)d_in[4];
    const float* W_o    = (const float*)d_in[5];
    const float* b_o    = (const float*)d_in[6];
    const int* esrc = (const int*)d_in[7];
    const int* edst = (const int*)d_in[8];
    const int* lsrc = (const int*)d_in[9];
    const int* ldst = (const int*)d_in[10];
    const int* tgt  = (const int*)d_in[11];
    const int* gids = (const int*)d_in[12];
    float* out = (float*)d_out;

    cudaFuncSetAttribute(k_mmw<0>, cudaFuncAttributeMaxDynamicSharedMemorySize, MMW_SMEM);
    cudaFuncSetAttribute(k_mmw<1>, cudaFuncAttributeMaxDynamicSharedMemorySize, MMW_SMEM);

    __half *msgIn_p, *msgH_p, *msgHB_p, *accH_p, *mpH_p, *hb_p, *WhT_p, *WoT_p;
    cudaGetSymbolAddress((void**)&msgIn_p, g_msgIn);
    cudaGetSymbolAddress((void**)&msgH_p,  g_msgH);
    cudaGetSymbolAddress((void**)&msgHB_p, g_msgHB);
    cudaGetSymbolAddress((void**)&accH_p,  g_accH);
    cudaGetSymbolAddress((void**)&mpH_p,   g_mpH);
    cudaGetSymbolAddress((void**)&hb_p,    g_hbias);
    cudaGetSymbolAddress((void**)&WhT_p,   g_WhT);
    cudaGetSymbolAddress((void**)&WoT_p,   g_WoT);
    int *lg_rp, *lg_cur, *lg_csr_p, *nd_rp, *nd_cur, *nd_csr_p, *part_p, *part2_p;
    cudaGetSymbolAddress((void**)&lg_rp,    g_lg_rowptr);
    cudaGetSymbolAddress((void**)&lg_cur,   g_lg_cursor);
    cudaGetSymbolAddress((void**)&lg_csr_p, g_lg_csr);
    cudaGetSymbolAddress((void**)&nd_rp,    g_nd_rowptr);
    cudaGetSymbolAddress((void**)&nd_cur,   g_nd_cursor);
    cudaGetSymbolAddress((void**)&nd_csr_p, g_nd_csr);
    cudaGetSymbolAddress((void**)&part_p,   g_part);
    cudaGetSymbolAddress((void**)&part2_p,  g_part2);

    // ---- CSR build: line graph ----
    k_zeroi<<<1172, 256>>>(lg_cur, N_EDGES_C);
    k_hist<<<2344, 256>>>(ldst, lg_cur, N_LG_C);
    k_scan1<<<293, 256>>>(lg_cur, lg_rp, N_EDGES_C, part_p);
    k_scan1<<<1, 256>>>(part_p, part2_p, 293, nullptr);
    k_scan3<<<1172, 256>>>(lg_rp, lg_cur, part2_p, N_EDGES_C, N_LG_C);
    k_fill<<<2344, 256>>>(lsrc, ldst, lg_cur, lg_csr_p, N_LG_C);
    // ---- CSR build: node graph ----
    k_zeroi<<<586, 256>>>(nd_cur, N_NODES_C);
    k_hist<<<1172, 256>>>(edst, nd_cur, N_EDGES_C);
    k_scan1<<<147, 256>>>(nd_cur, nd_rp, N_NODES_C, part_p);
    k_scan1<<<1, 256>>>(part_p, part2_p, 147, nullptr);
    k_scan3<<<586, 256>>>(nd_rp, nd_cur, part2_p, N_NODES_C, N_EDGES_C);
    k_fill_id<<<1172, 256>>>(edst, nd_cur, nd_csr_p, N_EDGES_C);

    k_prep_w<<<512, 256>>>(W_h, W_o);
    k_zero_alpha<<<37500, 256>>>();
    k_zero_out<<<512, 256>>>(out);
    k_tree_scatter<<<15000, 256>>>(tree, tgt);
    k_msg_in<<<(N_EDGES_C + 63) / 64, 256>>>(node_x, bond_x, W_i, esrc);
    k_hbias<<<(N_NODES_C + 63) / 64, 256>>>(node_x, W_o, b_o);

    // BP iterations: msg ping-pong (msgIn -> msgH -> msgHB -> msgH)
    k_lg_gather<true><<<75000, 256>>>(esrc, msgIn_p);
    k_mmw<0><<<2344, 512, MMW_SMEM>>>(accH_p, msgIn_p, WhT_p,
                                      msgH_p, nullptr, nullptr, N_EDGES_C);
    k_lg_gather<false><<<75000, 256>>>(esrc, msgH_p);
    k_mmw<0><<<2344, 512, MMW_SMEM>>>(accH_p, msgIn_p, WhT_p,
                                      msgHB_p, nullptr, nullptr, N_EDGES_C);
    k_lg_gather<false><<<75000, 256>>>(esrc, msgHB_p);
    k_mmw<0><<<2344, 512, MMW_SMEM>>>(accH_p, msgIn_p, WhT_p,
                                      msgH_p, nullptr, nullptr, N_EDGES_C);

    k_node_gather<<<37500, 256>>>(msgH_p);
    k_counts<<<586, 256>>>(gids);
    k_mmw<1><<<1172, 512, MMW_SMEM>>>(mpH_p, hb_p, WoT_p,
                                      nullptr, gids, out, N_NODES_C);
    k_div<<<512, 256>>>(out);
}

// round 14
// speedup vs baseline: 1.6408x; 1.0263x over previous
#include <cuda_runtime.h>
#include <cuda_fp16.h>
#include <cstdint>

#define N_NODES_C 150000
#define N_EDGES_C 300000
#define N_LG_C    600000
#define HID       256
#define NGRAPH    2048
#define AFD       35
#define BFD       5
#define KIN       40

#define E_SPLIT   150016
#define V_SPLIT   75008

// ---------------- scratch (static device globals; no allocation) ----------------
__device__ __half g_msgIn[(size_t)N_EDGES_C * HID];
__device__ __half g_msgH [(size_t)N_EDGES_C * HID];
__device__ __half g_msgHB[(size_t)N_EDGES_C * HID];
__device__ __half g_accH[((size_t)N_EDGES_C + 128) * HID];
__device__ __half g_mpH [((size_t)N_NODES_C + 128) * HID];
__device__ float  g_alpha[(size_t)N_NODES_C * HID];
__device__ __half g_hbias[(size_t)N_NODES_C * HID];
__device__ __half g_WhT[HID * HID];
__device__ __half g_WoT[HID * HID];
__device__ float  g_counts[NGRAPH];

// CSR structures
__device__ int g_lg_rowptr[N_EDGES_C + 1];
__device__ int g_lg_cursor[N_EDGES_C];
__device__ int g_lg_csr[N_LG_C];
__device__ int g_nd_rowptr[N_NODES_C + 1];
__device__ int g_nd_cursor[N_NODES_C];
__device__ int g_nd_csr[N_EDGES_C];
__device__ int g_part [1024];
__device__ int g_part2[1024];

// ---------------- PTX helpers (portable: sm_80/sm_90 level only) ----------------
__device__ __forceinline__ uint32_t smem_u32(const void* p) {
    uint32_t a;
    asm("{ .reg .u64 t; cvta.to.shared.u64 t, %1; cvt.u32.u64 %0, t; }" : "=r"(a) : "l"(p));
    return a;
}
__device__ __forceinline__ void red4(float* p, float a, float b, float c, float d) {
    asm volatile("red.global.add.v4.f32 [%0], {%1, %2, %3, %4};"
                 :: "l"(p), "f"(a), "f"(b), "f"(c), "f"(d) : "memory");
}
__device__ __forceinline__ void red2(float* p, float a, float b) {
    asm volatile("red.global.add.v2.f32 [%0], {%1, %2};"
                 :: "l"(p), "f"(a), "f"(b) : "memory");
}
__device__ __forceinline__ void ldsm4(uint32_t* r, uint32_t addr) {
    asm volatile("ldmatrix.sync.aligned.m8n8.x4.shared.b16 {%0,%1,%2,%3}, [%4];"
                 : "=r"(r[0]), "=r"(r[1]), "=r"(r[2]), "=r"(r[3]) : "r"(addr));
}
__device__ __forceinline__ void mma_f16(float* d, const uint32_t* a, const uint32_t* b) {
    asm volatile(
        "mma.sync.aligned.m16n8k16.row.col.f32.f16.f16.f32 "
        "{%0,%1,%2,%3}, {%4,%5,%6,%7}, {%8,%9}, {%0,%1,%2,%3};"
        : "+f"(d[0]), "+f"(d[1]), "+f"(d[2]), "+f"(d[3])
        : "r"(a[0]), "r"(a[1]), "r"(a[2]), "r"(a[3]), "r"(b[0]), "r"(b[1]));
}
__device__ __forceinline__ uint32_t h2u(__half2 h) { return *reinterpret_cast<uint32_t*>(&h); }
__device__ __forceinline__ void cp16(uint32_t dst, const void* src) {
    asm volatile("cp.async.cg.shared.global [%0], [%1], 16;" :: "r"(dst), "l"(src));
}
#define CP_COMMIT() asm volatile("cp.async.commit_group;" ::: "memory")
#define CP_WAIT0()  asm volatile("cp.async.wait_group 0;" ::: "memory")

// ---------------- CSR build kernels ----------------
__global__ void k_zeroi(int* __restrict__ p, int n) {
    int i = blockIdx.x * 256 + threadIdx.x;
    if (i < n) p[i] = 0;
}
__global__ void k_hist(const int* __restrict__ dst, int* __restrict__ cnt, int n) {
    int i = blockIdx.x * 256 + threadIdx.x;
    if (i < n) atomicAdd(&cnt[dst[i]], 1);
}
__global__ void k_scan1(const int* __restrict__ cnt, int* __restrict__ ex, int n,
                        int* __restrict__ part) {
    __shared__ int sh[256];
    int base = blockIdx.x * 1024;
    int t = threadIdx.x;
    int v[4], s = 0;
#pragma unroll
    for (int j = 0; j < 4; j++) {
        int i = base + t * 4 + j;
        v[j] = (i < n) ? cnt[i] : 0;
        s += v[j];
    }
    sh[t] = s;
    __syncthreads();
    for (int off = 1; off < 256; off <<= 1) {
        int x = (t >= off) ? sh[t - off] : 0;
        __syncthreads();
        sh[t] += x;
        __syncthreads();
    }
    int run = (t > 0) ? sh[t - 1] : 0;
    if (part && t == 255) part[blockIdx.x] = sh[255];
#pragma unroll
    for (int j = 0; j < 4; j++) {
        int i = base + t * 4 + j;
        if (i < n) ex[i] = run;
        run += v[j];
    }
}
__global__ void k_scan3(int* __restrict__ ex, int* __restrict__ cursor,
                        const int* __restrict__ part2, int n, int ntot) {
    int i = blockIdx.x * 256 + threadIdx.x;
    if (i < n) {
        int v = ex[i] + part2[i >> 10];
        ex[i] = v;
        cursor[i] = v;
    }
    if (i == 0) ex[n] = ntot;
}
__global__ void k_fill(const int* __restrict__ src, const int* __restrict__ dst,
                       int* __restrict__ cursor, int* __restrict__ csr, int n) {
    int i = blockIdx.x * 256 + threadIdx.x;
    if (i < n) {
        int pos = atomicAdd(&cursor[dst[i]], 1);
        csr[pos] = src[i];
    }
}
__global__ void k_fill_id(const int* __restrict__ dst, int* __restrict__ cursor,
                          int* __restrict__ csr, int n) {
    int i = blockIdx.x * 256 + threadIdx.x;
    if (i < n) {
        int pos = atomicAdd(&cursor[dst[i]], 1);
        csr[pos] = i;
    }
}

// ---------------- utility kernels ----------------
__global__ void k_zero_alpha() {
    int i = blockIdx.x * 256 + threadIdx.x;
    ((float4*)g_alpha)[i] = make_float4(0.f, 0.f, 0.f, 0.f);
}
__global__ void k_zero_out(float* __restrict__ out) {
    int i = blockIdx.x * 256 + threadIdx.x;
    ((float4*)out)[i] = make_float4(0.f, 0.f, 0.f, 0.f);
    if (i < NGRAPH) g_counts[i] = 0.f;
}
__global__ void k_counts(const int* __restrict__ gids) {
    int v = blockIdx.x * 256 + threadIdx.x;
    if (v < N_NODES_C) atomicAdd(&g_counts[gids[v]], 1.0f);
}
__global__ void k_div(float* __restrict__ out) {
    int i = blockIdx.x * 256 + threadIdx.x;
    int g = i >> 6;
    float c = fmaxf(g_counts[g], 1.0f);
    float4 v = ((float4*)out)[i];
    v.x /= c; v.y /= c; v.z /= c; v.w /= c;
    ((float4*)out)[i] = v;
}
__global__ void k_prep_w(const float* __restrict__ Wh, const float* __restrict__ Wo) {
    int n = blockIdx.x & 255;
    int k = threadIdx.x;
    if (blockIdx.x < 256) g_WhT[n * 256 + k] = __float2half_rn(Wh[k * 256 + n]);
    else                  g_WoT[n * 256 + k] = __float2half_rn(Wo[(AFD + k) * 256 + n]);
}
__global__ void k_tree_scatter(const float* __restrict__ tree, const int* __restrict__ tgt) {
    int i = blockIdx.x * 256 + threadIdx.x;
    int t = i >> 6, q = i & 63;
    float4 v = ((const float4*)tree)[(size_t)t * 64 + q];
    red4(g_alpha + (size_t)tgt[t] * HID + q * 4, v.x, v.y, v.z, v.w);
}

__device__ __forceinline__ uint2 f4toh4(float4 v) {
    __half2 h01 = __floats2half2_rn(v.x, v.y);
    __half2 h23 = __floats2half2_rn(v.z, v.w);
    return make_uint2(h2u(h01), h2u(h23));
}
__device__ __forceinline__ float4 h4tof4(uint2 u) {
    __half2 a = *reinterpret_cast<__half2*>(&u.x);
    __half2 b = *reinterpret_cast<__half2*>(&u.y);
    float2 fa = __half22float2(a);
    float2 fb = __half22float2(b);
    return make_float4(fa.x, fa.y, fb.x, fb.y);
}

// ---------------- CSR gather (chunked): acc[e] = alpha[esrc[e]] + sum relu?(src) -----
template<bool FIRST>
__global__ __launch_bounds__(256)
void k_lg_gather(const int* __restrict__ esrc, const __half* __restrict__ srch,
                 int e_off, int e_cnt) {
    int i = blockIdx.x * 256 + threadIdx.x;
    int e = e_off + (i >> 6), q = i & 63;
    if (e >= e_off + e_cnt) return;
    int a = __ldg(&esrc[e]);
    float4 acc = ((const float4*)g_alpha)[(size_t)a * 64 + q];
    int beg = __ldg(&g_lg_rowptr[e]);
    int end = __ldg(&g_lg_rowptr[e + 1]);
    for (int j = beg; j < end; j++) {
        int s = __ldg(&g_lg_csr[j]);
        float4 v = h4tof4(__ldg((const uint2*)srch + (size_t)s * 64 + q));
        if (FIRST) {
            v.x = fmaxf(v.x, 0.f); v.y = fmaxf(v.y, 0.f);
            v.z = fmaxf(v.z, 0.f); v.w = fmaxf(v.w, 0.f);
        }
        acc.x += v.x; acc.y += v.y; acc.z += v.z; acc.w += v.w;
    }
    ((uint2*)g_accH)[(size_t)e * 64 + q] = f4toh4(acc);
}

// mplus[v] = alpha[v] + sum msg[nd_csr[...]]  (chunked)
__global__ __launch_bounds__(256)
void k_node_gather(const __half* __restrict__ msg, int v_off, int v_cnt) {
    int i = blockIdx.x * 256 + threadIdx.x;
    int v = v_off + (i >> 6), q = i & 63;
    if (v >= v_off + v_cnt) return;
    float4 acc = ((const float4*)g_alpha)[(size_t)v * 64 + q];
    int beg = __ldg(&g_nd_rowptr[v]);
    int end = __ldg(&g_nd_rowptr[v + 1]);
    for (int j = beg; j < end; j++) {
        int s = __ldg(&g_nd_csr[j]);
        float4 m = h4tof4(__ldg((const uint2*)msg + (size_t)s * 64 + q));
        acc.x += m.x; acc.y += m.y; acc.z += m.z; acc.w += m.w;
    }
    ((uint2*)g_mpH)[(size_t)v * 64 + q] = f4toh4(acc);
}

// ---------------- msg_input = [node_x[src]; bond_x] @ W_i  (fp16 out) ----------------
__global__ __launch_bounds__(256)
void k_msg_in(const float* __restrict__ node_x, const float* __restrict__ bond_x,
              const float* __restrict__ W_i, const int* __restrict__ esrc) {
    __shared__ float feat[64][KIN];
    int e0 = blockIdx.x * 64;
    int tid = threadIdx.x;
    float w[KIN];
#pragma unroll
    for (int k = 0; k < KIN; k++) w[k] = W_i[k * HID + tid];
    for (int idx = tid; idx < 64 * KIN; idx += 256) {
        int e = idx / KIN, k = idx % KIN;
        int ge = e0 + e;
        float vv = 0.f;
        if (ge < N_EDGES_C)
            vv = (k < AFD) ? node_x[(size_t)esrc[ge] * AFD + k]
                           : bond_x[(size_t)ge * BFD + (k - AFD)];
        feat[e][k] = vv;
    }
    __syncthreads();
    for (int e = 0; e < 64; e++) {
        int ge = e0 + e;
        if (ge >= N_EDGES_C) break;
        const float4* f4 = (const float4*)feat[e];
        float a0 = 0.f, a1 = 0.f;
#pragma unroll
        for (int k4 = 0; k4 < KIN / 4; k4++) {
            float4 ff = f4[k4];
            a0 = fmaf(ff.x, w[k4 * 4 + 0], a0);
            a1 = fmaf(ff.y, w[k4 * 4 + 1], a1);
            a0 = fmaf(ff.z, w[k4 * 4 + 2], a0);
            a1 = fmaf(ff.w, w[k4 * 4 + 3], a1);
        }
        g_msgIn[(size_t)ge * HID + tid] = __float2half_rn(a0 + a1);
    }
}

// ---------------- g_hbias = node_x @ W_o[:35] + b_o  (fp16 out) ----------------
__global__ __launch_bounds__(256)
void k_hbias(const float* __restrict__ node_x, const float* __restrict__ W_o,
             const float* __restrict__ b_o) {
    __shared__ float feat[64][36];
    int v0 = blockIdx.x * 64;
    int tid = threadIdx.x;
    float w[36];
#pragma unroll
    for (int k = 0; k < AFD; k++) w[k] = W_o[k * HID + tid];
    w[35] = 0.f;
    float bb = b_o[tid];
    for (int idx = tid; idx < 64 * 36; idx += 256) {
        int v = idx / 36, k = idx % 36;
        int gv = v0 + v;
        feat[v][k] = (gv < N_NODES_C && k < AFD) ? node_x[(size_t)gv * AFD + k] : 0.f;
    }
    __syncthreads();
    for (int v = 0; v < 64; v++) {
        int gv = v0 + v;
        if (gv >= N_NODES_C) break;
        const float4* f4 = (const float4*)feat[v];
        float a0 = bb, a1 = 0.f;
#pragma unroll
        for (int k4 = 0; k4 < 9; k4++) {
            float4 ff = f4[k4];
            a0 = fmaf(ff.x, w[k4 * 4 + 0], a0);
            a1 = fmaf(ff.y, w[k4 * 4 + 1], a1);
            a0 = fmaf(ff.z, w[k4 * 4 + 2], a0);
            a1 = fmaf(ff.w, w[k4 * 4 + 3], a1);
        }
        g_hbias[(size_t)gv * HID + tid] = __float2half_rn(a0 + a1);
    }
}

// ---------------- wide-N fp16 GEMM: D = Ah @ Bh^T  (1 mma term, chunked) -------------
#define MMW_BUF  49152
#define MMW_SMEM (2 * MMW_BUF)

template<int MODE>
__global__ __launch_bounds__(512, 1)
void k_mmw(const __half* __restrict__ Ahi,
           const __half* __restrict__ bias,
           const __half* __restrict__ Bhi,
           __half* __restrict__ dsth, const int* __restrict__ gids,
           float* __restrict__ out, int m_off, int M) {
    extern __shared__ char sm[];
    const int tid  = threadIdx.x;
    const int lane = tid & 31;
    const int wid  = tid >> 5;
    const int wm   = wid >> 2;
    const int wn   = wid & 3;
    const int m0   = m_off + blockIdx.x * 128;
    const uint32_t sbase = smem_u32(sm);

    float d[2][8][4];
#pragma unroll
    for (int i = 0; i < 2; i++)
#pragma unroll
        for (int j = 0; j < 8; j++)
#pragma unroll
            for (int q = 0; q < 4; q++) d[i][j][q] = 0.f;

    auto cpA = [&](int cc, int b) {
        uint32_t base = sbase + b * MMW_BUF;
#pragma unroll
        for (int j = 0; j < 2; j++) {
            int idx = tid + j * 512;
            int row = idx >> 3, seg = idx & 7;
            uint32_t off = (uint32_t)(row * 128 + seg * 16);
            uint32_t sw = off ^ ((off >> 3) & 0x70);
            cp16(base + sw, Ahi + (size_t)(m0 + row) * 256 + cc * 64 + seg * 8);
        }
    };
    auto cpB = [&](int cc, int b) {
        uint32_t base = sbase + b * MMW_BUF;
#pragma unroll
        for (int j = 0; j < 4; j++) {
            int idx = tid + j * 512;
            int row = idx >> 3, seg = idx & 7;
            uint32_t off = (uint32_t)(row * 128 + seg * 16);
            uint32_t sw = off ^ ((off >> 3) & 0x70);
            cp16(base + 16384u + sw, Bhi + (size_t)row * 256 + cc * 64 + seg * 8);
        }
    };
    auto compute = [&](int b) {
        uint32_t baseA  = sbase + b * MMW_BUF;
        uint32_t baseBh = baseA + 16384;
        const int r = lane & 7, q = lane >> 3;
        const int bro = ((q >> 1) << 3) + r;
        const int bkp = (q & 1) << 4;
#pragma unroll
        for (int s = 0; s < 4; s++) {
            uint32_t ah[2][4];
#pragma unroll
            for (int mt = 0; mt < 2; mt++) {
                uint32_t mrow = (uint32_t)(wm * 32 + mt * 16 + (q & 1) * 8 + r);
                uint32_t off = mrow * 128 + (q >> 1) * 16 + s * 32;
                uint32_t sw = off ^ ((off >> 3) & 0x70);
                ldsm4(ah[mt], baseA + sw);
            }
#pragma unroll
            for (int h = 0; h < 2; h++) {
                uint32_t bh4[2][4];
#pragma unroll
                for (int ntp = 0; ntp < 2; ntp++) {
                    uint32_t nrow = (uint32_t)(wn * 64 + h * 32 + ntp * 16 + bro);
                    uint32_t off = nrow * 128 + bkp + s * 32;
                    uint32_t sw = off ^ ((off >> 3) & 0x70);
                    ldsm4(bh4[ntp], baseBh + sw);
                }
#pragma unroll
                for (int mt = 0; mt < 2; mt++)
#pragma unroll
                    for (int nt = 0; nt < 4; nt++)
                        mma_f16(d[mt][h * 4 + nt], ah[mt], &bh4[nt >> 1][(nt & 1) * 2]);
            }
        }
    };

    cpA(0, 0); cpB(0, 0); CP_COMMIT();
    CP_WAIT0();
    __syncthreads();

#pragma unroll
    for (int c = 0; c < 4; c++) {
        if (c < 3) { cpA(c + 1, (c + 1) & 1); cpB(c + 1, (c + 1) & 1); CP_COMMIT(); }
        compute(c & 1);
        if (c < 3) CP_WAIT0();
        __syncthreads();
    }

#pragma unroll
    for (int mt = 0; mt < 2; mt++) {
#pragma unroll
        for (int n = 0; n < 8; n++) {
            int row = m0 + wm * 32 + mt * 16 + (lane >> 2);
            int col = wn * 64 + n * 8 + (lane & 3) * 2;
#pragma unroll
            for (int h2 = 0; h2 < 2; h2++) {
                int gr = row + h2 * 8;
                if (gr >= M) continue;
                size_t gb = (size_t)gr * 256 + col;
                uint32_t bu = *(const uint32_t*)(bias + gb);
                __half2 bh = *reinterpret_cast<__half2*>(&bu);
                float2 bv = __half22float2(bh);
                float ox = fmaxf(bv.x + d[mt][n][h2 * 2 + 0], 0.f);
                float oy = fmaxf(bv.y + d[mt][n][h2 * 2 + 1], 0.f);
                if (MODE == 0) {
                    __half2 hv = __floats2half2_rn(ox, oy);
                    *(uint32_t*)(dsth + gb) = h2u(hv);
                } else {
                    int g = gids[gr];
                    red2(out + (size_t)g * 256 + col, ox, oy);
                }
            }
        }
    }
}

// ---------------- launch ----------------
extern "C" void kernel_launch(void* const* d_in, const int* in_sizes, int n_in,
                              void* d_out, int out_size) {
    (void)in_sizes; (void)n_in; (void)out_size;
    const float* node_x = (const float*)d_in[0];
    const float* bond_x = (const float*)d_in[1];
    const float* tree   = (const float*)d_in[2];
    const float* W_i    = (const float*)d_in[3];
    const float* W_h    = (const float*)d_in[4];
    const float* W_o    = (const float*)d_in[5];
    const float* b_o    = (const float*)d_in[6];
    const int* esrc = (const int*)d_in[7];
    const int* edst = (const int*)d_in[8];
    const int* lsrc = (const int*)d_in[9];
    const int* ldst = (const int*)d_in[10];
    const int* tgt  = (const int*)d_in[11];
    const int* gids = (const int*)d_in[12];
    float* out = (float*)d_out;

    static cudaStream_t s1 = nullptr;
    static cudaEvent_t ev[12];
    if (!s1) {
        cudaStreamCreateWithFlags(&s1, cudaStreamNonBlocking);
        for (int i = 0; i < 12; i++)
            cudaEventCreateWithFlags(&ev[i], cudaEventDisableTiming);
        cudaFuncSetAttribute(k_mmw<0>, cudaFuncAttributeMaxDynamicSharedMemorySize, MMW_SMEM);
        cudaFuncSetAttribute(k_mmw<1>, cudaFuncAttributeMaxDynamicSharedMemorySize, MMW_SMEM);
    }

    __half *msgIn_p, *msgH_p, *msgHB_p, *accH_p, *mpH_p, *hb_p, *WhT_p, *WoT_p;
    cudaGetSymbolAddress((void**)&msgIn_p, g_msgIn);
    cudaGetSymbolAddress((void**)&msgH_p,  g_msgH);
    cudaGetSymbolAddress((void**)&msgHB_p, g_msgHB);
    cudaGetSymbolAddress((void**)&accH_p,  g_accH);
    cudaGetSymbolAddress((void**)&mpH_p,   g_mpH);
    cudaGetSymbolAddress((void**)&hb_p,    g_hbias);
    cudaGetSymbolAddress((void**)&WhT_p,   g_WhT);
    cudaGetSymbolAddress((void**)&WoT_p,   g_WoT);
    int *lg_rp, *lg_cur, *lg_csr_p, *nd_rp, *nd_cur, *nd_csr_p, *part_p, *part2_p;
    cudaGetSymbolAddress((void**)&lg_rp,    g_lg_rowptr);
    cudaGetSymbolAddress((void**)&lg_cur,   g_lg_cursor);
    cudaGetSymbolAddress((void**)&lg_csr_p, g_lg_csr);
    cudaGetSymbolAddress((void**)&nd_rp,    g_nd_rowptr);
    cudaGetSymbolAddress((void**)&nd_cur,   g_nd_cursor);
    cudaGetSymbolAddress((void**)&nd_csr_p, g_nd_csr);
    cudaGetSymbolAddress((void**)&part_p,   g_part);
    cudaGetSymbolAddress((void**)&part2_p,  g_part2);

    int evi = 0;

    // ==== fork side stream ====
    cudaEventRecord(ev[evi], 0);
    cudaStreamWaitEvent(s1, ev[evi], 0);
    evi++;

    // ---- side stream: CSR builds + weight prep + hbias + out/counts init ----
    k_zeroi<<<1172, 256, 0, s1>>>(lg_cur, N_EDGES_C);
    k_hist<<<2344, 256, 0, s1>>>(ldst, lg_cur, N_LG_C);
    k_scan1<<<293, 256, 0, s1>>>(lg_cur, lg_rp, N_EDGES_C, part_p);
    k_scan1<<<1, 256, 0, s1>>>(part_p, part2_p, 293, nullptr);
    k_scan3<<<1172, 256, 0, s1>>>(lg_rp, lg_cur, part2_p, N_EDGES_C, N_LG_C);
    k_fill<<<2344, 256, 0, s1>>>(lsrc, ldst, lg_cur, lg_csr_p, N_LG_C);
    k_zeroi<<<586, 256, 0, s1>>>(nd_cur, N_NODES_C);
    k_hist<<<1172, 256, 0, s1>>>(edst, nd_cur, N_EDGES_C);
    k_scan1<<<147, 256, 0, s1>>>(nd_cur, nd_rp, N_NODES_C, part_p);
    k_scan1<<<1, 256, 0, s1>>>(part_p, part2_p, 147, nullptr);
    k_scan3<<<586, 256, 0, s1>>>(nd_rp, nd_cur, part2_p, N_NODES_C, N_EDGES_C);
    k_fill_id<<<1172, 256, 0, s1>>>(edst, nd_cur, nd_csr_p, N_EDGES_C);
    k_prep_w<<<512, 256, 0, s1>>>(W_h, W_o);
    k_hbias<<<(N_NODES_C + 63) / 64, 256, 0, s1>>>(node_x, W_o, b_o);
    k_zero_out<<<512, 256, 0, s1>>>(out);
    k_counts<<<586, 256, 0, s1>>>(gids);

    // ---- main stream: alpha + msg_input ----
    k_zero_alpha<<<37500, 256>>>();
    k_tree_scatter<<<15000, 256>>>(tree, tgt);
    k_msg_in<<<(N_EDGES_C + 63) / 64, 256>>>(node_x, bond_x, W_i, esrc);

    // ==== join ====
    cudaEventRecord(ev[evi], s1);
    cudaStreamWaitEvent(0, ev[evi], 0);
    evi++;

    // ==== BP iterations: G0 -> [M0 || G1] -> M1 ====
    const __half* srcb[3] = { msgIn_p, msgH_p, msgHB_p };
    __half*       dstb[3] = { msgH_p, msgHB_p, msgH_p };
    const int E1 = N_EDGES_C - E_SPLIT;               // 149984
    for (int it = 0; it < 3; it++) {
        if (it == 0) k_lg_gather<true><<<E_SPLIT / 4, 256>>>(esrc, srcb[it], 0, E_SPLIT);
        else         k_lg_gather<false><<<E_SPLIT / 4, 256>>>(esrc, srcb[it], 0, E_SPLIT);
        cudaEventRecord(ev[evi], 0);
        cudaStreamWaitEvent(s1, ev[evi], 0);
        evi++;
        if (it == 0) k_lg_gather<true><<<(E1 + 3) / 4, 256, 0, s1>>>(esrc, srcb[it], E_SPLIT, E1);
        else         k_lg_gather<false><<<(E1 + 3) / 4, 256, 0, s1>>>(esrc, srcb[it], E_SPLIT, E1);
        k_mmw<0><<<E_SPLIT / 128, 512, MMW_SMEM>>>(accH_p, msgIn_p, WhT_p, dstb[it],
                                                   nullptr, nullptr, 0, N_EDGES_C);
        k_mmw<0><<<(E1 + 127) / 128, 512, MMW_SMEM, s1>>>(accH_p, msgIn_p, WhT_p, dstb[it],
                                                          nullptr, nullptr, E_SPLIT, N_EDGES_C);
        cudaEventRecord(ev[evi], s1);
        cudaStreamWaitEvent(0, ev[evi], 0);
        evi++;
    }

    // ==== readout: NG0 -> [MM0 || NG1] -> MM1 ====
    const int V1 = N_NODES_C - V_SPLIT;               // 74992
    k_node_gather<<<V_SPLIT / 4, 256>>>(msgH_p, 0, V_SPLIT);
    cudaEventRecord(ev[evi], 0);
    cudaStreamWaitEvent(s1, ev[evi], 0);
    evi++;
    k_node_gather<<<(V1 + 3) / 4, 256, 0, s1>>>(msgH_p, V_SPLIT, V1);
    k_mmw<1><<<V_SPLIT / 128, 512, MMW_SMEM>>>(mpH_p, hb_p, WoT_p, nullptr,
                                               gids, out, 0, N_NODES_C);
    k_mmw<1><<<(V1 + 127) / 128, 512, MMW_SMEM, s1>>>(mpH_p, hb_p, WoT_p, nullptr,
                                                      gids, out, V_SPLIT, N_NODES_C);
    cudaEventRecord(ev[evi], s1);
    cudaStreamWaitEvent(0, ev[evi], 0);
    evi++;

    k_div<<<512, 256>>>(out);
}

// round 15
// speedup vs baseline: 1.6465x; 1.0035x over previous
#include <cuda_runtime.h>
#include <cuda_fp16.h>
#include <cstdint>

#define N_NODES_C 150000
#define N_EDGES_C 300000
#define N_LG_C    600000
#define HID       256
#define NGRAPH    2048
#define AFD       35
#define BFD       5
#define KIN       40

#define E_SPLIT   150016
#define V_SPLIT   75008

// ---------------- scratch (static device globals; no allocation) ----------------
__device__ __half g_msgIn[(size_t)N_EDGES_C * HID];
__device__ __half g_msgH [(size_t)N_EDGES_C * HID];
__device__ __half g_msgHB[(size_t)N_EDGES_C * HID];
__device__ __half g_accH[((size_t)N_EDGES_C + 128) * HID];
__device__ __half g_mpH [((size_t)N_NODES_C + 128) * HID];
__device__ float  g_alpha [(size_t)N_NODES_C * HID];
__device__ __half g_alphaH[(size_t)N_NODES_C * HID];
__device__ __half g_hbias[(size_t)N_NODES_C * HID];
__device__ __half g_WhT[HID * HID];
__device__ __half g_WoT[HID * HID];
__device__ __half g_WiT  [HID * 64];   // W_i^T padded [n][64]
__device__ __half g_WoTop[HID * 64];   // W_o[:35]^T padded [n][64]
__device__ float  g_counts[NGRAPH];

// CSR structures
__device__ int g_lg_rowptr[N_EDGES_C + 1];
__device__ int g_lg_cursor[N_EDGES_C];
__device__ int g_lg_csr[N_LG_C];
__device__ int g_nd_rowptr[N_NODES_C + 1];
__device__ int g_nd_cursor[N_NODES_C];
__device__ int g_nd_csr[N_EDGES_C];
__device__ int g_part [1024];
__device__ int g_part2[1024];

// ---------------- PTX helpers (portable: sm_80/sm_90 level only) ----------------
__device__ __forceinline__ uint32_t smem_u32(const void* p) {
    uint32_t a;
    asm("{ .reg .u64 t; cvta.to.shared.u64 t, %1; cvt.u32.u64 %0, t; }" : "=r"(a) : "l"(p));
    return a;
}
__device__ __forceinline__ void red4(float* p, float a, float b, float c, float d) {
    asm volatile("red.global.add.v4.f32 [%0], {%1, %2, %3, %4};"
                 :: "l"(p), "f"(a), "f"(b), "f"(c), "f"(d) : "memory");
}
__device__ __forceinline__ void red2(float* p, float a, float b) {
    asm volatile("red.global.add.v2.f32 [%0], {%1, %2};"
                 :: "l"(p), "f"(a), "f"(b) : "memory");
}
__device__ __forceinline__ void ldsm4(uint32_t* r, uint32_t addr) {
    asm volatile("ldmatrix.sync.aligned.m8n8.x4.shared.b16 {%0,%1,%2,%3}, [%4];"
                 : "=r"(r[0]), "=r"(r[1]), "=r"(r[2]), "=r"(r[3]) : "r"(addr));
}
__device__ __forceinline__ void mma_f16(float* d, const uint32_t* a, const uint32_t* b) {
    asm volatile(
        "mma.sync.aligned.m16n8k16.row.col.f32.f16.f16.f32 "
        "{%0,%1,%2,%3}, {%4,%5,%6,%7}, {%8,%9}, {%0,%1,%2,%3};"
        : "+f"(d[0]), "+f"(d[1]), "+f"(d[2]), "+f"(d[3])
        : "r"(a[0]), "r"(a[1]), "r"(a[2]), "r"(a[3]), "r"(b[0]), "r"(b[1]));
}
__device__ __forceinline__ uint32_t h2u(__half2 h) { return *reinterpret_cast<uint32_t*>(&h); }
__device__ __forceinline__ void cp16(uint32_t dst, const void* src) {
    asm volatile("cp.async.cg.shared.global [%0], [%1], 16;" :: "r"(dst), "l"(src));
}
#define CP_COMMIT() asm volatile("cp.async.commit_group;" ::: "memory")
#define CP_WAIT0()  asm volatile("cp.async.wait_group 0;" ::: "memory")

// ---------------- CSR build kernels ----------------
__global__ void k_zeroi(int* __restrict__ p, int n) {
    int i = blockIdx.x * 256 + threadIdx.x;
    if (i < n) p[i] = 0;
}
__global__ void k_hist(const int* __restrict__ dst, int* __restrict__ cnt, int n) {
    int i = blockIdx.x * 256 + threadIdx.x;
    if (i < n) atomicAdd(&cnt[dst[i]], 1);
}
__global__ void k_scan1(const int* __restrict__ cnt, int* __restrict__ ex, int n,
                        int* __restrict__ part) {
    __shared__ int sh[256];
    int base = blockIdx.x * 1024;
    int t = threadIdx.x;
    int v[4], s = 0;
#pragma unroll
    for (int j = 0; j < 4; j++) {
        int i = base + t * 4 + j;
        v[j] = (i < n) ? cnt[i] : 0;
        s += v[j];
    }
    sh[t] = s;
    __syncthreads();
    for (int off = 1; off < 256; off <<= 1) {
        int x = (t >= off) ? sh[t - off] : 0;
        __syncthreads();
        sh[t] += x;
        __syncthreads();
    }
    int run = (t > 0) ? sh[t - 1] : 0;
    if (part && t == 255) part[blockIdx.x] = sh[255];
#pragma unroll
    for (int j = 0; j < 4; j++) {
        int i = base + t * 4 + j;
        if (i < n) ex[i] = run;
        run += v[j];
    }
}
__global__ void k_scan3(int* __restrict__ ex, int* __restrict__ cursor,
                        const int* __restrict__ part2, int n, int ntot) {
    int i = blockIdx.x * 256 + threadIdx.x;
    if (i < n) {
        int v = ex[i] + part2[i >> 10];
        ex[i] = v;
        cursor[i] = v;
    }
    if (i == 0) ex[n] = ntot;
}
__global__ void k_fill(const int* __restrict__ src, const int* __restrict__ dst,
                       int* __restrict__ cursor, int* __restrict__ csr, int n) {
    int i = blockIdx.x * 256 + threadIdx.x;
    if (i < n) {
        int pos = atomicAdd(&cursor[dst[i]], 1);
        csr[pos] = src[i];
    }
}
__global__ void k_fill_id(const int* __restrict__ dst, int* __restrict__ cursor,
                          int* __restrict__ csr, int n) {
    int i = blockIdx.x * 256 + threadIdx.x;
    if (i < n) {
        int pos = atomicAdd(&cursor[dst[i]], 1);
        csr[pos] = i;
    }
}

// ---------------- utility kernels ----------------
__global__ void k_zero_alpha() {
    int i = blockIdx.x * 256 + threadIdx.x;
    ((float4*)g_alpha)[i] = make_float4(0.f, 0.f, 0.f, 0.f);
}
__global__ void k_zero_out(float* __restrict__ out) {
    int i = blockIdx.x * 256 + threadIdx.x;
    ((float4*)out)[i] = make_float4(0.f, 0.f, 0.f, 0.f);
    if (i < NGRAPH) g_counts[i] = 0.f;
}
__global__ void k_counts(const int* __restrict__ gids) {
    int v = blockIdx.x * 256 + threadIdx.x;
    if (v < N_NODES_C) atomicAdd(&g_counts[gids[v]], 1.0f);
}
__global__ void k_div(float* __restrict__ out) {
    int i = blockIdx.x * 256 + threadIdx.x;
    int g = i >> 6;
    float c = fmaxf(g_counts[g], 1.0f);
    float4 v = ((float4*)out)[i];
    v.x /= c; v.y /= c; v.z /= c; v.w /= c;
    ((float4*)out)[i] = v;
}
__global__ void k_prep_w(const float* __restrict__ Wh, const float* __restrict__ Wo) {
    int n = blockIdx.x & 255;
    int k = threadIdx.x;
    if (blockIdx.x < 256) g_WhT[n * 256 + k] = __float2half_rn(Wh[k * 256 + n]);
    else                  g_WoT[n * 256 + k] = __float2half_rn(Wo[(AFD + k) * 256 + n]);
}
// W_i^T and W_o[:35]^T, padded K -> 64, fp16
__global__ void k_prep_w2(const float* __restrict__ Wi, const float* __restrict__ Wo) {
    int n = blockIdx.x & 255;
    int k = threadIdx.x;   // 0..63
    if (blockIdx.x < 256)
        g_WiT[n * 64 + k]   = __float2half_rn((k < KIN) ? Wi[k * 256 + n] : 0.f);
    else
        g_WoTop[n * 64 + k] = __float2half_rn((k < AFD) ? Wo[k * 256 + n] : 0.f);
}
__global__ void k_tree_scatter(const float* __restrict__ tree, const int* __restrict__ tgt) {
    int i = blockIdx.x * 256 + threadIdx.x;
    int t = i >> 6, q = i & 63;
    float4 v = ((const float4*)tree)[(size_t)t * 64 + q];
    red4(g_alpha + (size_t)tgt[t] * HID + q * 4, v.x, v.y, v.z, v.w);
}

__device__ __forceinline__ uint2 f4toh4(float4 v) {
    __half2 h01 = __floats2half2_rn(v.x, v.y);
    __half2 h23 = __floats2half2_rn(v.z, v.w);
    return make_uint2(h2u(h01), h2u(h23));
}
__device__ __forceinline__ float4 h4tof4(uint2 u) {
    __half2 a = *reinterpret_cast<__half2*>(&u.x);
    __half2 b = *reinterpret_cast<__half2*>(&u.y);
    float2 fa = __half22float2(a);
    float2 fb = __half22float2(b);
    return make_float4(fa.x, fa.y, fb.x, fb.y);
}

// alpha fp32 -> fp16 copy
__global__ void k_alpha_cvt() {
    int i = blockIdx.x * 256 + threadIdx.x;   // N_NODES*64
    float4 v = ((const float4*)g_alpha)[i];
    ((uint2*)g_alphaH)[i] = f4toh4(v);
}

// ---------------- CSR gather (chunked): acc[e] = alphaH[esrc[e]] + sum relu?(src) ----
template<bool FIRST>
__global__ __launch_bounds__(256)
void k_lg_gather(const int* __restrict__ esrc, const __half* __restrict__ srch,
                 int e_off, int e_cnt) {
    int i = blockIdx.x * 256 + threadIdx.x;
    int e = e_off + (i >> 6), q = i & 63;
    if (e >= e_off + e_cnt) return;
    int a = __ldg(&esrc[e]);
    float4 acc = h4tof4(__ldg((const uint2*)g_alphaH + (size_t)a * 64 + q));
    int beg = __ldg(&g_lg_rowptr[e]);
    int end = __ldg(&g_lg_rowptr[e + 1]);
    for (int j = beg; j < end; j++) {
        int s = __ldg(&g_lg_csr[j]);
        float4 v = h4tof4(__ldg((const uint2*)srch + (size_t)s * 64 + q));
        if (FIRST) {
            v.x = fmaxf(v.x, 0.f); v.y = fmaxf(v.y, 0.f);
            v.z = fmaxf(v.z, 0.f); v.w = fmaxf(v.w, 0.f);
        }
        acc.x += v.x; acc.y += v.y; acc.z += v.z; acc.w += v.w;
    }
    ((uint2*)g_accH)[(size_t)e * 64 + q] = f4toh4(acc);
}

// mplus[v] = alphaH[v] + sum msg[nd_csr[...]]
__global__ __launch_bounds__(256)
void k_node_gather(const __half* __restrict__ msg, int v_off, int v_cnt) {
    int i = blockIdx.x * 256 + threadIdx.x;
    int v = v_off + (i >> 6), q = i & 63;
    if (v >= v_off + v_cnt) return;
    float4 acc = h4tof4(__ldg((const uint2*)g_alphaH + (size_t)v * 64 + q));
    int beg = __ldg(&g_nd_rowptr[v]);
    int end = __ldg(&g_nd_rowptr[v + 1]);
    for (int j = beg; j < end; j++) {
        int s = __ldg(&g_nd_csr[j]);
        float4 m = h4tof4(__ldg((const uint2*)msg + (size_t)s * 64 + q));
        acc.x += m.x; acc.y += m.y; acc.z += m.z; acc.w += m.w;
    }
    ((uint2*)g_mpH)[(size_t)v * 64 + q] = f4toh4(acc);
}

// ---------------- single-chunk gather-GEMM (K=64 padded) ----------------
// MODE 0: msgIn[e] = [node_x[esrc[e]]; bond_x[e]; 0pad] @ WiT^T        (fp16 out)
// MODE 1: hbias[v] = [node_x[v]; 0pad] @ WoTop^T + b_o                 (fp16 out)
// SMEM: A 128x64 fp16 (16K) + B 256x64 fp16 (32K) = 48K static.
template<int MODE>
__global__ __launch_bounds__(512)
void k_gmm(const float* __restrict__ nx, const float* __restrict__ bx,
           const int* __restrict__ esrc, const __half* __restrict__ BT,
           const float* __restrict__ b_o, __half* __restrict__ dsth, int M) {
    __shared__ char sm[49152];
    __shared__ int sIdx[128];
    const int tid  = threadIdx.x;
    const int lane = tid & 31;
    const int wid  = tid >> 5;
    const int wm   = wid >> 2;
    const int wn   = wid & 3;
    const int m0   = blockIdx.x * 128;
    const uint32_t sbase = smem_u32(sm);

    // B via cp.async: 256 rows x 128B
#pragma unroll
    for (int j = 0; j < 4; j++) {
        int idx = tid + j * 512;
        int row = idx >> 3, seg = idx & 7;
        uint32_t off = (uint32_t)(row * 128 + seg * 16);
        uint32_t sw = off ^ ((off >> 3) & 0x70);
        cp16(sbase + 16384u + sw, BT + (size_t)row * 64 + seg * 8);
    }
    CP_COMMIT();

    if (MODE == 0 && tid < 128) {
        int ge = m0 + tid;
        sIdx[tid] = (ge < M) ? esrc[ge] : 0;
    }
    if (MODE == 0) __syncthreads();

    // A staging: 128 rows x 64 k (scalar fp16 stores, swizzled)
    for (int idx = tid; idx < 8192; idx += 512) {
        int row = idx >> 6, k = idx & 63;
        int ge = m0 + row;
        float v = 0.f;
        if (ge < M) {
            if (MODE == 0) {
                if (k < AFD)      v = nx[(size_t)sIdx[row] * AFD + k];
                else if (k < KIN) v = bx[(size_t)ge * BFD + (k - AFD)];
            } else {
                if (k < AFD)      v = nx[(size_t)ge * AFD + k];
            }
        }
        uint32_t off = (uint32_t)(row * 128 + k * 2);
        uint32_t sw = off ^ ((off >> 3) & 0x70);
        *(__half*)(sm + sw) = __float2half_rn(v);
    }
    CP_WAIT0();
    __syncthreads();

    float d[2][8][4];
#pragma unroll
    for (int i = 0; i < 2; i++)
#pragma unroll
        for (int j = 0; j < 8; j++)
#pragma unroll
            for (int q = 0; q < 4; q++) d[i][j][q] = 0.f;

    {
        uint32_t baseA  = sbase;
        uint32_t baseBh = sbase + 16384;
        const int r = lane & 7, q = lane >> 3;
        const int bro = ((q >> 1) << 3) + r;
        const int bkp = (q & 1) << 4;
#pragma unroll
        for (int s = 0; s < 4; s++) {
            uint32_t ah[2][4];
#pragma unroll
            for (int mt = 0; mt < 2; mt++) {
                uint32_t mrow = (uint32_t)(wm * 32 + mt * 16 + (q & 1) * 8 + r);
                uint32_t off = mrow * 128 + (q >> 1) * 16 + s * 32;
                uint32_t sw = off ^ ((off >> 3) & 0x70);
                ldsm4(ah[mt], baseA + sw);
            }
#pragma unroll
            for (int h = 0; h < 2; h++) {
                uint32_t bh4[2][4];
#pragma unroll
                for (int ntp = 0; ntp < 2; ntp++) {
                    uint32_t nrow = (uint32_t)(wn * 64 + h * 32 + ntp * 16 + bro);
                    uint32_t off = nrow * 128 + bkp + s * 32;
                    uint32_t sw = off ^ ((off >> 3) & 0x70);
                    ldsm4(bh4[ntp], baseBh + sw);
                }
#pragma unroll
                for (int mt = 0; mt < 2; mt++)
#pragma unroll
                    for (int nt = 0; nt < 4; nt++)
                        mma_f16(d[mt][h * 4 + nt], ah[mt], &bh4[nt >> 1][(nt & 1) * 2]);
            }
        }
    }

#pragma unroll
    for (int mt = 0; mt < 2; mt++) {
#pragma unroll
        for (int n = 0; n < 8; n++) {
            int row = m0 + wm * 32 + mt * 16 + (lane >> 2);
            int col = wn * 64 + n * 8 + (lane & 3) * 2;
#pragma unroll
            for (int h2 = 0; h2 < 2; h2++) {
                int gr = row + h2 * 8;
                if (gr >= M) continue;
                float ox = d[mt][n][h2 * 2 + 0];
                float oy = d[mt][n][h2 * 2 + 1];
                if (MODE == 1) {
                    float2 bo = *(const float2*)(b_o + col);
                    ox += bo.x; oy += bo.y;
                }
                __half2 hv = __floats2half2_rn(ox, oy);
                *(uint32_t*)(dsth + (size_t)gr * 256 + col) = h2u(hv);
            }
        }
    }
}

// ---------------- wide-N fp16 GEMM: D = Ah @ Bh^T  (1 mma term, chunked) -------------
#define MMW_BUF  49152
#define MMW_SMEM (2 * MMW_BUF)

template<int MODE>
__global__ __launch_bounds__(512, 1)
void k_mmw(const __half* __restrict__ Ahi,
           const __half* __restrict__ bias,
           const __half* __restrict__ Bhi,
           __half* __restrict__ dsth, const int* __restrict__ gids,
           float* __restrict__ out, int m_off, int M) {
    extern __shared__ char sm[];
    const int tid  = threadIdx.x;
    const int lane = tid & 31;
    const int wid  = tid >> 5;
    const int wm   = wid >> 2;
    const int wn   = wid & 3;
    const int m0   = m_off + blockIdx.x * 128;
    const uint32_t sbase = smem_u32(sm);

    float d[2][8][4];
#pragma unroll
    for (int i = 0; i < 2; i++)
#pragma unroll
        for (int j = 0; j < 8; j++)
#pragma unroll
            for (int q = 0; q < 4; q++) d[i][j][q] = 0.f;

    auto cpA = [&](int cc, int b) {
        uint32_t base = sbase + b * MMW_BUF;
#pragma unroll
        for (int j = 0; j < 2; j++) {
            int idx = tid + j * 512;
            int row = idx >> 3, seg = idx & 7;
            uint32_t off = (uint32_t)(row * 128 + seg * 16);
            uint32_t sw = off ^ ((off >> 3) & 0x70);
            cp16(base + sw, Ahi + (size_t)(m0 + row) * 256 + cc * 64 + seg * 8);
        }
    };
    auto cpB = [&](int cc, int b) {
        uint32_t base = sbase + b * MMW_BUF;
#pragma unroll
        for (int j = 0; j < 4; j++) {
            int idx = tid + j * 512;
            int row = idx >> 3, seg = idx & 7;
            uint32_t off = (uint32_t)(row * 128 + seg * 16);
            uint32_t sw = off ^ ((off >> 3) & 0x70);
            cp16(base + 16384u + sw, Bhi + (size_t)row * 256 + cc * 64 + seg * 8);
        }
    };
    auto compute = [&](int b) {
        uint32_t baseA  = sbase + b * MMW_BUF;
        uint32_t baseBh = baseA + 16384;
        const int r = lane & 7, q = lane >> 3;
        const int bro = ((q >> 1) << 3) + r;
        const int bkp = (q & 1) << 4;
#pragma unroll
        for (int s = 0; s < 4; s++) {
            uint32_t ah[2][4];
#pragma unroll
            for (int mt = 0; mt < 2; mt++) {
                uint32_t mrow = (uint32_t)(wm * 32 + mt * 16 + (q & 1) * 8 + r);
                uint32_t off = mrow * 128 + (q >> 1) * 16 + s * 32;
                uint32_t sw = off ^ ((off >> 3) & 0x70);
                ldsm4(ah[mt], baseA + sw);
            }
#pragma unroll
            for (int h = 0; h < 2; h++) {
                uint32_t bh4[2][4];
#pragma unroll
                for (int ntp = 0; ntp < 2; ntp++) {
                    uint32_t nrow = (uint32_t)(wn * 64 + h * 32 + ntp * 16 + bro);
                    uint32_t off = nrow * 128 + bkp + s * 32;
                    uint32_t sw = off ^ ((off >> 3) & 0x70);
                    ldsm4(bh4[ntp], baseBh + sw);
                }
#pragma unroll
                for (int mt = 0; mt < 2; mt++)
#pragma unroll
                    for (int nt = 0; nt < 4; nt++)
                        mma_f16(d[mt][h * 4 + nt], ah[mt], &bh4[nt >> 1][(nt & 1) * 2]);
            }
        }
    };

    cpA(0, 0); cpB(0, 0); CP_COMMIT();
    CP_WAIT0();
    __syncthreads();

#pragma unroll
    for (int c = 0; c < 4; c++) {
        if (c < 3) { cpA(c + 1, (c + 1) & 1); cpB(c + 1, (c + 1) & 1); CP_COMMIT(); }
        compute(c & 1);
        if (c < 3) CP_WAIT0();
        __syncthreads();
    }

#pragma unroll
    for (int mt = 0; mt < 2; mt++) {
#pragma unroll
        for (int n = 0; n < 8; n++) {
            int row = m0 + wm * 32 + mt * 16 + (lane >> 2);
            int col = wn * 64 + n * 8 + (lane & 3) * 2;
#pragma unroll
            for (int h2 = 0; h2 < 2; h2++) {
                int gr = row + h2 * 8;
                if (gr >= M) continue;
                size_t gb = (size_t)gr * 256 + col;
                uint32_t bu = *(const uint32_t*)(bias + gb);
                __half2 bh = *reinterpret_cast<__half2*>(&bu);
                float2 bv = __half22float2(bh);
                float ox = fmaxf(bv.x + d[mt][n][h2 * 2 + 0], 0.f);
                float oy = fmaxf(bv.y + d[mt][n][h2 * 2 + 1], 0.f);
                if (MODE == 0) {
                    __half2 hv = __floats2half2_rn(ox, oy);
                    *(uint32_t*)(dsth + gb) = h2u(hv);
                } else {
                    int g = gids[gr];
                    red2(out + (size_t)g * 256 + col, ox, oy);
                }
            }
        }
    }
}

// ---------------- launch ----------------
extern "C" void kernel_launch(void* const* d_in, const int* in_sizes, int n_in,
                              void* d_out, int out_size) {
    (void)in_sizes; (void)n_in; (void)out_size;
    const float* node_x = (const float*)d_in[0];
    const float* bond_x = (const float*)d_in[1];
    const float* tree   = (const float*)d_in[2];
    const float* W_i    = (const float*)d_in[3];
    const float* W_h    = (const float*)d_in[4];
    const float* W_o    = (const float*)d_in[5];
    const float* b_o    = (const float*)d_in[6];
    const int* esrc = (const int*)d_in[7];
    const int* edst = (const int*)d_in[8];
    const int* lsrc = (const int*)d_in[9];
    const int* ldst = (const int*)d_in[10];
    const int* tgt  = (const int*)d_in[11];
    const int* gids = (const int*)d_in[12];
    float* out = (float*)d_out;

    static cudaStream_t s1 = nullptr;
    static cudaEvent_t ev[12];
    if (!s1) {
        cudaStreamCreateWithFlags(&s1, cudaStreamNonBlocking);
        for (int i = 0; i < 12; i++)
            cudaEventCreateWithFlags(&ev[i], cudaEventDisableTiming);
        cudaFuncSetAttribute(k_mmw<0>, cudaFuncAttributeMaxDynamicSharedMemorySize, MMW_SMEM);
        cudaFuncSetAttribute(k_mmw<1>, cudaFuncAttributeMaxDynamicSharedMemorySize, MMW_SMEM);
    }

    __half *msgIn_p, *msgH_p, *msgHB_p, *accH_p, *mpH_p, *hb_p;
    __half *WhT_p, *WoT_p, *WiT_p, *WoTop_p;
    cudaGetSymbolAddress((void**)&msgIn_p, g_msgIn);
    cudaGetSymbolAddress((void**)&msgH_p,  g_msgH);
    cudaGetSymbolAddress((void**)&msgHB_p, g_msgHB);
    cudaGetSymbolAddress((void**)&accH_p,  g_accH);
    cudaGetSymbolAddress((void**)&mpH_p,   g_mpH);
    cudaGetSymbolAddress((void**)&hb_p,    g_hbias);
    cudaGetSymbolAddress((void**)&WhT_p,   g_WhT);
    cudaGetSymbolAddress((void**)&WoT_p,   g_WoT);
    cudaGetSymbolAddress((void**)&WiT_p,   g_WiT);
    cudaGetSymbolAddress((void**)&WoTop_p, g_WoTop);
    int *lg_rp, *lg_cur, *lg_csr_p, *nd_rp, *nd_cur, *nd_csr_p, *part_p, *part2_p;
    cudaGetSymbolAddress((void**)&lg_rp,    g_lg_rowptr);
    cudaGetSymbolAddress((void**)&lg_cur,   g_lg_cursor);
    cudaGetSymbolAddress((void**)&lg_csr_p, g_lg_csr);
    cudaGetSymbolAddress((void**)&nd_rp,    g_nd_rowptr);
    cudaGetSymbolAddress((void**)&nd_cur,   g_nd_cursor);
    cudaGetSymbolAddress((void**)&nd_csr_p, g_nd_csr);
    cudaGetSymbolAddress((void**)&part_p,   g_part);
    cudaGetSymbolAddress((void**)&part2_p,  g_part2);

    int evi = 0;

    // weight prep for the K=64 GEMMs must precede BOTH streams' consumers
    k_prep_w2<<<512, 64>>>(W_i, W_o);

    // ==== fork side stream ====
    cudaEventRecord(ev[evi], 0);
    cudaStreamWaitEvent(s1, ev[evi], 0);
    evi++;

    // ---- side stream: CSR builds + weight prep + hbias + out/counts init ----
    k_zeroi<<<1172, 256, 0, s1>>>(lg_cur, N_EDGES_C);
    k_hist<<<2344, 256, 0, s1>>>(ldst, lg_cur, N_LG_C);
    k_scan1<<<293, 256, 0, s1>>>(lg_cur, lg_rp, N_EDGES_C, part_p);
    k_scan1<<<1, 256, 0, s1>>>(part_p, part2_p, 293, nullptr);
    k_scan3<<<1172, 256, 0, s1>>>(lg_rp, lg_cur, part2_p, N_EDGES_C, N_LG_C);
    k_fill<<<2344, 256, 0, s1>>>(lsrc, ldst, lg_cur, lg_csr_p, N_LG_C);
    k_zeroi<<<586, 256, 0, s1>>>(nd_cur, N_NODES_C);
    k_hist<<<1172, 256, 0, s1>>>(edst, nd_cur, N_EDGES_C);
    k_scan1<<<147, 256, 0, s1>>>(nd_cur, nd_rp, N_NODES_C, part_p);
    k_scan1<<<1, 256, 0, s1>>>(part_p, part2_p, 147, nullptr);
    k_scan3<<<586, 256, 0, s1>>>(nd_rp, nd_cur, part2_p, N_NODES_C, N_EDGES_C);
    k_fill_id<<<1172, 256, 0, s1>>>(edst, nd_cur, nd_csr_p, N_EDGES_C);
    k_prep_w<<<512, 256, 0, s1>>>(W_h, W_o);
    k_gmm<1><<<1172, 512, 0, s1>>>(node_x, nullptr, nullptr, WoTop_p, b_o, hb_p, N_NODES_C);
    k_zero_out<<<512, 256, 0, s1>>>(out);
    k_counts<<<586, 256, 0, s1>>>(gids);

    // ---- main stream: alpha + msg_input ----
    k_zero_alpha<<<37500, 256>>>();
    k_tree_scatter<<<15000, 256>>>(tree, tgt);
    k_alpha_cvt<<<37500, 256>>>();
    k_gmm<0><<<2344, 512>>>(node_x, bond_x, esrc, WiT_p, nullptr, msgIn_p, N_EDGES_C);

    // ==== join ====
    cudaEventRecord(ev[evi], s1);
    cudaStreamWaitEvent(0, ev[evi], 0);
    evi++;

    // ==== BP iterations: G0 -> [M0 || G1] -> M1 ====
    const __half* srcb[3] = { msgIn_p, msgH_p, msgHB_p };
    __half*       dstb[3] = { msgH_p, msgHB_p, msgH_p };
    const int E1 = N_EDGES_C - E_SPLIT;
    for (int it = 0; it < 3; it++) {
        if (it == 0) k_lg_gather<true><<<E_SPLIT / 4, 256>>>(esrc, srcb[it], 0, E_SPLIT);
        else         k_lg_gather<false><<<E_SPLIT / 4, 256>>>(esrc, srcb[it], 0, E_SPLIT);
        cudaEventRecord(ev[evi], 0);
        cudaStreamWaitEvent(s1, ev[evi], 0);
        evi++;
        if (it == 0) k_lg_gather<true><<<(E1 + 3) / 4, 256, 0, s1>>>(esrc, srcb[it], E_SPLIT, E1);
        else         k_lg_gather<false><<<(E1 + 3) / 4, 256, 0, s1>>>(esrc, srcb[it], E_SPLIT, E1);
        k_mmw<0><<<E_SPLIT / 128, 512, MMW_SMEM>>>(accH_p, msgIn_p, WhT_p, dstb[it],
                                                   nullptr, nullptr, 0, N_EDGES_C);
        k_mmw<0><<<(E1 + 127) / 128, 512, MMW_SMEM, s1>>>(accH_p, msgIn_p, WhT_p, dstb[it],
                                                          nullptr, nullptr, E_SPLIT, N_EDGES_C);
        cudaEventRecord(ev[evi], s1);
        cudaStreamWaitEvent(0, ev[evi], 0);
        evi++;
    }

    // ==== readout: NG0 -> [MM0 || NG1] -> MM1 ====
    const int V1 = N_NODES_C - V_SPLIT;
    k_node_gather<<<V_SPLIT / 4, 256>>>(msgH_p, 0, V_SPLIT);
    cudaEventRecord(ev[evi], 0);
    cudaStreamWaitEvent(s1, ev[evi], 0);
    evi++;
    k_node_gather<<<(V1 + 3) / 4, 256, 0, s1>>>(msgH_p, V_SPLIT, V1);
    k_mmw<1><<<V_SPLIT / 128, 512, MMW_SMEM>>>(mpH_p, hb_p, WoT_p, nullptr,
                                               gids, out, 0, N_NODES_C);
    k_mmw<1><<<(V1 + 127) / 128, 512, MMW_SMEM, s1>>>(mpH_p, hb_p, WoT_p, nullptr,
                                                      gids, out, V_SPLIT, N_NODES_C);
    cudaEventRecord(ev[evi], s1);
    cudaStreamWaitEvent(0, ev[evi], 0);
    evi++;

    k_div<<<512, 256>>>(out);
}

// round 16
// speedup vs baseline: 1.6550x; 1.0052x over previous
#include <cuda_runtime.h>
#include <cuda_fp16.h>
#include <cstdint>

#define N_NODES_C 150000
#define N_EDGES_C 300000
#define N_LG_C    600000
#define HID       256
#define NGRAPH    2048
#define AFD       35
#define BFD       5
#define KIN       40

// ---------------- scratch (static device globals; no allocation) ----------------
__device__ __half g_msgIn[(size_t)N_EDGES_C * HID];
__device__ __half g_msgH [(size_t)N_EDGES_C * HID];
__device__ __half g_msgHB[(size_t)N_EDGES_C * HID];
__device__ float  g_alpha [(size_t)N_NODES_C * HID];
__device__ __half g_alphaH[(size_t)N_NODES_C * HID];
__device__ __half g_hbias[(size_t)N_NODES_C * HID];
__device__ __half g_WhT[HID * HID];
__device__ __half g_WoT[HID * HID];
__device__ __half g_WiT  [HID * 64];
__device__ __half g_WoTop[HID * 64];
__device__ float  g_counts[NGRAPH];

// CSR structures
__device__ int g_lg_rowptr[N_EDGES_C + 1];
__device__ int g_lg_cursor[N_EDGES_C];
__device__ int g_lg_csr[N_LG_C];
__device__ int g_nd_rowptr[N_NODES_C + 1];
__device__ int g_nd_cursor[N_NODES_C];
__device__ int g_nd_csr[N_EDGES_C];
__device__ int g_part [1024];
__device__ int g_part2[1024];

// ---------------- PTX helpers (portable: sm_80/sm_90 level only) ----------------
__device__ __forceinline__ uint32_t smem_u32(const void* p) {
    uint32_t a;
    asm("{ .reg .u64 t; cvta.to.shared.u64 t, %1; cvt.u32.u64 %0, t; }" : "=r"(a) : "l"(p));
    return a;
}
__device__ __forceinline__ void red4(float* p, float a, float b, float c, float d) {
    asm volatile("red.global.add.v4.f32 [%0], {%1, %2, %3, %4};"
                 :: "l"(p), "f"(a), "f"(b), "f"(c), "f"(d) : "memory");
}
__device__ __forceinline__ void red2(float* p, float a, float b) {
    asm volatile("red.global.add.v2.f32 [%0], {%1, %2};"
                 :: "l"(p), "f"(a), "f"(b) : "memory");
}
__device__ __forceinline__ void ldsm4(uint32_t* r, uint32_t addr) {
    asm volatile("ldmatrix.sync.aligned.m8n8.x4.shared.b16 {%0,%1,%2,%3}, [%4];"
                 : "=r"(r[0]), "=r"(r[1]), "=r"(r[2]), "=r"(r[3]) : "r"(addr));
}
__device__ __forceinline__ void mma_f16(float* d, const uint32_t* a, const uint32_t* b) {
    asm volatile(
        "mma.sync.aligned.m16n8k16.row.col.f32.f16.f16.f32 "
        "{%0,%1,%2,%3}, {%4,%5,%6,%7}, {%8,%9}, {%0,%1,%2,%3};"
        : "+f"(d[0]), "+f"(d[1]), "+f"(d[2]), "+f"(d[3])
        : "r"(a[0]), "r"(a[1]), "r"(a[2]), "r"(a[3]), "r"(b[0]), "r"(b[1]));
}
__device__ __forceinline__ uint32_t h2u(__half2 h) { return *reinterpret_cast<uint32_t*>(&h); }
__device__ __forceinline__ void cp16(uint32_t dst, const void* src) {
    asm volatile("cp.async.cg.shared.global [%0], [%1], 16;" :: "r"(dst), "l"(src));
}
#define CP_COMMIT() asm volatile("cp.async.commit_group;" ::: "memory")
#define CP_WAIT0()  asm volatile("cp.async.wait_group 0;" ::: "memory")

// ---------------- CSR build kernels ----------------
__global__ void k_zeroi(int* __restrict__ p, int n) {
    int i = blockIdx.x * 256 + threadIdx.x;
    if (i < n) p[i] = 0;
}
__global__ void k_hist(const int* __restrict__ dst, int* __restrict__ cnt, int n) {
    int i = blockIdx.x * 256 + threadIdx.x;
    if (i < n) atomicAdd(&cnt[dst[i]], 1);
}
__global__ void k_scan1(const int* __restrict__ cnt, int* __restrict__ ex, int n,
                        int* __restrict__ part) {
    __shared__ int sh[256];
    int base = blockIdx.x * 1024;
    int t = threadIdx.x;
    int v[4], s = 0;
#pragma unroll
    for (int j = 0; j < 4; j++) {
        int i = base + t * 4 + j;
        v[j] = (i < n) ? cnt[i] : 0;
        s += v[j];
    }
    sh[t] = s;
    __syncthreads();
    for (int off = 1; off < 256; off <<= 1) {
        int x = (t >= off) ? sh[t - off] : 0;
        __syncthreads();
        sh[t] += x;
        __syncthreads();
    }
    int run = (t > 0) ? sh[t - 1] : 0;
    if (part && t == 255) part[blockIdx.x] = sh[255];
#pragma unroll
    for (int j = 0; j < 4; j++) {
        int i = base + t * 4 + j;
        if (i < n) ex[i] = run;
        run += v[j];
    }
}
__global__ void k_scan3(int* __restrict__ ex, int* __restrict__ cursor,
                        const int* __restrict__ part2, int n, int ntot) {
    int i = blockIdx.x * 256 + threadIdx.x;
    if (i < n) {
        int v = ex[i] + part2[i >> 10];
        ex[i] = v;
        cursor[i] = v;
    }
    if (i == 0) ex[n] = ntot;
}
__global__ void k_fill(const int* __restrict__ src, const int* __restrict__ dst,
                       int* __restrict__ cursor, int* __restrict__ csr, int n) {
    int i = blockIdx.x * 256 + threadIdx.x;
    if (i < n) {
        int pos = atomicAdd(&cursor[dst[i]], 1);
        csr[pos] = src[i];
    }
}
__global__ void k_fill_id(const int* __restrict__ dst, int* __restrict__ cursor,
                          int* __restrict__ csr, int n) {
    int i = blockIdx.x * 256 + threadIdx.x;
    if (i < n) {
        int pos = atomicAdd(&cursor[dst[i]], 1);
        csr[pos] = i;
    }
}

// ---------------- utility kernels ----------------
__global__ void k_zero_alpha() {
    int i = blockIdx.x * 256 + threadIdx.x;
    ((float4*)g_alpha)[i] = make_float4(0.f, 0.f, 0.f, 0.f);
}
__global__ void k_zero_out(float* __restrict__ out) {
    int i = blockIdx.x * 256 + threadIdx.x;
    ((float4*)out)[i] = make_float4(0.f, 0.f, 0.f, 0.f);
    if (i < NGRAPH) g_counts[i] = 0.f;
}
__global__ void k_counts(const int* __restrict__ gids) {
    int v = blockIdx.x * 256 + threadIdx.x;
    if (v < N_NODES_C) atomicAdd(&g_counts[gids[v]], 1.0f);
}
__global__ void k_div(float* __restrict__ out) {
    int i = blockIdx.x * 256 + threadIdx.x;
    int g = i >> 6;
    float c = fmaxf(g_counts[g], 1.0f);
    float4 v = ((float4*)out)[i];
    v.x /= c; v.y /= c; v.z /= c; v.w /= c;
    ((float4*)out)[i] = v;
}
__global__ void k_prep_w(const float* __restrict__ Wh, const float* __restrict__ Wo) {
    int n = blockIdx.x & 255;
    int k = threadIdx.x;
    if (blockIdx.x < 256) g_WhT[n * 256 + k] = __float2half_rn(Wh[k * 256 + n]);
    else                  g_WoT[n * 256 + k] = __float2half_rn(Wo[(AFD + k) * 256 + n]);
}
__global__ void k_prep_w2(const float* __restrict__ Wi, const float* __restrict__ Wo) {
    int n = blockIdx.x & 255;
    int k = threadIdx.x;
    if (blockIdx.x < 256)
        g_WiT[n * 64 + k]   = __float2half_rn((k < KIN) ? Wi[k * 256 + n] : 0.f);
    else
        g_WoTop[n * 64 + k] = __float2half_rn((k < AFD) ? Wo[k * 256 + n] : 0.f);
}
__global__ void k_tree_scatter(const float* __restrict__ tree, const int* __restrict__ tgt) {
    int i = blockIdx.x * 256 + threadIdx.x;
    int t = i >> 6, q = i & 63;
    float4 v = ((const float4*)tree)[(size_t)t * 64 + q];
    red4(g_alpha + (size_t)tgt[t] * HID + q * 4, v.x, v.y, v.z, v.w);
}
__device__ __forceinline__ uint2 f4toh4(float4 v) {
    __half2 h01 = __floats2half2_rn(v.x, v.y);
    __half2 h23 = __floats2half2_rn(v.z, v.w);
    return make_uint2(h2u(h01), h2u(h23));
}
__global__ void k_alpha_cvt() {
    int i = blockIdx.x * 256 + threadIdx.x;
    float4 v = ((const float4*)g_alpha)[i];
    ((uint2*)g_alphaH)[i] = f4toh4(v);
}
// add 8 fp16 (as uint4) into fp32 acc, optional relu on the source
__device__ __forceinline__ void addh8(float* acc, uint4 w, bool dorelu) {
    uint32_t u[4] = { w.x, w.y, w.z, w.w };
#pragma unroll
    for (int i = 0; i < 4; i++) {
        __half2 h = *reinterpret_cast<__half2*>(&u[i]);
        float2 f = __half22float2(h);
        if (dorelu) { f.x = fmaxf(f.x, 0.f); f.y = fmaxf(f.y, 0.f); }
        acc[i * 2 + 0] += f.x;
        acc[i * 2 + 1] += f.y;
    }
}

// ---------------- single-chunk gather-GEMM (K=64 padded) ----------------
// MODE 0: msgIn[e] = [node_x[esrc[e]]; bond_x[e]; 0pad] @ WiT^T        (fp16 out)
// MODE 1: hbias[v] = [node_x[v]; 0pad] @ WoTop^T + b_o                 (fp16 out)
template<int MODE>
__global__ __launch_bounds__(512)
void k_gmm(const float* __restrict__ nx, const float* __restrict__ bx,
           const int* __restrict__ esrc, const __half* __restrict__ BT,
           const float* __restrict__ b_o, __half* __restrict__ dsth, int M) {
    __shared__ char sm[49152];
    __shared__ int sIdx[128];
    const int tid  = threadIdx.x;
    const int lane = tid & 31;
    const int wid  = tid >> 5;
    const int wm   = wid >> 2;
    const int wn   = wid & 3;
    const int m0   = blockIdx.x * 128;
    const uint32_t sbase = smem_u32(sm);

#pragma unroll
    for (int j = 0; j < 4; j++) {
        int idx = tid + j * 512;
        int row = idx >> 3, seg = idx & 7;
        uint32_t off = (uint32_t)(row * 128 + seg * 16);
        uint32_t sw = off ^ ((off >> 3) & 0x70);
        cp16(sbase + 16384u + sw, BT + (size_t)row * 64 + seg * 8);
    }
    CP_COMMIT();

    if (MODE == 0 && tid < 128) {
        int ge = m0 + tid;
        sIdx[tid] = (ge < M) ? esrc[ge] : 0;
    }
    if (MODE == 0) __syncthreads();

    for (int idx = tid; idx < 8192; idx += 512) {
        int row = idx >> 6, k = idx & 63;
        int ge = m0 + row;
        float v = 0.f;
        if (ge < M) {
            if (MODE == 0) {
                if (k < AFD)      v = nx[(size_t)sIdx[row] * AFD + k];
                else if (k < KIN) v = bx[(size_t)ge * BFD + (k - AFD)];
            } else {
                if (k < AFD)      v = nx[(size_t)ge * AFD + k];
            }
        }
        uint32_t off = (uint32_t)(row * 128 + k * 2);
        uint32_t sw = off ^ ((off >> 3) & 0x70);
        *(__half*)(sm + sw) = __float2half_rn(v);
    }
    CP_WAIT0();
    __syncthreads();

    float d[2][8][4];
#pragma unroll
    for (int i = 0; i < 2; i++)
#pragma unroll
        for (int j = 0; j < 8; j++)
#pragma unroll
            for (int q = 0; q < 4; q++) d[i][j][q] = 0.f;

    {
        uint32_t baseA  = sbase;
        uint32_t baseBh = sbase + 16384;
        const int r = lane & 7, q = lane >> 3;
        const int bro = ((q >> 1) << 3) + r;
        const int bkp = (q & 1) << 4;
#pragma unroll
        for (int s = 0; s < 4; s++) {
            uint32_t ah[2][4];
#pragma unroll
            for (int mt = 0; mt < 2; mt++) {
                uint32_t mrow = (uint32_t)(wm * 32 + mt * 16 + (q & 1) * 8 + r);
                uint32_t off = mrow * 128 + (q >> 1) * 16 + s * 32;
                uint32_t sw = off ^ ((off >> 3) & 0x70);
                ldsm4(ah[mt], baseA + sw);
            }
#pragma unroll
            for (int h = 0; h < 2; h++) {
                uint32_t bh4[2][4];
#pragma unroll
                for (int ntp = 0; ntp < 2; ntp++) {
                    uint32_t nrow = (uint32_t)(wn * 64 + h * 32 + ntp * 16 + bro);
                    uint32_t off = nrow * 128 + bkp + s * 32;
                    uint32_t sw = off ^ ((off >> 3) & 0x70);
                    ldsm4(bh4[ntp], baseBh + sw);
                }
#pragma unroll
                for (int mt = 0; mt < 2; mt++)
#pragma unroll
                    for (int nt = 0; nt < 4; nt++)
                        mma_f16(d[mt][h * 4 + nt], ah[mt], &bh4[nt >> 1][(nt & 1) * 2]);
            }
        }
    }

#pragma unroll
    for (int mt = 0; mt < 2; mt++) {
#pragma unroll
        for (int n = 0; n < 8; n++) {
            int row = m0 + wm * 32 + mt * 16 + (lane >> 2);
            int col = wn * 64 + n * 8 + (lane & 3) * 2;
#pragma unroll
            for (int h2 = 0; h2 < 2; h2++) {
                int gr = row + h2 * 8;
                if (gr >= M) continue;
                float ox = d[mt][n][h2 * 2 + 0];
                float oy = d[mt][n][h2 * 2 + 1];
                if (MODE == 1) {
                    float2 bo = *(const float2*)(b_o + col);
                    ox += bo.x; oy += bo.y;
                }
                __half2 hv = __floats2half2_rn(ox, oy);
                *(uint32_t*)(dsth + (size_t)gr * 256 + col) = h2u(hv);
            }
        }
    }
}

// ---------------- fused gather + GEMM ----------------
// A[row] = alphaH[ridx(row)] + sum_{csr} relu?(srch[s])    (full-row gather to SMEM)
// D = A @ BT^T  (K=256 in 4 chunks from SMEM)
// MODE 0: dsth = relu(bias + D) fp16      MODE 1: out[gids[row]] += relu(bias + D)
// SMEM: A 4x16KB subtiles (64KB) | B double-buffer 2x32KB = 128KB dynamic.
#define GMF_SMEM 131072

template<int MODE, bool FIRST>
__global__ __launch_bounds__(512, 1)
void k_gmf(const int* __restrict__ ridx, const int* __restrict__ rowptr,
           const int* __restrict__ csr, const __half* __restrict__ srch,
           const __half* __restrict__ bias, const __half* __restrict__ BT,
           __half* __restrict__ dsth, const int* __restrict__ gids,
           float* __restrict__ out, int M) {
    extern __shared__ char sm[];
    __shared__ int sIdx[128];
    __shared__ int sPtr[129];
    const int tid  = threadIdx.x;
    const int lane = tid & 31;
    const int wid  = tid >> 5;
    const int wm   = wid >> 2;
    const int wn   = wid & 3;
    const int m0   = blockIdx.x * 128;
    const uint32_t sbase = smem_u32(sm);

    auto cpB = [&](int cc, int b) {
        uint32_t base = sbase + 65536u + b * 32768u;
#pragma unroll
        for (int j = 0; j < 4; j++) {
            int idx = tid + j * 512;
            int row = idx >> 3, seg = idx & 7;
            uint32_t off = (uint32_t)(row * 128 + seg * 16);
            uint32_t sw = off ^ ((off >> 3) & 0x70);
            cp16(base + sw, BT + (size_t)row * 256 + cc * 64 + seg * 8);
        }
    };

    // B chunk 0 in flight under the gather
    cpB(0, 0);
    CP_COMMIT();

    if (tid < 128) {
        int gr = m0 + tid;
        sIdx[tid] = (MODE == 0) ? ((gr < M) ? __ldg(&ridx[gr]) : 0) : gr;
    }
    if (tid <= 128) {
        int gr = m0 + tid;
        sPtr[tid] = __ldg(&rowptr[gr < M ? gr : M]);
    }
    __syncthreads();

    // gather A: 2 passes x 64 rows, 8 threads/row, 32 halves (64B) per thread
#pragma unroll
    for (int pass = 0; pass < 2; pass++) {
        int r  = pass * 64 + (tid >> 3);
        int sg = tid & 7;
        int gr = m0 + r;
        float acc[32];
#pragma unroll
        for (int u = 0; u < 32; u++) acc[u] = 0.f;
        if (gr < M) {
            size_t cb = (size_t)sg * 32;
            const uint4* ap = (const uint4*)(g_alphaH + (size_t)sIdx[r] * 256 + cb);
#pragma unroll
            for (int u = 0; u < 4; u++) addh8(acc + u * 8, __ldg(ap + u), false);
            int beg = sPtr[r], end = sPtr[r + 1];
            for (int j = beg; j < end; j++) {
                int s = __ldg(&csr[j]);
                const uint4* sp = (const uint4*)(srch + (size_t)s * 256 + cb);
#pragma unroll
                for (int u = 0; u < 4; u++) addh8(acc + u * 8, __ldg(sp + u), FIRST);
            }
        }
        // store to A subtile (chunk = sg>>1), swizzled 16B units
        char* subt = sm + (sg >> 1) * 16384;
        uint32_t rowoff = (uint32_t)r * 128 + (sg & 1) * 64;
#pragma unroll
        for (int u = 0; u < 4; u++) {
            uint32_t off = rowoff + u * 16;
            uint32_t sw = off ^ ((off >> 3) & 0x70);
            uint4 pk;
            pk.x = h2u(__floats2half2_rn(acc[u * 8 + 0], acc[u * 8 + 1]));
            pk.y = h2u(__floats2half2_rn(acc[u * 8 + 2], acc[u * 8 + 3]));
            pk.z = h2u(__floats2half2_rn(acc[u * 8 + 4], acc[u * 8 + 5]));
            pk.w = h2u(__floats2half2_rn(acc[u * 8 + 6], acc[u * 8 + 7]));
            *(uint4*)(subt + sw) = pk;
        }
    }
    CP_WAIT0();
    __syncthreads();

    float d[2][8][4];
#pragma unroll
    for (int i = 0; i < 2; i++)
#pragma unroll
        for (int j = 0; j < 8; j++)
#pragma unroll
            for (int q = 0; q < 4; q++) d[i][j][q] = 0.f;

    const int r = lane & 7, q = lane >> 3;
    const int bro = ((q >> 1) << 3) + r;
    const int bkp = (q & 1) << 4;
#pragma unroll
    for (int c = 0; c < 4; c++) {
        if (c < 3) { cpB(c + 1, (c + 1) & 1); CP_COMMIT(); }
        uint32_t baseA  = sbase + c * 16384u;
        uint32_t baseBh = sbase + 65536u + (c & 1) * 32768u;
#pragma unroll
        for (int s = 0; s < 4; s++) {
            uint32_t ah[2][4];
#pragma unroll
            for (int mt = 0; mt < 2; mt++) {
                uint32_t mrow = (uint32_t)(wm * 32 + mt * 16 + (q & 1) * 8 + r);
                uint32_t off = mrow * 128 + (q >> 1) * 16 + s * 32;
                uint32_t sw = off ^ ((off >> 3) & 0x70);
                ldsm4(ah[mt], baseA + sw);
            }
#pragma unroll
            for (int h = 0; h < 2; h++) {
                uint32_t bh4[2][4];
#pragma unroll
                for (int ntp = 0; ntp < 2; ntp++) {
                    uint32_t nrow = (uint32_t)(wn * 64 + h * 32 + ntp * 16 + bro);
                    uint32_t off = nrow * 128 + bkp + s * 32;
                    uint32_t sw = off ^ ((off >> 3) & 0x70);
                    ldsm4(bh4[ntp], baseBh + sw);
                }
#pragma unroll
                for (int mt = 0; mt < 2; mt++)
#pragma unroll
                    for (int nt = 0; nt < 4; nt++)
                        mma_f16(d[mt][h * 4 + nt], ah[mt], &bh4[nt >> 1][(nt & 1) * 2]);
            }
        }
        if (c < 3) CP_WAIT0();
        __syncthreads();
    }

#pragma unroll
    for (int mt = 0; mt < 2; mt++) {
#pragma unroll
        for (int n = 0; n < 8; n++) {
            int row = m0 + wm * 32 + mt * 16 + (lane >> 2);
            int col = wn * 64 + n * 8 + (lane & 3) * 2;
#pragma unroll
            for (int h2 = 0; h2 < 2; h2++) {
                int gr = row + h2 * 8;
                if (gr >= M) continue;
                size_t gb = (size_t)gr * 256 + col;
                uint32_t bu = *(const uint32_t*)(bias + gb);
                __half2 bh = *reinterpret_cast<__half2*>(&bu);
                float2 bv = __half22float2(bh);
                float ox = fmaxf(bv.x + d[mt][n][h2 * 2 + 0], 0.f);
                float oy = fmaxf(bv.y + d[mt][n][h2 * 2 + 1], 0.f);
                if (MODE == 0) {
                    __half2 hv = __floats2half2_rn(ox, oy);
                    *(uint32_t*)(dsth + gb) = h2u(hv);
                } else {
                    int g = gids[gr];
                    red2(out + (size_t)g * 256 + col, ox, oy);
                }
            }
        }
    }
}

// ---------------- launch ----------------
extern "C" void kernel_launch(void* const* d_in, const int* in_sizes, int n_in,
                              void* d_out, int out_size) {
    (void)in_sizes; (void)n_in; (void)out_size;
    const float* node_x = (const float*)d_in[0];
    const float* bond_x = (const float*)d_in[1];
    const float* tree   = (const float*)d_in[2];
    const float* W_i    = (const float*)d_in[3];
    const float* W_h    = (const float*)d_in[4];
    const float* W_o    = (const float*)d_in[5];
    const float* b_o    = (const float*)d_in[6];
    const int* esrc = (const int*)d_in[7];
    const int* edst = (const int*)d_in[8];
    const int* lsrc = (const int*)d_in[9];
    const int* ldst = (const int*)d_in[10];
    const int* tgt  = (const int*)d_in[11];
    const int* gids = (const int*)d_in[12];
    float* out = (float*)d_out;

    static cudaStream_t s1 = nullptr;
    static cudaEvent_t ev[4];
    if (!s1) {
        cudaStreamCreateWithFlags(&s1, cudaStreamNonBlocking);
        for (int i = 0; i < 4; i++)
            cudaEventCreateWithFlags(&ev[i], cudaEventDisableTiming);
        cudaFuncSetAttribute(k_gmf<0, true>,  cudaFuncAttributeMaxDynamicSharedMemorySize, GMF_SMEM);
        cudaFuncSetAttribute(k_gmf<0, false>, cudaFuncAttributeMaxDynamicSharedMemorySize, GMF_SMEM);
        cudaFuncSetAttribute(k_gmf<1, false>, cudaFuncAttributeMaxDynamicSharedMemorySize, GMF_SMEM);
    }

    __half *msgIn_p, *msgH_p, *msgHB_p, *hb_p;
    __half *WhT_p, *WoT_p, *WiT_p, *WoTop_p;
    cudaGetSymbolAddress((void**)&msgIn_p, g_msgIn);
    cudaGetSymbolAddress((void**)&msgH_p,  g_msgH);
    cudaGetSymbolAddress((void**)&msgHB_p, g_msgHB);
    cudaGetSymbolAddress((void**)&hb_p,    g_hbias);
    cudaGetSymbolAddress((void**)&WhT_p,   g_WhT);
    cudaGetSymbolAddress((void**)&WoT_p,   g_WoT);
    cudaGetSymbolAddress((void**)&WiT_p,   g_WiT);
    cudaGetSymbolAddress((void**)&WoTop_p, g_WoTop);
    int *lg_rp, *lg_cur, *lg_csr_p, *nd_rp, *nd_cur, *nd_csr_p, *part_p, *part2_p;
    cudaGetSymbolAddress((void**)&lg_rp,    g_lg_rowptr);
    cudaGetSymbolAddress((void**)&lg_cur,   g_lg_cursor);
    cudaGetSymbolAddress((void**)&lg_csr_p, g_lg_csr);
    cudaGetSymbolAddress((void**)&nd_rp,    g_nd_rowptr);
    cudaGetSymbolAddress((void**)&nd_cur,   g_nd_cursor);
    cudaGetSymbolAddress((void**)&nd_csr_p, g_nd_csr);
    cudaGetSymbolAddress((void**)&part_p,   g_part);
    cudaGetSymbolAddress((void**)&part2_p,  g_part2);

    // weight prep for the K=64 GEMMs precedes both streams' consumers
    k_prep_w2<<<512, 64>>>(W_i, W_o);

    // ==== fork side stream ====
    cudaEventRecord(ev[0], 0);
    cudaStreamWaitEvent(s1, ev[0], 0);

    // ---- side stream: CSR builds + weight prep + hbias + out/counts init ----
    k_zeroi<<<1172, 256, 0, s1>>>(lg_cur, N_EDGES_C);
    k_hist<<<2344, 256, 0, s1>>>(ldst, lg_cur, N_LG_C);
    k_scan1<<<293, 256, 0, s1>>>(lg_cur, lg_rp, N_EDGES_C, part_p);
    k_scan1<<<1, 256, 0, s1>>>(part_p, part2_p, 293, nullptr);
    k_scan3<<<1172, 256, 0, s1>>>(lg_rp, lg_cur, part2_p, N_EDGES_C, N_LG_C);
    k_fill<<<2344, 256, 0, s1>>>(lsrc, ldst, lg_cur, lg_csr_p, N_LG_C);
    k_zeroi<<<586, 256, 0, s1>>>(nd_cur, N_NODES_C);
    k_hist<<<1172, 256, 0, s1>>>(edst, nd_cur, N_EDGES_C);
    k_scan1<<<147, 256, 0, s1>>>(nd_cur, nd_rp, N_NODES_C, part_p);
    k_scan1<<<1, 256, 0, s1>>>(part_p, part2_p, 147, nullptr);
    k_scan3<<<586, 256, 0, s1>>>(nd_rp, nd_cur, part2_p, N_NODES_C, N_EDGES_C);
    k_fill_id<<<1172, 256, 0, s1>>>(edst, nd_cur, nd_csr_p, N_EDGES_C);
    k_prep_w<<<512, 256, 0, s1>>>(W_h, W_o);
    k_gmm<1><<<1172, 512, 0, s1>>>(node_x, nullptr, nullptr, WoTop_p, b_o, hb_p, N_NODES_C);
    k_zero_out<<<512, 256, 0, s1>>>(out);
    k_counts<<<586, 256, 0, s1>>>(gids);

    // ---- main stream: alpha + msg_input ----
    k_zero_alpha<<<37500, 256>>>();
    k_tree_scatter<<<15000, 256>>>(tree, tgt);
    k_alpha_cvt<<<37500, 256>>>();
    k_gmm<0><<<2344, 512>>>(node_x, bond_x, esrc, WiT_p, nullptr, msgIn_p, N_EDGES_C);

    // ==== join ====
    cudaEventRecord(ev[1], s1);
    cudaStreamWaitEvent(0, ev[1], 0);

    // ==== BP iterations (fused gather + GEMM), msg ping-pong ====
    k_gmf<0, true><<<2344, 512, GMF_SMEM>>>(esrc, lg_rp, lg_csr_p, msgIn_p, msgIn_p,
                                            WhT_p, msgH_p, nullptr, nullptr, N_EDGES_C);
    k_gmf<0, false><<<2344, 512, GMF_SMEM>>>(esrc, lg_rp, lg_csr_p, msgH_p, msgIn_p,
                                             WhT_p, msgHB_p, nullptr, nullptr, N_EDGES_C);
    k_gmf<0, false><<<2344, 512, GMF_SMEM>>>(esrc, lg_rp, lg_csr_p, msgHB_p, msgIn_p,
                                             WhT_p, msgH_p, nullptr, nullptr, N_EDGES_C);

    // ==== fused readout ====
    k_gmf<1, false><<<1172, 512, GMF_SMEM>>>(nullptr, nd_rp, nd_csr_p, msgH_p, hb_p,
                                             WoT_p, nullptr, gids, out, N_NODES_C);
    k_div<<<512, 256>>>(out);
}

// round 17
// speedup vs baseline: 1.7392x; 1.0509x over previous
#include <cuda_runtime.h>
#include <cuda_fp16.h>
#include <cstdint>

#define N_NODES_C 150000
#define N_EDGES_C 300000
#define N_LG_C    600000
#define HID       256
#define NGRAPH    2048
#define AFD       35
#define BFD       5
#define KIN       40

// ---------------- scratch (static device globals; no allocation) ----------------
__device__ __half g_msgIn[(size_t)N_EDGES_C * HID];
__device__ __half g_msgH [(size_t)N_EDGES_C * HID];
__device__ __half g_msgHB[(size_t)N_EDGES_C * HID];
__device__ float  g_alpha [(size_t)N_NODES_C * HID];
__device__ __half g_alphaH[(size_t)N_NODES_C * HID];
__device__ __half g_hbias[(size_t)N_NODES_C * HID];
__device__ __half g_WhT[HID * HID];
__device__ __half g_WoT[HID * HID];
__device__ __half g_WiT  [HID * 64];
__device__ __half g_WoTop[HID * 64];
__device__ float  g_counts[NGRAPH];

// CSR structures
__device__ int g_lg_rowptr[N_EDGES_C + 1];
__device__ int g_lg_cursor[N_EDGES_C];
__device__ int g_lg_csr[N_LG_C];
__device__ int g_nd_rowptr[N_NODES_C + 1];
__device__ int g_nd_cursor[N_NODES_C];
__device__ int g_nd_csr[N_EDGES_C];
__device__ int g_part [1024];
__device__ int g_part2[1024];

// ---------------- PTX helpers (portable: sm_80/sm_90 level only) ----------------
__device__ __forceinline__ uint32_t smem_u32(const void* p) {
    uint32_t a;
    asm("{ .reg .u64 t; cvta.to.shared.u64 t, %1; cvt.u32.u64 %0, t; }" : "=r"(a) : "l"(p));
    return a;
}
__device__ __forceinline__ void red4(float* p, float a, float b, float c, float d) {
    asm volatile("red.global.add.v4.f32 [%0], {%1, %2, %3, %4};"
                 :: "l"(p), "f"(a), "f"(b), "f"(c), "f"(d) : "memory");
}
__device__ __forceinline__ void red2(float* p, float a, float b) {
    asm volatile("red.global.add.v2.f32 [%0], {%1, %2};"
                 :: "l"(p), "f"(a), "f"(b) : "memory");
}
__device__ __forceinline__ void ldsm4(uint32_t* r, uint32_t addr) {
    asm volatile("ldmatrix.sync.aligned.m8n8.x4.shared.b16 {%0,%1,%2,%3}, [%4];"
                 : "=r"(r[0]), "=r"(r[1]), "=r"(r[2]), "=r"(r[3]) : "r"(addr));
}
__device__ __forceinline__ void mma_f16(float* d, const uint32_t* a, const uint32_t* b) {
    asm volatile(
        "mma.sync.aligned.m16n8k16.row.col.f32.f16.f16.f32 "
        "{%0,%1,%2,%3}, {%4,%5,%6,%7}, {%8,%9}, {%0,%1,%2,%3};"
        : "+f"(d[0]), "+f"(d[1]), "+f"(d[2]), "+f"(d[3])
        : "r"(a[0]), "r"(a[1]), "r"(a[2]), "r"(a[3]), "r"(b[0]), "r"(b[1]));
}
__device__ __forceinline__ uint32_t h2u(__half2 h) { return *reinterpret_cast<uint32_t*>(&h); }
__device__ __forceinline__ void cp16(uint32_t dst, const void* src) {
    asm volatile("cp.async.cg.shared.global [%0], [%1], 16;" :: "r"(dst), "l"(src));
}
#define CP_COMMIT() asm volatile("cp.async.commit_group;" ::: "memory")
#define CP_WAIT0()  asm volatile("cp.async.wait_group 0;" ::: "memory")

// ---------------- CSR build kernels ----------------
__global__ void k_zeroi(int* __restrict__ p, int n) {
    int i = blockIdx.x * 256 + threadIdx.x;
    if (i < n) p[i] = 0;
}
__global__ void k_hist(const int* __restrict__ dst, int* __restrict__ cnt, int n) {
    int i = blockIdx.x * 256 + threadIdx.x;
    if (i < n) atomicAdd(&cnt[dst[i]], 1);
}
__global__ void k_scan1(const int* __restrict__ cnt, int* __restrict__ ex, int n,
                        int* __restrict__ part) {
    __shared__ int sh[256];
    int base = blockIdx.x * 1024;
    int t = threadIdx.x;
    int v[4], s = 0;
#pragma unroll
    for (int j = 0; j < 4; j++) {
        int i = base + t * 4 + j;
        v[j] = (i < n) ? cnt[i] : 0;
        s += v[j];
    }
    sh[t] = s;
    __syncthreads();
    for (int off = 1; off < 256; off <<= 1) {
        int x = (t >= off) ? sh[t - off] : 0;
        __syncthreads();
        sh[t] += x;
        __syncthreads();
    }
    int run = (t > 0) ? sh[t - 1] : 0;
    if (part && t == 255) part[blockIdx.x] = sh[255];
#pragma unroll
    for (int j = 0; j < 4; j++) {
        int i = base + t * 4 + j;
        if (i < n) ex[i] = run;
        run += v[j];
    }
}
__global__ void k_scan3(int* __restrict__ ex, int* __restrict__ cursor,
                        const int* __restrict__ part2, int n, int ntot) {
    int i = blockIdx.x * 256 + threadIdx.x;
    if (i < n) {
        int v = ex[i] + part2[i >> 10];
        ex[i] = v;
        cursor[i] = v;
    }
    if (i == 0) ex[n] = ntot;
}
__global__ void k_fill(const int* __restrict__ src, const int* __restrict__ dst,
                       int* __restrict__ cursor, int* __restrict__ csr, int n) {
    int i = blockIdx.x * 256 + threadIdx.x;
    if (i < n) {
        int pos = atomicAdd(&cursor[dst[i]], 1);
        csr[pos] = src[i];
    }
}
__global__ void k_fill_id(const int* __restrict__ dst, int* __restrict__ cursor,
                          int* __restrict__ csr, int n) {
    int i = blockIdx.x * 256 + threadIdx.x;
    if (i < n) {
        int pos = atomicAdd(&cursor[dst[i]], 1);
        csr[pos] = i;
    }
}

// ---------------- utility kernels ----------------
__global__ void k_zero_alpha() {
    int i = blockIdx.x * 256 + threadIdx.x;
    ((float4*)g_alpha)[i] = make_float4(0.f, 0.f, 0.f, 0.f);
}
__global__ void k_zero_out(float* __restrict__ out) {
    int i = blockIdx.x * 256 + threadIdx.x;
    ((float4*)out)[i] = make_float4(0.f, 0.f, 0.f, 0.f);
    if (i < NGRAPH) g_counts[i] = 0.f;
}
__global__ void k_counts(const int* __restrict__ gids) {
    int v = blockIdx.x * 256 + threadIdx.x;
    if (v < N_NODES_C) atomicAdd(&g_counts[gids[v]], 1.0f);
}
__global__ void k_div(float* __restrict__ out) {
    int i = blockIdx.x * 256 + threadIdx.x;
    int g = i >> 6;
    float c = fmaxf(g_counts[g], 1.0f);
    float4 v = ((float4*)out)[i];
    v.x /= c; v.y /= c; v.z /= c; v.w /= c;
    ((float4*)out)[i] = v;
}
__global__ void k_prep_w(const float* __restrict__ Wh, const float* __restrict__ Wo) {
    int n = blockIdx.x & 255;
    int k = threadIdx.x;
    if (blockIdx.x < 256) g_WhT[n * 256 + k] = __float2half_rn(Wh[k * 256 + n]);
    else                  g_WoT[n * 256 + k] = __float2half_rn(Wo[(AFD + k) * 256 + n]);
}
__global__ void k_prep_w2(const float* __restrict__ Wi, const float* __restrict__ Wo) {
    int n = blockIdx.x & 255;
    int k = threadIdx.x;
    if (blockIdx.x < 256)
        g_WiT[n * 64 + k]   = __float2half_rn((k < KIN) ? Wi[k * 256 + n] : 0.f);
    else
        g_WoTop[n * 64 + k] = __float2half_rn((k < AFD) ? Wo[k * 256 + n] : 0.f);
}
__global__ void k_tree_scatter(const float* __restrict__ tree, const int* __restrict__ tgt) {
    int i = blockIdx.x * 256 + threadIdx.x;
    int t = i >> 6, q = i & 63;
    float4 v = ((const float4*)tree)[(size_t)t * 64 + q];
    red4(g_alpha + (size_t)tgt[t] * HID + q * 4, v.x, v.y, v.z, v.w);
}
__device__ __forceinline__ uint2 f4toh4(float4 v) {
    __half2 h01 = __floats2half2_rn(v.x, v.y);
    __half2 h23 = __floats2half2_rn(v.z, v.w);
    return make_uint2(h2u(h01), h2u(h23));
}
__global__ void k_alpha_cvt() {
    int i = blockIdx.x * 256 + threadIdx.x;
    float4 v = ((const float4*)g_alpha)[i];
    ((uint2*)g_alphaH)[i] = f4toh4(v);
}
// add 8 fp16 (as uint4) into fp32 acc, optional relu on the source
__device__ __forceinline__ void addh8(float* acc, uint4 w, bool dorelu) {
    uint32_t u[4] = { w.x, w.y, w.z, w.w };
#pragma unroll
    for (int i = 0; i < 4; i++) {
        __half2 h = *reinterpret_cast<__half2*>(&u[i]);
        float2 f = __half22float2(h);
        if (dorelu) { f.x = fmaxf(f.x, 0.f); f.y = fmaxf(f.y, 0.f); }
        acc[i * 2 + 0] += f.x;
        acc[i * 2 + 1] += f.y;
    }
}

// ---------------- single-chunk gather-GEMM (K=64 padded) ----------------
template<int MODE>
__global__ __launch_bounds__(512)
void k_gmm(const float* __restrict__ nx, const float* __restrict__ bx,
           const int* __restrict__ esrc, const __half* __restrict__ BT,
           const float* __restrict__ b_o, __half* __restrict__ dsth, int M) {
    __shared__ char sm[49152];
    __shared__ int sIdx[128];
    const int tid  = threadIdx.x;
    const int lane = tid & 31;
    const int wid  = tid >> 5;
    const int wm   = wid >> 2;
    const int wn   = wid & 3;
    const int m0   = blockIdx.x * 128;
    const uint32_t sbase = smem_u32(sm);

#pragma unroll
    for (int j = 0; j < 4; j++) {
        int idx = tid + j * 512;
        int row = idx >> 3, seg = idx & 7;
        uint32_t off = (uint32_t)(row * 128 + seg * 16);
        uint32_t sw = off ^ ((off >> 3) & 0x70);
        cp16(sbase + 16384u + sw, BT + (size_t)row * 64 + seg * 8);
    }
    CP_COMMIT();

    if (MODE == 0 && tid < 128) {
        int ge = m0 + tid;
        sIdx[tid] = (ge < M) ? esrc[ge] : 0;
    }
    if (MODE == 0) __syncthreads();

    for (int idx = tid; idx < 8192; idx += 512) {
        int row = idx >> 6, k = idx & 63;
        int ge = m0 + row;
        float v = 0.f;
        if (ge < M) {
            if (MODE == 0) {
                if (k < AFD)      v = nx[(size_t)sIdx[row] * AFD + k];
                else if (k < KIN) v = bx[(size_t)ge * BFD + (k - AFD)];
            } else {
                if (k < AFD)      v = nx[(size_t)ge * AFD + k];
            }
        }
        uint32_t off = (uint32_t)(row * 128 + k * 2);
        uint32_t sw = off ^ ((off >> 3) & 0x70);
        *(__half*)(sm + sw) = __float2half_rn(v);
    }
    CP_WAIT0();
    __syncthreads();

    float d[2][8][4];
#pragma unroll
    for (int i = 0; i < 2; i++)
#pragma unroll
        for (int j = 0; j < 8; j++)
#pragma unroll
            for (int q = 0; q < 4; q++) d[i][j][q] = 0.f;

    {
        uint32_t baseA  = sbase;
        uint32_t baseBh = sbase + 16384;
        const int r = lane & 7, q = lane >> 3;
        const int bro = ((q >> 1) << 3) + r;
        const int bkp = (q & 1) << 4;
#pragma unroll
        for (int s = 0; s < 4; s++) {
            uint32_t ah[2][4];
#pragma unroll
            for (int mt = 0; mt < 2; mt++) {
                uint32_t mrow = (uint32_t)(wm * 32 + mt * 16 + (q & 1) * 8 + r);
                uint32_t off = mrow * 128 + (q >> 1) * 16 + s * 32;
                uint32_t sw = off ^ ((off >> 3) & 0x70);
                ldsm4(ah[mt], baseA + sw);
            }
#pragma unroll
            for (int h = 0; h < 2; h++) {
                uint32_t bh4[2][4];
#pragma unroll
                for (int ntp = 0; ntp < 2; ntp++) {
                    uint32_t nrow = (uint32_t)(wn * 64 + h * 32 + ntp * 16 + bro);
                    uint32_t off = nrow * 128 + bkp + s * 32;
                    uint32_t sw = off ^ ((off >> 3) & 0x70);
                    ldsm4(bh4[ntp], baseBh + sw);
                }
#pragma unroll
                for (int mt = 0; mt < 2; mt++)
#pragma unroll
                    for (int nt = 0; nt < 4; nt++)
                        mma_f16(d[mt][h * 4 + nt], ah[mt], &bh4[nt >> 1][(nt & 1) * 2]);
            }
        }
    }

#pragma unroll
    for (int mt = 0; mt < 2; mt++) {
#pragma unroll
        for (int n = 0; n < 8; n++) {
            int row = m0 + wm * 32 + mt * 16 + (lane >> 2);
            int col = wn * 64 + n * 8 + (lane & 3) * 2;
#pragma unroll
            for (int h2 = 0; h2 < 2; h2++) {
                int gr = row + h2 * 8;
                if (gr >= M) continue;
                float ox = d[mt][n][h2 * 2 + 0];
                float oy = d[mt][n][h2 * 2 + 1];
                if (MODE == 1) {
                    float2 bo = *(const float2*)(b_o + col);
                    ox += bo.x; oy += bo.y;
                }
                __half2 hv = __floats2half2_rn(ox, oy);
                *(uint32_t*)(dsth + (size_t)gr * 256 + col) = h2u(hv);
            }
        }
    }
}

// ---------------- fused gather + GEMM, 64-row tile, 2 CTAs/SM ----------------
// A[row] = alphaH[ridx(row)] + sum_{csr} relu?(srch[s])   (full-row gather to SMEM)
// D = A @ BT^T  (K=256 in 4 chunks)
// MODE 0: dsth = relu(bias + D) fp16      MODE 1: out[gids[row]] += relu(bias + D)
// SMEM: A 4x8KB subtiles (32KB) | B double-buffer 2x32KB = 96KB dynamic.
#define GMF_SMEM 98304

template<int MODE, bool FIRST>
__global__ __launch_bounds__(256, 2)
void k_gmf(const int* __restrict__ ridx, const int* __restrict__ rowptr,
           const int* __restrict__ csr, const __half* __restrict__ srch,
           const __half* __restrict__ bias, const __half* __restrict__ BT,
           __half* __restrict__ dsth, const int* __restrict__ gids,
           float* __restrict__ out, int M) {
    extern __shared__ char sm[];
    __shared__ int sIdx[64];
    __shared__ int sPtr[65];
    const int tid  = threadIdx.x;
    const int lane = tid & 31;
    const int wid  = tid >> 5;          // 0..7
    const int wm   = wid >> 2;          // 0..1 : 32-row band
    const int wn   = wid & 3;           // 0..3 : 64-col band
    const int m0   = blockIdx.x * 64;
    const uint32_t sbase = smem_u32(sm);

    auto cpB = [&](int cc, int b) {
        uint32_t base = sbase + 32768u + b * 32768u;
#pragma unroll
        for (int j = 0; j < 8; j++) {
            int idx = tid + j * 256;
            int row = idx >> 3, seg = idx & 7;
            uint32_t off = (uint32_t)(row * 128 + seg * 16);
            uint32_t sw = off ^ ((off >> 3) & 0x70);
            cp16(base + sw, BT + (size_t)row * 256 + cc * 64 + seg * 8);
        }
    };

    // B chunk 0 in flight under the gather
    cpB(0, 0);
    CP_COMMIT();

    if (tid < 64) {
        int gr = m0 + tid;
        sIdx[tid] = (MODE == 0) ? ((gr < M) ? __ldg(&ridx[gr]) : 0) : gr;
    }
    if (tid < 65) {
        int gr = m0 + tid;
        sPtr[tid] = __ldg(&rowptr[gr < M ? gr : M]);
    }
    __syncthreads();

    // gather A: 2 passes x 32 rows, 8 threads/row, 32 halves (64B) per thread
#pragma unroll
    for (int pass = 0; pass < 2; pass++) {
        int r  = pass * 32 + (tid >> 3);
        int sg = tid & 7;
        int gr = m0 + r;
        float acc[32];
#pragma unroll
        for (int u = 0; u < 32; u++) acc[u] = 0.f;
        if (gr < M) {
            size_t cb = (size_t)sg * 32;
            const uint4* ap = (const uint4*)(g_alphaH + (size_t)sIdx[r] * 256 + cb);
#pragma unroll
            for (int u = 0; u < 4; u++) addh8(acc + u * 8, __ldg(ap + u), false);
            int beg = sPtr[r], end = sPtr[r + 1];
            for (int j = beg; j < end; j++) {
                int s = __ldg(&csr[j]);
                const uint4* sp = (const uint4*)(srch + (size_t)s * 256 + cb);
#pragma unroll
                for (int u = 0; u < 4; u++) addh8(acc + u * 8, __ldg(sp + u), FIRST);
            }
        }
        // store to A subtile (chunk = sg>>1), swizzled 16B units
        char* subt = sm + (sg >> 1) * 8192;
        uint32_t rowoff = (uint32_t)r * 128 + (sg & 1) * 64;
#pragma unroll
        for (int u = 0; u < 4; u++) {
            uint32_t off = rowoff + u * 16;
            uint32_t sw = off ^ ((off >> 3) & 0x70);
            uint4 pk;
            pk.x = h2u(__floats2half2_rn(acc[u * 8 + 0], acc[u * 8 + 1]));
            pk.y = h2u(__floats2half2_rn(acc[u * 8 + 2], acc[u * 8 + 3]));
            pk.z = h2u(__floats2half2_rn(acc[u * 8 + 4], acc[u * 8 + 5]));
            pk.w = h2u(__floats2half2_rn(acc[u * 8 + 6], acc[u * 8 + 7]));
            *(uint4*)(subt + sw) = pk;
        }
    }
    CP_WAIT0();
    __syncthreads();

    float d[2][8][4];
#pragma unroll
    for (int i = 0; i < 2; i++)
#pragma unroll
        for (int j = 0; j < 8; j++)
#pragma unroll
            for (int q = 0; q < 4; q++) d[i][j][q] = 0.f;

    const int r = lane & 7, q = lane >> 3;
    const int bro = ((q >> 1) << 3) + r;
    const int bkp = (q & 1) << 4;
#pragma unroll
    for (int c = 0; c < 4; c++) {
        if (c < 3) { cpB(c + 1, (c + 1) & 1); CP_COMMIT(); }
        uint32_t baseA  = sbase + c * 8192u;
        uint32_t baseBh = sbase + 32768u + (c & 1) * 32768u;
#pragma unroll
        for (int s = 0; s < 4; s++) {
            uint32_t ah[2][4];
#pragma unroll
            for (int mt = 0; mt < 2; mt++) {
                uint32_t mrow = (uint32_t)(wm * 32 + mt * 16 + (q & 1) * 8 + r);
                uint32_t off = mrow * 128 + (q >> 1) * 16 + s * 32;
                uint32_t sw = off ^ ((off >> 3) & 0x70);
                ldsm4(ah[mt], baseA + sw);
            }
#pragma unroll
            for (int h = 0; h < 2; h++) {
                uint32_t bh4[2][4];
#pragma unroll
                for (int ntp = 0; ntp < 2; ntp++) {
                    uint32_t nrow = (uint32_t)(wn * 64 + h * 32 + ntp * 16 + bro);
                    uint32_t off = nrow * 128 + bkp + s * 32;
                    uint32_t sw = off ^ ((off >> 3) & 0x70);
                    ldsm4(bh4[ntp], baseBh + sw);
                }
#pragma unroll
                for (int mt = 0; mt < 2; mt++)
#pragma unroll
                    for (int nt = 0; nt < 4; nt++)
                        mma_f16(d[mt][h * 4 + nt], ah[mt], &bh4[nt >> 1][(nt & 1) * 2]);
            }
        }
        if (c < 3) CP_WAIT0();
        __syncthreads();
    }

#pragma unroll
    for (int mt = 0; mt < 2; mt++) {
#pragma unroll
        for (int n = 0; n < 8; n++) {
            int row = m0 + wm * 32 + mt * 16 + (lane >> 2);
            int col = wn * 64 + n * 8 + (lane & 3) * 2;
#pragma unroll
            for (int h2 = 0; h2 < 2; h2++) {
                int gr = row + h2 * 8;
                if (gr >= M) continue;
                size_t gb = (size_t)gr * 256 + col;
                uint32_t bu = *(const uint32_t*)(bias + gb);
                __half2 bh = *reinterpret_cast<__half2*>(&bu);
                float2 bv = __half22float2(bh);
                float ox = fmaxf(bv.x + d[mt][n][h2 * 2 + 0], 0.f);
                float oy = fmaxf(bv.y + d[mt][n][h2 * 2 + 1], 0.f);
                if (MODE == 0) {
                    __half2 hv = __floats2half2_rn(ox, oy);
                    *(uint32_t*)(dsth + gb) = h2u(hv);
                } else {
                    int g = gids[gr];
                    red2(out + (size_t)g * 256 + col, ox, oy);
                }
            }
        }
    }
}

// ---------------- launch ----------------
extern "C" void kernel_launch(void* const* d_in, const int* in_sizes, int n_in,
                              void* d_out, int out_size) {
    (void)in_sizes; (void)n_in; (void)out_size;
    const float* node_x = (const float*)d_in[0];
    const float* bond_x = (const float*)d_in[1];
    const float* tree   = (const float*)d_in[2];
    const float* W_i    = (const float*)d_in[3];
    const float* W_h    = (const float*)d_in[4];
    const float* W_o    = (const float*)d_in[5];
    const float* b_o    = (const float*)d_in[6];
    const int* esrc = (const int*)d_in[7];
    const int* edst = (const int*)d_in[8];
    const int* lsrc = (const int*)d_in[9];
    const int* ldst = (const int*)d_in[10];
    const int* tgt  = (const int*)d_in[11];
    const int* gids = (const int*)d_in[12];
    float* out = (float*)d_out;

    static cudaStream_t s1 = nullptr;
    static cudaEvent_t ev[4];
    if (!s1) {
        cudaStreamCreateWithFlags(&s1, cudaStreamNonBlocking);
        for (int i = 0; i < 4; i++)
            cudaEventCreateWithFlags(&ev[i], cudaEventDisableTiming);
        cudaFuncSetAttribute(k_gmf<0, true>,  cudaFuncAttributeMaxDynamicSharedMemorySize, GMF_SMEM);
        cudaFuncSetAttribute(k_gmf<0, false>, cudaFuncAttributeMaxDynamicSharedMemorySize, GMF_SMEM);
        cudaFuncSetAttribute(k_gmf<1, false>, cudaFuncAttributeMaxDynamicSharedMemorySize, GMF_SMEM);
    }

    __half *msgIn_p, *msgH_p, *msgHB_p, *hb_p;
    __half *WhT_p, *WoT_p, *WiT_p, *WoTop_p;
    cudaGetSymbolAddress((void**)&msgIn_p, g_msgIn);
    cudaGetSymbolAddress((void**)&msgH_p,  g_msgH);
    cudaGetSymbolAddress((void**)&msgHB_p, g_msgHB);
    cudaGetSymbolAddress((void**)&hb_p,    g_hbias);
    cudaGetSymbolAddress((void**)&WhT_p,   g_WhT);
    cudaGetSymbolAddress((void**)&WoT_p,   g_WoT);
    cudaGetSymbolAddress((void**)&WiT_p,   g_WiT);
    cudaGetSymbolAddress((void**)&WoTop_p, g_WoTop);
    int *lg_rp, *lg_cur, *lg_csr_p, *nd_rp, *nd_cur, *nd_csr_p, *part_p, *part2_p;
    cudaGetSymbolAddress((void**)&lg_rp,    g_lg_rowptr);
    cudaGetSymbolAddress((void**)&lg_cur,   g_lg_cursor);
    cudaGetSymbolAddress((void**)&lg_csr_p, g_lg_csr);
    cudaGetSymbolAddress((void**)&nd_rp,    g_nd_rowptr);
    cudaGetSymbolAddress((void**)&nd_cur,   g_nd_cursor);
    cudaGetSymbolAddress((void**)&nd_csr_p, g_nd_csr);
    cudaGetSymbolAddress((void**)&part_p,   g_part);
    cudaGetSymbolAddress((void**)&part2_p,  g_part2);

    k_prep_w2<<<512, 64>>>(W_i, W_o);

    // ==== fork side stream ====
    cudaEventRecord(ev[0], 0);
    cudaStreamWaitEvent(s1, ev[0], 0);

    // ---- side stream: CSR builds + weight prep + hbias + out/counts init ----
    k_zeroi<<<1172, 256, 0, s1>>>(lg_cur, N_EDGES_C);
    k_hist<<<2344, 256, 0, s1>>>(ldst, lg_cur, N_LG_C);
    k_scan1<<<293, 256, 0, s1>>>(lg_cur, lg_rp, N_EDGES_C, part_p);
    k_scan1<<<1, 256, 0, s1>>>(part_p, part2_p, 293, nullptr);
    k_scan3<<<1172, 256, 0, s1>>>(lg_rp, lg_cur, part2_p, N_EDGES_C, N_LG_C);
    k_fill<<<2344, 256, 0, s1>>>(lsrc, ldst, lg_cur, lg_csr_p, N_LG_C);
    k_zeroi<<<586, 256, 0, s1>>>(nd_cur, N_NODES_C);
    k_hist<<<1172, 256, 0, s1>>>(edst, nd_cur, N_EDGES_C);
    k_scan1<<<147, 256, 0, s1>>>(nd_cur, nd_rp, N_NODES_C, part_p);
    k_scan1<<<1, 256, 0, s1>>>(part_p, part2_p, 147, nullptr);
    k_scan3<<<586, 256, 0, s1>>>(nd_rp, nd_cur, part2_p, N_NODES_C, N_EDGES_C);
    k_fill_id<<<1172, 256, 0, s1>>>(edst, nd_cur, nd_csr_p, N_EDGES_C);
    k_prep_w<<<512, 256, 0, s1>>>(W_h, W_o);
    k_gmm<1><<<1172, 512, 0, s1>>>(node_x, nullptr, nullptr, WoTop_p, b_o, hb_p, N_NODES_C);
    k_zero_out<<<512, 256, 0, s1>>>(out);
    k_counts<<<586, 256, 0, s1>>>(gids);

    // ---- main stream: alpha + msg_input ----
    k_zero_alpha<<<37500, 256>>>();
    k_tree_scatter<<<15000, 256>>>(tree, tgt);
    k_alpha_cvt<<<37500, 256>>>();
    k_gmm<0><<<2344, 512>>>(node_x, bond_x, esrc, WiT_p, nullptr, msgIn_p, N_EDGES_C);

    // ==== join ====
    cudaEventRecord(ev[1], s1);
    cudaStreamWaitEvent(0, ev[1], 0);

    // ==== BP iterations (fused gather + GEMM, 64-row tiles) ====
    k_gmf<0, true><<<4688, 256, GMF_SMEM>>>(esrc, lg_rp, lg_csr_p, msgIn_p, msgIn_p,
                                            WhT_p, msgH_p, nullptr, nullptr, N_EDGES_C);
    k_gmf<0, false><<<4688, 256, GMF_SMEM>>>(esrc, lg_rp, lg_csr_p, msgH_p, msgIn_p,
                                             WhT_p, msgHB_p, nullptr, nullptr, N_EDGES_C);
    k_gmf<0, false><<<4688, 256, GMF_SMEM>>>(esrc, lg_rp, lg_csr_p, msgHB_p, msgIn_p,
                                             WhT_p, msgH_p, nullptr, nullptr, N_EDGES_C);

    // ==== fused readout ====
    k_gmf<1, false><<<2344, 256, GMF_SMEM>>>(nullptr, nd_rp, nd_csr_p, msgH_p, hb_p,
                                             WoT_p, nullptr, gids, out, N_NODES_C);
    k_div<<<512, 256>>>(out);
}